// round 1
// baseline (speedup 1.0000x reference)
#include <cuda_runtime.h>
#include <math.h>

#define S_LEN 2048
#define HID   2048
#define NHEADS 32
#define HDIM   64
#define QDIM  2048   // NHEADS*HDIM
#define KVDIM  512   // 8*64
#define VD     128   // effective value dim (concat of two 64-d heads)
#define LAMBDA_INIT 0.7455692280263552f

// ---------------- scratch (static device allocations are allowed) ----------------
__device__ float g_Q[(size_t)S_LEN * QDIM];            // 16 MB
__device__ float g_K[(size_t)S_LEN * KVDIM];           // 4 MB
__device__ float g_V[(size_t)S_LEN * KVDIM];           // 4 MB
__device__ float g_O[(size_t)NHEADS * S_LEN * VD];     // 32 MB (per-head 128-wide attention out)
__device__ float g_A[(size_t)S_LEN * QDIM];            // 16 MB (pre-Wo activations)
__device__ float g_lam;

// ---------------- SGEMM: C[M,N] = A[M,K] @ B[N,K]^T  (both row-major) ----------------
// 128x128 tile, BK=8, 256 threads, 8x8 per thread (4+4 split), float4 everywhere.
__global__ __launch_bounds__(256) void sgemm128(
    const float* __restrict__ A, const float* __restrict__ B,
    float* __restrict__ C, int M, int N, int K) {
  __shared__ float As[8][128];
  __shared__ float Bs[8][128];
  const int tid = threadIdx.x;
  const int tx = tid & 15;
  const int ty = tid >> 4;
  const int m0 = blockIdx.y << 7;
  const int n0 = blockIdx.x << 7;
  const int lr = tid >> 1;         // 0..127
  const int lc = (tid & 1) << 2;   // 0 or 4
  const float* Ag = A + (size_t)(m0 + lr) * K + lc;
  const float* Bg = B + (size_t)(n0 + lr) * K + lc;

  float acc[8][8];
#pragma unroll
  for (int i = 0; i < 8; i++)
#pragma unroll
    for (int j = 0; j < 8; j++) acc[i][j] = 0.f;

  float4 a4 = *(const float4*)Ag;
  float4 b4 = *(const float4*)Bg;

  for (int k0 = 0; k0 < K; k0 += 8) {
    As[lc + 0][lr] = a4.x; As[lc + 1][lr] = a4.y; As[lc + 2][lr] = a4.z; As[lc + 3][lr] = a4.w;
    Bs[lc + 0][lr] = b4.x; Bs[lc + 1][lr] = b4.y; Bs[lc + 2][lr] = b4.z; Bs[lc + 3][lr] = b4.w;
    __syncthreads();
    if (k0 + 8 < K) {
      a4 = *(const float4*)(Ag + k0 + 8);
      b4 = *(const float4*)(Bg + k0 + 8);
    }
#pragma unroll
    for (int kk = 0; kk < 8; kk++) {
      float4 alo = *(const float4*)&As[kk][ty << 2];
      float4 ahi = *(const float4*)&As[kk][64 + (ty << 2)];
      float4 blo = *(const float4*)&Bs[kk][tx << 2];
      float4 bhi = *(const float4*)&Bs[kk][64 + (tx << 2)];
      float av[8] = {alo.x, alo.y, alo.z, alo.w, ahi.x, ahi.y, ahi.z, ahi.w};
      float bv[8] = {blo.x, blo.y, blo.z, blo.w, bhi.x, bhi.y, bhi.z, bhi.w};
#pragma unroll
      for (int i = 0; i < 8; i++)
#pragma unroll
        for (int j = 0; j < 8; j++)
          acc[i][j] = fmaf(av[i], bv[j], acc[i][j]);
    }
    __syncthreads();
  }

#pragma unroll
  for (int i = 0; i < 8; i++) {
    int row = m0 + ((i < 4) ? ((ty << 2) + i) : (64 + (ty << 2) + (i - 4)));
    float4 lo = make_float4(acc[i][0], acc[i][1], acc[i][2], acc[i][3]);
    float4 hi = make_float4(acc[i][4], acc[i][5], acc[i][6], acc[i][7]);
    *(float4*)(C + (size_t)row * N + n0 + (tx << 2)) = lo;
    *(float4*)(C + (size_t)row * N + n0 + 64 + (tx << 2)) = hi;
  }
}

// ---------------- RoPE (in-place, pairwise to avoid RAW races) ----------------
__global__ void rope_kernel(float* __restrict__ X, const float* __restrict__ cosb,
                            const float* __restrict__ sinb, int width) {
  int idx = blockIdx.x * blockDim.x + threadIdx.x;
  int pairsPerRow = width >> 1;
  int total = S_LEN * pairsPerRow;
  if (idx >= total) return;
  int s = idx / pairsPerRow;
  int p = idx - s * pairsPerRow;
  int head = p >> 5;        // 32 pairs per 64-d head
  int d = p & 31;
  int c1 = head * HDIM + d;
  float c  = cosb[s * HDIM + d];
  float sn = sinb[s * HDIM + d];
  float c2  = cosb[s * HDIM + d + 32];
  float sn2 = sinb[s * HDIM + d + 32];
  size_t base = (size_t)s * width;
  float x1 = X[base + c1];
  float x2 = X[base + c1 + 32];
  X[base + c1]      = x1 * c  - x2 * sn;   // q*cos + (-x2)*sin for d<32
  X[base + c1 + 32] = x2 * c2 + x1 * sn2;  // q*cos + ( x1)*sin for d>=32
}

// ---------------- lambda scalar ----------------
__global__ void lam_kernel(const float* __restrict__ lq1, const float* __restrict__ lk1,
                           const float* __restrict__ lq2, const float* __restrict__ lk2) {
  int d = threadIdx.x;  // 32 threads
  float s1 = lq1[d] * lk1[d] + lq1[d + 32] * lk1[d + 32];
  float s2 = lq2[d] * lk2[d] + lq2[d + 32] * lk2[d + 32];
#pragma unroll
  for (int off = 16; off > 0; off >>= 1) {
    s1 += __shfl_xor_sync(0xffffffffu, s1, off);
    s2 += __shfl_xor_sync(0xffffffffu, s2, off);
  }
  if (d == 0) g_lam = expf(s1) - expf(s2) + LAMBDA_INIT;
}

// ---------------- flash attention (fp32, causal, GQA, 128-wide V) ----------------
// Grid: (32 q-blocks reversed, 32 heads). 256 threads = 16x16.
// Per thread: 4 q-rows x 4 score-cols; output accum 4 rows x 8 V-cols.
__global__ __launch_bounds__(256) void flash_attn_kernel(
    const float* __restrict__ Q, const float* __restrict__ K,
    const float* __restrict__ V, float* __restrict__ O) {
  extern __shared__ float sm[];
  float* Qs = sm;             // [64][64]  d-major: Qs[d*64 + q]
  float* Ks = Qs + 4096;      // [64][64]  d-major: Ks[d*64 + k]
  float* Vs = Ks + 4096;      // [64][128] k-major
  float* Ps = Vs + 8192;      // [64][68]  q-major, padded

  const int tid = threadIdx.x;
  const int tx = tid & 15;
  const int ty = tid >> 4;
  const int h  = blockIdx.y;
  const int qb = (int)gridDim.x - 1 - (int)blockIdx.x;  // heavy blocks first
  const int q0 = qb * 64;
  const int kh = h >> 2;                 // GQA: k head
  const int ii = h & 15;                 // v_rep index
  const int vh0 = ii >> 2;               // first 64 dims of V
  const int vh1 = 4 + vh0;               // last 64 dims of V

  // Load Q tile transposed into Qs[d][q]
  {
    const int r = tid >> 4;
    const int cg = (tid & 15) << 2;
#pragma unroll
    for (int rep = 0; rep < 4; rep++) {
      int rr = r + (rep << 4);
      float4 v4 = *(const float4*)(Q + (size_t)(q0 + rr) * QDIM + h * HDIM + cg);
      Qs[(cg + 0) * 64 + rr] = v4.x;
      Qs[(cg + 1) * 64 + rr] = v4.y;
      Qs[(cg + 2) * 64 + rr] = v4.z;
      Qs[(cg + 3) * 64 + rr] = v4.w;
    }
  }

  float acc[4][8];
#pragma unroll
  for (int i = 0; i < 4; i++)
#pragma unroll
    for (int c = 0; c < 8; c++) acc[i][c] = 0.f;
  float m_i[4], l_i[4];
#pragma unroll
  for (int i = 0; i < 4; i++) { m_i[i] = -1e30f; l_i[i] = 0.f; }

  for (int kb = 0; kb <= qb; kb++) {
    const int k0 = kb * 64;
    __syncthreads();  // prior PV done before overwriting Ks/Vs/Ps

    // Load K tile transposed into Ks[d][k]
    {
      const int r = tid >> 4;
      const int cg = (tid & 15) << 2;
#pragma unroll
      for (int rep = 0; rep < 4; rep++) {
        int rr = r + (rep << 4);
        float4 v4 = *(const float4*)(K + (size_t)(k0 + rr) * KVDIM + kh * HDIM + cg);
        Ks[(cg + 0) * 64 + rr] = v4.x;
        Ks[(cg + 1) * 64 + rr] = v4.y;
        Ks[(cg + 2) * 64 + rr] = v4.z;
        Ks[(cg + 3) * 64 + rr] = v4.w;
      }
    }
    // Load V tile [64][128]: cols 0..63 from head vh0, 64..127 from head vh1
    {
#pragma unroll
      for (int t = 0; t < 8; t++) {
        int idx = tid + (t << 8);
        int row = idx >> 5;
        int col = (idx & 31) << 2;
        int sh = (col < 64) ? vh0 : vh1;
        int sc = (col < 64) ? col : (col - 64);
        float4 v4 = *(const float4*)(V + (size_t)(k0 + row) * KVDIM + sh * HDIM + sc);
        *(float4*)(Vs + row * 128 + col) = v4;
      }
    }
    __syncthreads();

    // Scores S = Q K^T / sqrt(64)
    float s[4][4];
#pragma unroll
    for (int i = 0; i < 4; i++)
#pragma unroll
      for (int j = 0; j < 4; j++) s[i][j] = 0.f;
#pragma unroll 8
    for (int d = 0; d < 64; d++) {
      float4 aq = *(const float4*)(Qs + d * 64 + (ty << 2));
      float4 bk = *(const float4*)(Ks + d * 64 + (tx << 2));
      float av[4] = {aq.x, aq.y, aq.z, aq.w};
      float bv[4] = {bk.x, bk.y, bk.z, bk.w};
#pragma unroll
      for (int i = 0; i < 4; i++)
#pragma unroll
        for (int j = 0; j < 4; j++)
          s[i][j] = fmaf(av[i], bv[j], s[i][j]);
    }
    const bool diag = (kb == qb);
#pragma unroll
    for (int i = 0; i < 4; i++)
#pragma unroll
      for (int j = 0; j < 4; j++) {
        s[i][j] *= 0.125f;
        if (diag && (k0 + (tx << 2) + j) > (q0 + (ty << 2) + i)) s[i][j] = -1e30f;
      }

    // Online softmax: reduce over the 16 lanes sharing ty (contiguous half-warp)
    float rm[4];
#pragma unroll
    for (int i = 0; i < 4; i++)
      rm[i] = fmaxf(fmaxf(s[i][0], s[i][1]), fmaxf(s[i][2], s[i][3]));
#pragma unroll
    for (int off = 8; off > 0; off >>= 1)
#pragma unroll
      for (int i = 0; i < 4; i++)
        rm[i] = fmaxf(rm[i], __shfl_xor_sync(0xffffffffu, rm[i], off));

    float alpha[4], rs[4];
    float p[4][4];
#pragma unroll
    for (int i = 0; i < 4; i++) {
      float mn = fmaxf(m_i[i], rm[i]);
      alpha[i] = __expf(m_i[i] - mn);
      m_i[i] = mn;
      rs[i] = 0.f;
#pragma unroll
      for (int j = 0; j < 4; j++) {
        p[i][j] = __expf(s[i][j] - mn);
        rs[i] += p[i][j];
      }
    }
#pragma unroll
    for (int off = 8; off > 0; off >>= 1)
#pragma unroll
      for (int i = 0; i < 4; i++)
        rs[i] += __shfl_xor_sync(0xffffffffu, rs[i], off);
#pragma unroll
    for (int i = 0; i < 4; i++) {
      l_i[i] = l_i[i] * alpha[i] + rs[i];
#pragma unroll
      for (int c = 0; c < 8; c++) acc[i][c] *= alpha[i];
    }

    // Stage P (row-major, pad 68)
#pragma unroll
    for (int i = 0; i < 4; i++) {
      float4 pw = make_float4(p[i][0], p[i][1], p[i][2], p[i][3]);
      *(float4*)(Ps + ((ty << 2) + i) * 68 + (tx << 2)) = pw;
    }
    __syncthreads();

    // O += P @ V
#pragma unroll 4
    for (int kk = 0; kk < 64; kk++) {
      float pa0 = Ps[((ty << 2) + 0) * 68 + kk];
      float pa1 = Ps[((ty << 2) + 1) * 68 + kk];
      float pa2 = Ps[((ty << 2) + 2) * 68 + kk];
      float pa3 = Ps[((ty << 2) + 3) * 68 + kk];
      float4 v0 = *(const float4*)(Vs + kk * 128 + (tx << 2));
      float4 v1 = *(const float4*)(Vs + kk * 128 + 64 + (tx << 2));
      float vb[8] = {v0.x, v0.y, v0.z, v0.w, v1.x, v1.y, v1.z, v1.w};
      float pa[4] = {pa0, pa1, pa2, pa3};
#pragma unroll
      for (int i = 0; i < 4; i++)
#pragma unroll
        for (int c = 0; c < 8; c++)
          acc[i][c] = fmaf(pa[i], vb[c], acc[i][c]);
    }
  }

  // Epilogue: normalize and write O[h][s][0..127]
#pragma unroll
  for (int i = 0; i < 4; i++) {
    float inv = 1.0f / l_i[i];
    int row = q0 + (ty << 2) + i;
    float4 o0 = make_float4(acc[i][0] * inv, acc[i][1] * inv, acc[i][2] * inv, acc[i][3] * inv);
    float4 o1 = make_float4(acc[i][4] * inv, acc[i][5] * inv, acc[i][6] * inv, acc[i][7] * inv);
    *(float4*)(O + ((size_t)h * S_LEN + row) * VD + (tx << 2)) = o0;
    *(float4*)(O + ((size_t)h * S_LEN + row) * VD + 64 + (tx << 2)) = o1;
  }
}

// ---------------- differential combine + RMS norm ----------------
__global__ void combine_kernel(const float* __restrict__ O, float* __restrict__ A) {
  const int s = blockIdx.x;
  const int i = blockIdx.y;
  const int d = threadIdx.x;  // 128 threads
  const float lam = g_lam;
  float o1 = O[((size_t)i * S_LEN + s) * VD + d];
  float o2 = O[((size_t)(i + 16) * S_LEN + s) * VD + d];
  float a = o1 - lam * o2;
  float ss = a * a;
#pragma unroll
  for (int off = 16; off > 0; off >>= 1)
    ss += __shfl_xor_sync(0xffffffffu, ss, off);
  __shared__ float ws[4];
  int warp = d >> 5, lane = d & 31;
  if (lane == 0) ws[warp] = ss;
  __syncthreads();
  float tot = ws[0] + ws[1] + ws[2] + ws[3];
  float r = rsqrtf(tot * (1.0f / 128.0f) + 1e-6f);
  A[(size_t)s * QDIM + i * VD + d] = (1.0f - LAMBDA_INIT) * a * r;
}

// ---------------- launch ----------------
extern "C" void kernel_launch(void* const* d_in, const int* in_sizes, int n_in,
                              void* d_out, int out_size) {
  const float* hidden = (const float*)d_in[0];
  const float* cosb   = (const float*)d_in[1];
  const float* sinb   = (const float*)d_in[2];
  const float* Wq     = (const float*)d_in[3];
  const float* Wk     = (const float*)d_in[4];
  const float* Wv     = (const float*)d_in[5];
  const float* Wo     = (const float*)d_in[6];
  const float* lq1    = (const float*)d_in[7];
  const float* lk1    = (const float*)d_in[8];
  const float* lq2    = (const float*)d_in[9];
  const float* lk2    = (const float*)d_in[10];
  float* out = (float*)d_out;

  float *Qp, *Kp, *Vp, *Op, *Ap;
  cudaGetSymbolAddress((void**)&Qp, g_Q);
  cudaGetSymbolAddress((void**)&Kp, g_K);
  cudaGetSymbolAddress((void**)&Vp, g_V);
  cudaGetSymbolAddress((void**)&Op, g_O);
  cudaGetSymbolAddress((void**)&Ap, g_A);

  // Projections
  sgemm128<<<dim3(QDIM / 128, S_LEN / 128), 256>>>(hidden, Wq, Qp, S_LEN, QDIM, HID);
  sgemm128<<<dim3(KVDIM / 128, S_LEN / 128), 256>>>(hidden, Wk, Kp, S_LEN, KVDIM, HID);
  sgemm128<<<dim3(KVDIM / 128, S_LEN / 128), 256>>>(hidden, Wv, Vp, S_LEN, KVDIM, HID);

  // RoPE
  rope_kernel<<<(S_LEN * (QDIM / 2)) / 256, 256>>>(Qp, cosb, sinb, QDIM);
  rope_kernel<<<(S_LEN * (KVDIM / 2)) / 256, 256>>>(Kp, cosb, sinb, KVDIM);

  // lambda
  lam_kernel<<<1, 32>>>(lq1, lk1, lq2, lk2);

  // Attention
  int smemBytes = (4096 + 4096 + 8192 + 64 * 68) * 4;  // 82944 B
  cudaFuncSetAttribute(flash_attn_kernel, cudaFuncAttributeMaxDynamicSharedMemorySize, smemBytes);
  flash_attn_kernel<<<dim3(32, 32), 256, smemBytes>>>(Qp, Kp, Vp, Op);

  // Differential combine + RMS norm
  combine_kernel<<<dim3(S_LEN, 16), 128>>>(Op, Ap);

  // Output projection
  sgemm128<<<dim3(QDIM / 128, S_LEN / 128), 256>>>(Ap, Wo, out, S_LEN, QDIM, QDIM);
}

// round 3
// speedup vs baseline: 1.2893x; 1.2893x over previous
#include <cuda_runtime.h>
#include <cuda_bf16.h>
#include <math.h>
#include <stdint.h>

#define S_LEN 2048
#define HID   2048
#define NHEADS 32
#define HDIM   64
#define QDIM  2048
#define KVDIM  512
#define VD     128
#define KC3   (3 * HID)     // 6144, concat-K for bf16x3
#define LAMBDA_INIT 0.7455692280263552f

// ---------------- scratch ----------------
__device__ float g_Q[(size_t)S_LEN * QDIM];
__device__ float g_K[(size_t)S_LEN * KVDIM];
__device__ float g_V[(size_t)S_LEN * KVDIM];
__device__ float g_O[(size_t)NHEADS * S_LEN * VD];
__device__ float g_lam;
__device__ __align__(256) __nv_bfloat16 g_Hc[(size_t)S_LEN * KC3];    // activations cat [h,h,l]
__device__ __align__(256) __nv_bfloat16 g_Wqc[(size_t)QDIM * KC3];    // weights cat [h,l,h]
__device__ __align__(256) __nv_bfloat16 g_Wkc[(size_t)KVDIM * KC3];
__device__ __align__(256) __nv_bfloat16 g_Wvc[(size_t)KVDIM * KC3];
__device__ __align__(256) __nv_bfloat16 g_Woc[(size_t)HID * KC3];
__device__ __align__(256) __nv_bfloat16 g_Ac[(size_t)S_LEN * KC3];    // attention-out cat [h,h,l]

// ---------------- helpers ----------------
__device__ __forceinline__ uint32_t smem_u32(const void* p) {
  uint32_t r;
  asm("{ .reg .u64 t; cvta.to.shared.u64 t, %1; cvt.u32.u64 %0, t; }" : "=r"(r) : "l"(p));
  return r;
}
#define CP_ASYNC16(sa, ga) \
  asm volatile("cp.async.cg.shared.global [%0], [%1], 16;" :: "r"(sa), "l"(ga) : "memory")
#define CP_COMMIT() asm volatile("cp.async.commit_group;" ::: "memory")
#define CP_WAIT0()  asm volatile("cp.async.wait_group 0;" ::: "memory")

#define LDMATRIX_X4(r0, r1, r2, r3, addr) \
  asm volatile("ldmatrix.sync.aligned.m8n8.x4.shared.b16 {%0,%1,%2,%3}, [%4];" \
               : "=r"(r0), "=r"(r1), "=r"(r2), "=r"(r3) : "r"(addr))

#define MMA16816(c0, c1, c2, c3, a0, a1, a2, a3, b0, b1) \
  asm volatile("mma.sync.aligned.m16n8k16.row.col.f32.bf16.bf16.f32 " \
               "{%0,%1,%2,%3}, {%4,%5,%6,%7}, {%8,%9}, {%0,%1,%2,%3};" \
               : "+f"(c0), "+f"(c1), "+f"(c2), "+f"(c3) \
               : "r"(a0), "r"(a1), "r"(a2), "r"(a3), "r"(b0), "r"(b1))

// ---------------- bf16 HMMA GEMM: C[M,N] = A[M,Kc] @ B[N,Kc]^T ----------------
// CTA tile 128x128, BK=32, 256 threads (8 warps, 2m x 4n), warp tile 64x32.
// Smem rows padded to 40 bf16 (80 B) -> conflict-free ldmatrix.
#define BK 32
#define ROWB 80   // bytes per smem row
#define TILE_B (128 * ROWB)  // 10240 B per tile buffer

__device__ __forceinline__ void hgemm_core(
    const __nv_bfloat16* __restrict__ A, const __nv_bfloat16* __restrict__ B,
    float* __restrict__ C, int N, int Kc, int m0, int n0) {
  __shared__ __align__(16) char smA[2 * TILE_B];
  __shared__ __align__(16) char smB[2 * TILE_B];
  const int tid = threadIdx.x;
  const int warp = tid >> 5;
  const int lane = tid & 31;
  const int wm = warp & 1;        // 0..1 -> 64 rows
  const int wn = warp >> 1;       // 0..3 -> 32 cols
  const uint32_t sA = smem_u32(smA);
  const uint32_t sB = smem_u32(smB);

  // loader mapping: 512 chunks of 16B per tile (128 rows x 4 chunks)
  const int lrow = tid >> 1;               // 0..127
  const int lch0 = (tid & 1) << 1;         // 0 or 2 (two consecutive chunks)

  float acc[4][4][4];
#pragma unroll
  for (int i = 0; i < 4; i++)
#pragma unroll
    for (int j = 0; j < 4; j++)
#pragma unroll
      for (int c = 0; c < 4; c++) acc[i][j][c] = 0.f;

  const int T = Kc >> 5;  // k-tiles

  // prologue: load tile 0 into buf 0
  {
    const __nv_bfloat16* ag = A + (size_t)(m0 + lrow) * Kc + lch0 * 8;
    const __nv_bfloat16* bg = B + (size_t)(n0 + lrow) * Kc + lch0 * 8;
    uint32_t so = lrow * ROWB + lch0 * 16;
    CP_ASYNC16(sA + so, ag);       CP_ASYNC16(sA + so + 16, ag + 8);
    CP_ASYNC16(sB + so, bg);       CP_ASYNC16(sB + so + 16, bg + 8);
    CP_COMMIT();
  }

  for (int t = 0; t < T; ++t) {
    CP_WAIT0();
    __syncthreads();
    const uint32_t cb = (uint32_t)(t & 1) * TILE_B;   // compute buffer
    if (t + 1 < T) {
      const uint32_t pb = (uint32_t)((t + 1) & 1) * TILE_B;
      const int k0 = (t + 1) << 5;
      const __nv_bfloat16* ag = A + (size_t)(m0 + lrow) * Kc + k0 + lch0 * 8;
      const __nv_bfloat16* bg = B + (size_t)(n0 + lrow) * Kc + k0 + lch0 * 8;
      uint32_t so = pb + lrow * ROWB + lch0 * 16;
      CP_ASYNC16(sA + so, ag);     CP_ASYNC16(sA + so + 16, ag + 8);
      CP_ASYNC16(sB + so, bg);     CP_ASYNC16(sB + so + 16, bg + 8);
      CP_COMMIT();
    }

#pragma unroll
    for (int ks = 0; ks < 2; ++ks) {
      // A fragments: 4 m-frags of 16 rows
      uint32_t a[4][4];
#pragma unroll
      for (int mi = 0; mi < 4; ++mi) {
        uint32_t addr = sA + cb + (uint32_t)((wm << 6) + (mi << 4) + (lane & 15)) * ROWB
                        + ((lane >> 4) << 4) + (ks << 5);
        LDMATRIX_X4(a[mi][0], a[mi][1], a[mi][2], a[mi][3], addr);
      }
      // B fragments: 2 pairs covering 4 n-frags of 8 cols
      uint32_t b[4][2];
#pragma unroll
      for (int pr = 0; pr < 2; ++pr) {
        int r = (lane & 7) + (((lane >> 4) & 1) << 3);
        int hk = (lane >> 3) & 1;
        uint32_t addr = sB + cb + (uint32_t)((wn << 5) + (pr << 4) + r) * ROWB
                        + (hk << 4) + (ks << 5);
        uint32_t r0, r1, r2, r3;
        LDMATRIX_X4(r0, r1, r2, r3, addr);
        b[pr * 2 + 0][0] = r0; b[pr * 2 + 0][1] = r1;
        b[pr * 2 + 1][0] = r2; b[pr * 2 + 1][1] = r3;
      }
#pragma unroll
      for (int mi = 0; mi < 4; ++mi)
#pragma unroll
        for (int ni = 0; ni < 4; ++ni)
          MMA16816(acc[mi][ni][0], acc[mi][ni][1], acc[mi][ni][2], acc[mi][ni][3],
                   a[mi][0], a[mi][1], a[mi][2], a[mi][3], b[ni][0], b[ni][1]);
    }
    __syncthreads();
  }

  // epilogue: direct float2 stores
#pragma unroll
  for (int mi = 0; mi < 4; ++mi) {
    int row = m0 + (wm << 6) + (mi << 4) + (lane >> 2);
#pragma unroll
    for (int ni = 0; ni < 4; ++ni) {
      int col = n0 + (wn << 5) + (ni << 3) + ((lane & 3) << 1);
      *(float2*)(C + (size_t)row * N + col)       = make_float2(acc[mi][ni][0], acc[mi][ni][1]);
      *(float2*)(C + (size_t)(row + 8) * N + col) = make_float2(acc[mi][ni][2], acc[mi][ni][3]);
    }
  }
}

__global__ __launch_bounds__(256, 1) void hgemm_qkv_kernel(
    const __nv_bfloat16* __restrict__ Hc,
    const __nv_bfloat16* __restrict__ Wqc, const __nv_bfloat16* __restrict__ Wkc,
    const __nv_bfloat16* __restrict__ Wvc,
    float* __restrict__ Qo, float* __restrict__ Ko, float* __restrict__ Vo) {
  const int z = blockIdx.z;
  const __nv_bfloat16* Bp;
  float* C;
  int N;
  if (z == 0)      { Bp = Wqc; C = Qo; N = QDIM; }
  else if (z == 1) { Bp = Wkc; C = Ko; N = KVDIM; }
  else             { Bp = Wvc; C = Vo; N = KVDIM; }
  const int n0 = blockIdx.x << 7;
  if (n0 >= N) return;
  const int m0 = blockIdx.y << 7;
  hgemm_core(Hc, Bp, C, N, KC3, m0, n0);
}

__global__ __launch_bounds__(256, 1) void hgemm_o_kernel(
    const __nv_bfloat16* __restrict__ Ac, const __nv_bfloat16* __restrict__ Woc,
    float* __restrict__ out) {
  hgemm_core(Ac, Woc, out, HID, KC3, blockIdx.y << 7, blockIdx.x << 7);
}

// ---------------- fp32 -> bf16 hi/lo concat split ----------------
// Activation (isW=0): [h, h, l]; Weight (isW=1): [h, l, h]
__global__ void splitcat_kernel(const float* __restrict__ x, __nv_bfloat16* __restrict__ o,
                                int K, int isW, int total) {
  int i4 = (blockIdx.x * blockDim.x + threadIdx.x) << 2;
  if (i4 >= total) return;
  float4 v = *(const float4*)(x + i4);
  int row = i4 / K;
  int col = i4 - row * K;
  __nv_bfloat16 h[4], l[4];
  float vv[4] = {v.x, v.y, v.z, v.w};
#pragma unroll
  for (int j = 0; j < 4; j++) {
    h[j] = __float2bfloat16_rn(vv[j]);
    l[j] = __float2bfloat16_rn(vv[j] - __bfloat162float(h[j]));
  }
  size_t base = (size_t)row * (3 * K) + col;
  uint2 ph, pl;
  ph.x = (uint32_t)__bfloat16_as_ushort(h[0]) | ((uint32_t)__bfloat16_as_ushort(h[1]) << 16);
  ph.y = (uint32_t)__bfloat16_as_ushort(h[2]) | ((uint32_t)__bfloat16_as_ushort(h[3]) << 16);
  pl.x = (uint32_t)__bfloat16_as_ushort(l[0]) | ((uint32_t)__bfloat16_as_ushort(l[1]) << 16);
  pl.y = (uint32_t)__bfloat16_as_ushort(l[2]) | ((uint32_t)__bfloat16_as_ushort(l[3]) << 16);
  *(uint2*)(o + base) = ph;
  if (isW) {
    *(uint2*)(o + base + K)     = pl;
    *(uint2*)(o + base + 2 * K) = ph;
  } else {
    *(uint2*)(o + base + K)     = ph;
    *(uint2*)(o + base + 2 * K) = pl;
  }
}

// ---------------- RoPE (in-place) ----------------
__global__ void rope_kernel(float* __restrict__ X, const float* __restrict__ cosb,
                            const float* __restrict__ sinb, int width) {
  int idx = blockIdx.x * blockDim.x + threadIdx.x;
  int pairsPerRow = width >> 1;
  int total = S_LEN * pairsPerRow;
  if (idx >= total) return;
  int s = idx / pairsPerRow;
  int p = idx - s * pairsPerRow;
  int head = p >> 5;
  int d = p & 31;
  int c1 = head * HDIM + d;
  float c   = cosb[s * HDIM + d];
  float sn  = sinb[s * HDIM + d];
  float c2  = cosb[s * HDIM + d + 32];
  float sn2 = sinb[s * HDIM + d + 32];
  size_t base = (size_t)s * width;
  float x1 = X[base + c1];
  float x2 = X[base + c1 + 32];
  X[base + c1]      = x1 * c  - x2 * sn;
  X[base + c1 + 32] = x2 * c2 + x1 * sn2;
}

// ---------------- lambda ----------------
__global__ void lam_kernel(const float* __restrict__ lq1, const float* __restrict__ lk1,
                           const float* __restrict__ lq2, const float* __restrict__ lk2) {
  int d = threadIdx.x;
  float s1 = lq1[d] * lk1[d] + lq1[d + 32] * lk1[d + 32];
  float s2 = lq2[d] * lk2[d] + lq2[d + 32] * lk2[d + 32];
#pragma unroll
  for (int off = 16; off > 0; off >>= 1) {
    s1 += __shfl_xor_sync(0xffffffffu, s1, off);
    s2 += __shfl_xor_sync(0xffffffffu, s2, off);
  }
  if (d == 0) g_lam = expf(s1) - expf(s2) + LAMBDA_INIT;
}

// ---------------- flash attention (fp32, known correct) ----------------
__global__ __launch_bounds__(256) void flash_attn_kernel(
    const float* __restrict__ Q, const float* __restrict__ K,
    const float* __restrict__ V, float* __restrict__ O) {
  extern __shared__ float smf[];
  float* Qs = smf;
  float* Ks = Qs + 4096;
  float* Vs = Ks + 4096;
  float* Ps = Vs + 8192;

  const int tid = threadIdx.x;
  const int tx = tid & 15;
  const int ty = tid >> 4;
  const int h  = blockIdx.y;
  const int qb = (int)gridDim.x - 1 - (int)blockIdx.x;
  const int q0 = qb * 64;
  const int kh = h >> 2;
  const int ii = h & 15;
  const int vh0 = ii >> 2;
  const int vh1 = 4 + vh0;

  {
    const int r = tid >> 4;
    const int cg = (tid & 15) << 2;
#pragma unroll
    for (int rep = 0; rep < 4; rep++) {
      int rr = r + (rep << 4);
      float4 v4 = *(const float4*)(Q + (size_t)(q0 + rr) * QDIM + h * HDIM + cg);
      Qs[(cg + 0) * 64 + rr] = v4.x;
      Qs[(cg + 1) * 64 + rr] = v4.y;
      Qs[(cg + 2) * 64 + rr] = v4.z;
      Qs[(cg + 3) * 64 + rr] = v4.w;
    }
  }

  float acc[4][8];
#pragma unroll
  for (int i = 0; i < 4; i++)
#pragma unroll
    for (int c = 0; c < 8; c++) acc[i][c] = 0.f;
  float m_i[4], l_i[4];
#pragma unroll
  for (int i = 0; i < 4; i++) { m_i[i] = -1e30f; l_i[i] = 0.f; }

  for (int kb = 0; kb <= qb; kb++) {
    const int k0 = kb * 64;
    __syncthreads();

    {
      const int r = tid >> 4;
      const int cg = (tid & 15) << 2;
#pragma unroll
      for (int rep = 0; rep < 4; rep++) {
        int rr = r + (rep << 4);
        float4 v4 = *(const float4*)(K + (size_t)(k0 + rr) * KVDIM + kh * HDIM + cg);
        Ks[(cg + 0) * 64 + rr] = v4.x;
        Ks[(cg + 1) * 64 + rr] = v4.y;
        Ks[(cg + 2) * 64 + rr] = v4.z;
        Ks[(cg + 3) * 64 + rr] = v4.w;
      }
    }
    {
#pragma unroll
      for (int t = 0; t < 8; t++) {
        int idx = tid + (t << 8);
        int row = idx >> 5;
        int col = (idx & 31) << 2;
        int sh = (col < 64) ? vh0 : vh1;
        int sc = (col < 64) ? col : (col - 64);
        float4 v4 = *(const float4*)(V + (size_t)(k0 + row) * KVDIM + sh * HDIM + sc);
        *(float4*)(Vs + row * 128 + col) = v4;
      }
    }
    __syncthreads();

    float s[4][4];
#pragma unroll
    for (int i = 0; i < 4; i++)
#pragma unroll
      for (int j = 0; j < 4; j++) s[i][j] = 0.f;
#pragma unroll 8
    for (int d = 0; d < 64; d++) {
      float4 aq = *(const float4*)(Qs + d * 64 + (ty << 2));
      float4 bk = *(const float4*)(Ks + d * 64 + (tx << 2));
      float av[4] = {aq.x, aq.y, aq.z, aq.w};
      float bv[4] = {bk.x, bk.y, bk.z, bk.w};
#pragma unroll
      for (int i = 0; i < 4; i++)
#pragma unroll
        for (int j = 0; j < 4; j++)
          s[i][j] = fmaf(av[i], bv[j], s[i][j]);
    }
    const bool diag = (kb == qb);
#pragma unroll
    for (int i = 0; i < 4; i++)
#pragma unroll
      for (int j = 0; j < 4; j++) {
        s[i][j] *= 0.125f;
        if (diag && (k0 + (tx << 2) + j) > (q0 + (ty << 2) + i)) s[i][j] = -1e30f;
      }

    float rm[4];
#pragma unroll
    for (int i = 0; i < 4; i++)
      rm[i] = fmaxf(fmaxf(s[i][0], s[i][1]), fmaxf(s[i][2], s[i][3]));
#pragma unroll
    for (int off = 8; off > 0; off >>= 1)
#pragma unroll
      for (int i = 0; i < 4; i++)
        rm[i] = fmaxf(rm[i], __shfl_xor_sync(0xffffffffu, rm[i], off));

    float alpha[4], rs[4];
    float p[4][4];
#pragma unroll
    for (int i = 0; i < 4; i++) {
      float mn = fmaxf(m_i[i], rm[i]);
      alpha[i] = __expf(m_i[i] - mn);
      m_i[i] = mn;
      rs[i] = 0.f;
#pragma unroll
      for (int j = 0; j < 4; j++) {
        p[i][j] = __expf(s[i][j] - mn);
        rs[i] += p[i][j];
      }
    }
#pragma unroll
    for (int off = 8; off > 0; off >>= 1)
#pragma unroll
      for (int i = 0; i < 4; i++)
        rs[i] += __shfl_xor_sync(0xffffffffu, rs[i], off);
#pragma unroll
    for (int i = 0; i < 4; i++) {
      l_i[i] = l_i[i] * alpha[i] + rs[i];
#pragma unroll
      for (int c = 0; c < 8; c++) acc[i][c] *= alpha[i];
    }

#pragma unroll
    for (int i = 0; i < 4; i++) {
      float4 pw = make_float4(p[i][0], p[i][1], p[i][2], p[i][3]);
      *(float4*)(Ps + ((ty << 2) + i) * 68 + (tx << 2)) = pw;
    }
    __syncthreads();

#pragma unroll 4
    for (int kk = 0; kk < 64; kk++) {
      float pa0 = Ps[((ty << 2) + 0) * 68 + kk];
      float pa1 = Ps[((ty << 2) + 1) * 68 + kk];
      float pa2 = Ps[((ty << 2) + 2) * 68 + kk];
      float pa3 = Ps[((ty << 2) + 3) * 68 + kk];
      float4 v0 = *(const float4*)(Vs + kk * 128 + (tx << 2));
      float4 v1 = *(const float4*)(Vs + kk * 128 + 64 + (tx << 2));
      float vb[8] = {v0.x, v0.y, v0.z, v0.w, v1.x, v1.y, v1.z, v1.w};
      float pa[4] = {pa0, pa1, pa2, pa3};
#pragma unroll
      for (int i = 0; i < 4; i++)
#pragma unroll
        for (int c = 0; c < 8; c++)
          acc[i][c] = fmaf(pa[i], vb[c], acc[i][c]);
    }
  }

#pragma unroll
  for (int i = 0; i < 4; i++) {
    float inv = 1.0f / l_i[i];
    int row = q0 + (ty << 2) + i;
    float4 o0 = make_float4(acc[i][0] * inv, acc[i][1] * inv, acc[i][2] * inv, acc[i][3] * inv);
    float4 o1 = make_float4(acc[i][4] * inv, acc[i][5] * inv, acc[i][6] * inv, acc[i][7] * inv);
    *(float4*)(O + ((size_t)h * S_LEN + row) * VD + (tx << 2)) = o0;
    *(float4*)(O + ((size_t)h * S_LEN + row) * VD + 64 + (tx << 2)) = o1;
  }
}

// ---------------- differential combine + RMS norm -> bf16 concat ----------------
__global__ void combine_kernel(const float* __restrict__ O, __nv_bfloat16* __restrict__ Ac) {
  const int s = blockIdx.x;
  const int i = blockIdx.y;
  const int d = threadIdx.x;  // 128
  const float lam = g_lam;
  float o1 = O[((size_t)i * S_LEN + s) * VD + d];
  float o2 = O[((size_t)(i + 16) * S_LEN + s) * VD + d];
  float a = o1 - lam * o2;
  float ss = a * a;
#pragma unroll
  for (int off = 16; off > 0; off >>= 1)
    ss += __shfl_xor_sync(0xffffffffu, ss, off);
  __shared__ float ws[4];
  int warp = d >> 5, lane = d & 31;
  if (lane == 0) ws[warp] = ss;
  __syncthreads();
  float tot = ws[0] + ws[1] + ws[2] + ws[3];
  float r = rsqrtf(tot * (1.0f / 128.0f) + 1e-6f);
  float aval = (1.0f - LAMBDA_INIT) * a * r;
  __nv_bfloat16 h = __float2bfloat16_rn(aval);
  __nv_bfloat16 l = __float2bfloat16_rn(aval - __bfloat162float(h));
  size_t base = (size_t)s * KC3 + i * VD + d;
  Ac[base]            = h;   // seg0: hi
  Ac[base + QDIM]     = h;   // seg1: hi (activation pattern [h,h,l])
  Ac[base + 2 * QDIM] = l;   // seg2: lo
}

// ---------------- launch ----------------
extern "C" void kernel_launch(void* const* d_in, const int* in_sizes, int n_in,
                              void* d_out, int out_size) {
  const float* hidden = (const float*)d_in[0];
  const float* cosb   = (const float*)d_in[1];
  const float* sinb   = (const float*)d_in[2];
  const float* Wq     = (const float*)d_in[3];
  const float* Wk     = (const float*)d_in[4];
  const float* Wv     = (const float*)d_in[5];
  const float* Wo     = (const float*)d_in[6];
  const float* lq1    = (const float*)d_in[7];
  const float* lk1    = (const float*)d_in[8];
  const float* lq2    = (const float*)d_in[9];
  const float* lk2    = (const float*)d_in[10];
  float* out = (float*)d_out;

  float *Qp, *Kp, *Vp, *Op;
  cudaGetSymbolAddress((void**)&Qp, g_Q);
  cudaGetSymbolAddress((void**)&Kp, g_K);
  cudaGetSymbolAddress((void**)&Vp, g_V);
  cudaGetSymbolAddress((void**)&Op, g_O);
  __nv_bfloat16 *Hc, *Wqc, *Wkc, *Wvc, *Woc, *Ac;
  cudaGetSymbolAddress((void**)&Hc, g_Hc);
  cudaGetSymbolAddress((void**)&Wqc, g_Wqc);
  cudaGetSymbolAddress((void**)&Wkc, g_Wkc);
  cudaGetSymbolAddress((void**)&Wvc, g_Wvc);
  cudaGetSymbolAddress((void**)&Woc, g_Woc);
  cudaGetSymbolAddress((void**)&Ac, g_Ac);

  // splits (fp32 -> bf16 concat)
  {
    int n = S_LEN * HID;
    splitcat_kernel<<<n / 4 / 256, 256>>>(hidden, Hc, HID, 0, n);
    n = QDIM * HID;
    splitcat_kernel<<<n / 4 / 256, 256>>>(Wq, Wqc, HID, 1, n);
    n = KVDIM * HID;
    splitcat_kernel<<<n / 4 / 256, 256>>>(Wk, Wkc, HID, 1, n);
    splitcat_kernel<<<n / 4 / 256, 256>>>(Wv, Wvc, HID, 1, n);
    n = HID * QDIM;
    splitcat_kernel<<<n / 4 / 256, 256>>>(Wo, Woc, QDIM, 1, n);
  }

  // QKV projections (HMMA bf16x3 via concat-K)
  hgemm_qkv_kernel<<<dim3(QDIM / 128, S_LEN / 128, 3), 256>>>(Hc, Wqc, Wkc, Wvc, Qp, Kp, Vp);

  // RoPE
  rope_kernel<<<(S_LEN * (QDIM / 2)) / 256, 256>>>(Qp, cosb, sinb, QDIM);
  rope_kernel<<<(S_LEN * (KVDIM / 2)) / 256, 256>>>(Kp, cosb, sinb, KVDIM);

  // lambda
  lam_kernel<<<1, 32>>>(lq1, lk1, lq2, lk2);

  // attention
  int smemBytes = (4096 + 4096 + 8192 + 64 * 68) * 4;
  cudaFuncSetAttribute(flash_attn_kernel, cudaFuncAttributeMaxDynamicSharedMemorySize, smemBytes);
  flash_attn_kernel<<<dim3(32, 32), 256, smemBytes>>>(Qp, Kp, Vp, Op);

  // combine + RMS norm -> bf16 concat activations
  combine_kernel<<<dim3(S_LEN, 16), 128>>>(Op, Ac);

  // output projection
  hgemm_o_kernel<<<dim3(QDIM / 128, S_LEN / 128), 256>>>(Ac, Woc, out);
}

// round 5
// speedup vs baseline: 2.0460x; 1.5869x over previous
#include <cuda_runtime.h>
#include <cuda_bf16.h>
#include <math.h>
#include <stdint.h>

#define S_LEN 2048
#define HID   2048
#define NHEADS 32
#define HDIM   64
#define QDIM  2048
#define KVDIM  512
#define VD     128
#define KC3   (3 * HID)     // 6144, concat-K for bf16x3
#define LAMBDA_INIT 0.7455692280263552f

// ---------------- scratch ----------------
__device__ float g_Q[(size_t)S_LEN * QDIM];
__device__ float g_K[(size_t)S_LEN * KVDIM];
__device__ float g_V[(size_t)S_LEN * KVDIM];
__device__ float g_O[(size_t)NHEADS * S_LEN * VD];
__device__ float g_lam;
__device__ __align__(256) __nv_bfloat16 g_Hc[(size_t)S_LEN * KC3];
__device__ __align__(256) __nv_bfloat16 g_Wqc[(size_t)QDIM * KC3];
__device__ __align__(256) __nv_bfloat16 g_Wkc[(size_t)KVDIM * KC3];
__device__ __align__(256) __nv_bfloat16 g_Wvc[(size_t)KVDIM * KC3];
__device__ __align__(256) __nv_bfloat16 g_Woc[(size_t)HID * KC3];
__device__ __align__(256) __nv_bfloat16 g_Ac[(size_t)S_LEN * KC3];
// attention operands (bf16 hi/lo)
__device__ __align__(256) __nv_bfloat16 g_Qh[(size_t)S_LEN * QDIM],  g_Ql[(size_t)S_LEN * QDIM];
__device__ __align__(256) __nv_bfloat16 g_Kh[(size_t)S_LEN * KVDIM], g_Kl[(size_t)S_LEN * KVDIM];
__device__ __align__(256) __nv_bfloat16 g_Vth[(size_t)KVDIM * S_LEN], g_Vtl[(size_t)KVDIM * S_LEN]; // transposed [d][s]

// ---------------- helpers ----------------
__device__ __forceinline__ uint32_t smem_u32(const void* p) {
  uint32_t r;
  asm("{ .reg .u64 t; cvta.to.shared.u64 t, %1; cvt.u32.u64 %0, t; }" : "=r"(r) : "l"(p));
  return r;
}
#define CP_ASYNC16(sa, ga) \
  asm volatile("cp.async.cg.shared.global [%0], [%1], 16;" :: "r"(sa), "l"(ga) : "memory")
#define CP_COMMIT() asm volatile("cp.async.commit_group;" ::: "memory")
#define CP_WAIT0()  asm volatile("cp.async.wait_group 0;" ::: "memory")

#define LDMATRIX_X4(r0, r1, r2, r3, addr) \
  asm volatile("ldmatrix.sync.aligned.m8n8.x4.shared.b16 {%0,%1,%2,%3}, [%4];" \
               : "=r"(r0), "=r"(r1), "=r"(r2), "=r"(r3) : "r"(addr))

#define MMA16816(c0, c1, c2, c3, a0, a1, a2, a3, b0, b1) \
  asm volatile("mma.sync.aligned.m16n8k16.row.col.f32.bf16.bf16.f32 " \
               "{%0,%1,%2,%3}, {%4,%5,%6,%7}, {%8,%9}, {%0,%1,%2,%3};" \
               : "+f"(c0), "+f"(c1), "+f"(c2), "+f"(c3) \
               : "r"(a0), "r"(a1), "r"(a2), "r"(a3), "r"(b0), "r"(b1))

__device__ __forceinline__ uint32_t pack2bf_res(float a, float b, float& ra, float& rb) {
  __nv_bfloat16 ha = __float2bfloat16_rn(a), hb = __float2bfloat16_rn(b);
  ra = a - __bfloat162float(ha);
  rb = b - __bfloat162float(hb);
  return (uint32_t)__bfloat16_as_ushort(ha) | ((uint32_t)__bfloat16_as_ushort(hb) << 16);
}
__device__ __forceinline__ uint32_t pack2bf(float a, float b) {
  return (uint32_t)__bfloat16_as_ushort(__float2bfloat16_rn(a)) |
         ((uint32_t)__bfloat16_as_ushort(__float2bfloat16_rn(b)) << 16);
}

// ---------------- bf16 HMMA GEMM ----------------
#define ROWB 80
#define TILE_B (128 * ROWB)

__device__ __forceinline__ void hgemm_core(
    const __nv_bfloat16* __restrict__ A, const __nv_bfloat16* __restrict__ B,
    float* __restrict__ C, int N, int Kc, int m0, int n0) {
  __shared__ __align__(16) char smA[2 * TILE_B];
  __shared__ __align__(16) char smB[2 * TILE_B];
  const int tid = threadIdx.x;
  const int warp = tid >> 5;
  const int lane = tid & 31;
  const int wm = warp & 1;
  const int wn = warp >> 1;
  const uint32_t sA = smem_u32(smA);
  const uint32_t sB = smem_u32(smB);
  const int lrow = tid >> 1;
  const int lch0 = (tid & 1) << 1;

  float acc[4][4][4];
#pragma unroll
  for (int i = 0; i < 4; i++)
#pragma unroll
    for (int j = 0; j < 4; j++)
#pragma unroll
      for (int c = 0; c < 4; c++) acc[i][j][c] = 0.f;

  const int T = Kc >> 5;
  {
    const __nv_bfloat16* ag = A + (size_t)(m0 + lrow) * Kc + lch0 * 8;
    const __nv_bfloat16* bg = B + (size_t)(n0 + lrow) * Kc + lch0 * 8;
    uint32_t so = lrow * ROWB + lch0 * 16;
    CP_ASYNC16(sA + so, ag);       CP_ASYNC16(sA + so + 16, ag + 8);
    CP_ASYNC16(sB + so, bg);       CP_ASYNC16(sB + so + 16, bg + 8);
    CP_COMMIT();
  }

  for (int t = 0; t < T; ++t) {
    CP_WAIT0();
    __syncthreads();
    const uint32_t cb = (uint32_t)(t & 1) * TILE_B;
    if (t + 1 < T) {
      const uint32_t pb = (uint32_t)((t + 1) & 1) * TILE_B;
      const int k0 = (t + 1) << 5;
      const __nv_bfloat16* ag = A + (size_t)(m0 + lrow) * Kc + k0 + lch0 * 8;
      const __nv_bfloat16* bg = B + (size_t)(n0 + lrow) * Kc + k0 + lch0 * 8;
      uint32_t so = pb + lrow * ROWB + lch0 * 16;
      CP_ASYNC16(sA + so, ag);     CP_ASYNC16(sA + so + 16, ag + 8);
      CP_ASYNC16(sB + so, bg);     CP_ASYNC16(sB + so + 16, bg + 8);
      CP_COMMIT();
    }

#pragma unroll
    for (int ks = 0; ks < 2; ++ks) {
      uint32_t a[4][4];
#pragma unroll
      for (int mi = 0; mi < 4; ++mi) {
        uint32_t addr = sA + cb + (uint32_t)((wm << 6) + (mi << 4) + (lane & 15)) * ROWB
                        + ((lane >> 4) << 4) + (ks << 5);
        LDMATRIX_X4(a[mi][0], a[mi][1], a[mi][2], a[mi][3], addr);
      }
      uint32_t b[4][2];
#pragma unroll
      for (int pr = 0; pr < 2; ++pr) {
        int r = (lane & 7) + (((lane >> 4) & 1) << 3);
        int hk = (lane >> 3) & 1;
        uint32_t addr = sB + cb + (uint32_t)((wn << 5) + (pr << 4) + r) * ROWB
                        + (hk << 4) + (ks << 5);
        uint32_t r0, r1, r2, r3;
        LDMATRIX_X4(r0, r1, r2, r3, addr);
        b[pr * 2 + 0][0] = r0; b[pr * 2 + 0][1] = r1;
        b[pr * 2 + 1][0] = r2; b[pr * 2 + 1][1] = r3;
      }
#pragma unroll
      for (int mi = 0; mi < 4; ++mi)
#pragma unroll
        for (int ni = 0; ni < 4; ++ni)
          MMA16816(acc[mi][ni][0], acc[mi][ni][1], acc[mi][ni][2], acc[mi][ni][3],
                   a[mi][0], a[mi][1], a[mi][2], a[mi][3], b[ni][0], b[ni][1]);
    }
    __syncthreads();
  }

#pragma unroll
  for (int mi = 0; mi < 4; ++mi) {
    int row = m0 + (wm << 6) + (mi << 4) + (lane >> 2);
#pragma unroll
    for (int ni = 0; ni < 4; ++ni) {
      int col = n0 + (wn << 5) + (ni << 3) + ((lane & 3) << 1);
      *(float2*)(C + (size_t)row * N + col)       = make_float2(acc[mi][ni][0], acc[mi][ni][1]);
      *(float2*)(C + (size_t)(row + 8) * N + col) = make_float2(acc[mi][ni][2], acc[mi][ni][3]);
    }
  }
}

__global__ __launch_bounds__(256, 1) void hgemm_qkv_kernel(
    const __nv_bfloat16* __restrict__ Hc,
    const __nv_bfloat16* __restrict__ Wqc, const __nv_bfloat16* __restrict__ Wkc,
    const __nv_bfloat16* __restrict__ Wvc,
    float* __restrict__ Qo, float* __restrict__ Ko, float* __restrict__ Vo) {
  const int z = blockIdx.z;
  const __nv_bfloat16* Bp;
  float* C;
  int N;
  if (z == 0)      { Bp = Wqc; C = Qo; N = QDIM; }
  else if (z == 1) { Bp = Wkc; C = Ko; N = KVDIM; }
  else             { Bp = Wvc; C = Vo; N = KVDIM; }
  const int n0 = blockIdx.x << 7;
  if (n0 >= N) return;
  const int m0 = blockIdx.y << 7;
  hgemm_core(Hc, Bp, C, N, KC3, m0, n0);
}

__global__ __launch_bounds__(256, 1) void hgemm_o_kernel(
    const __nv_bfloat16* __restrict__ Ac, const __nv_bfloat16* __restrict__ Woc,
    float* __restrict__ out) {
  hgemm_core(Ac, Woc, out, HID, KC3, blockIdx.y << 7, blockIdx.x << 7);
}

// ---------------- fp32 -> bf16 hi/lo concat split ----------------
__global__ void splitcat_kernel(const float* __restrict__ x, __nv_bfloat16* __restrict__ o,
                                int K, int isW, int total) {
  int i4 = (blockIdx.x * blockDim.x + threadIdx.x) << 2;
  if (i4 >= total) return;
  float4 v = *(const float4*)(x + i4);
  int row = i4 / K;
  int col = i4 - row * K;
  __nv_bfloat16 h[4], l[4];
  float vv[4] = {v.x, v.y, v.z, v.w};
#pragma unroll
  for (int j = 0; j < 4; j++) {
    h[j] = __float2bfloat16_rn(vv[j]);
    l[j] = __float2bfloat16_rn(vv[j] - __bfloat162float(h[j]));
  }
  size_t base = (size_t)row * (3 * K) + col;
  uint2 ph, pl;
  ph.x = (uint32_t)__bfloat16_as_ushort(h[0]) | ((uint32_t)__bfloat16_as_ushort(h[1]) << 16);
  ph.y = (uint32_t)__bfloat16_as_ushort(h[2]) | ((uint32_t)__bfloat16_as_ushort(h[3]) << 16);
  pl.x = (uint32_t)__bfloat16_as_ushort(l[0]) | ((uint32_t)__bfloat16_as_ushort(l[1]) << 16);
  pl.y = (uint32_t)__bfloat16_as_ushort(l[2]) | ((uint32_t)__bfloat16_as_ushort(l[3]) << 16);
  *(uint2*)(o + base) = ph;
  if (isW) {
    *(uint2*)(o + base + K)     = pl;
    *(uint2*)(o + base + 2 * K) = ph;
  } else {
    *(uint2*)(o + base + K)     = ph;
    *(uint2*)(o + base + 2 * K) = pl;
  }
}

// ---------------- RoPE + hi/lo split ----------------
__global__ void rope_split_kernel(const float* __restrict__ X, const float* __restrict__ cosb,
                                  const float* __restrict__ sinb,
                                  __nv_bfloat16* __restrict__ Xh, __nv_bfloat16* __restrict__ Xl,
                                  int width) {
  int idx = blockIdx.x * blockDim.x + threadIdx.x;
  int pairsPerRow = width >> 1;
  int total = S_LEN * pairsPerRow;
  if (idx >= total) return;
  int s = idx / pairsPerRow;
  int p = idx - s * pairsPerRow;
  int head = p >> 5;
  int d = p & 31;
  int c1 = head * HDIM + d;
  float c   = cosb[s * HDIM + d];
  float sn  = sinb[s * HDIM + d];
  float c2  = cosb[s * HDIM + d + 32];
  float sn2 = sinb[s * HDIM + d + 32];
  size_t base = (size_t)s * width;
  float x1 = X[base + c1];
  float x2 = X[base + c1 + 32];
  float y1 = x1 * c  - x2 * sn;
  float y2 = x2 * c2 + x1 * sn2;
  __nv_bfloat16 h1 = __float2bfloat16_rn(y1);
  __nv_bfloat16 h2 = __float2bfloat16_rn(y2);
  Xh[base + c1]      = h1;
  Xh[base + c1 + 32] = h2;
  Xl[base + c1]      = __float2bfloat16_rn(y1 - __bfloat162float(h1));
  Xl[base + c1 + 32] = __float2bfloat16_rn(y2 - __bfloat162float(h2));
}

// ---------------- V transpose + split: Vt[d][s] ----------------
__global__ void vsplit_t_kernel(const float* __restrict__ V,
                                __nv_bfloat16* __restrict__ Vth, __nv_bfloat16* __restrict__ Vtl) {
  __shared__ float tile[32][33];
  int c0 = blockIdx.x << 5;
  int s0 = blockIdx.y << 5;
  int tx = threadIdx.x, ty = threadIdx.y;  // 32 x 8
#pragma unroll
  for (int i = 0; i < 4; i++)
    tile[ty + i * 8][tx] = V[(size_t)(s0 + ty + i * 8) * KVDIM + c0 + tx];
  __syncthreads();
#pragma unroll
  for (int i = 0; i < 4; i++) {
    int r = ty + i * 8;
    float v = tile[tx][r];
    __nv_bfloat16 hv = __float2bfloat16_rn(v);
    Vth[(size_t)(c0 + r) * S_LEN + s0 + tx] = hv;
    Vtl[(size_t)(c0 + r) * S_LEN + s0 + tx] = __float2bfloat16_rn(v - __bfloat162float(hv));
  }
}

// ---------------- lambda ----------------
__global__ void lam_kernel(const float* __restrict__ lq1, const float* __restrict__ lk1,
                           const float* __restrict__ lq2, const float* __restrict__ lk2) {
  int d = threadIdx.x;
  float s1 = lq1[d] * lk1[d] + lq1[d + 32] * lk1[d + 32];
  float s2 = lq2[d] * lk2[d] + lq2[d + 32] * lk2[d + 32];
#pragma unroll
  for (int off = 16; off > 0; off >>= 1) {
    s1 += __shfl_xor_sync(0xffffffffu, s1, off);
    s2 += __shfl_xor_sync(0xffffffffu, s2, off);
  }
  if (d == 0) g_lam = expf(s1) - expf(s2) + LAMBDA_INIT;
}

// ---------------- HMMA flash attention ----------------
#define ATT_QH   0
#define ATT_QL   18432
#define ATT_ST   36864
#define ATT_STGB 55296
#define ATT_SMEM (36864 + 2 * 55296)

__global__ __launch_bounds__(256, 1) void flash_attn_hmma(
    const __nv_bfloat16* __restrict__ Qh, const __nv_bfloat16* __restrict__ Ql,
    const __nv_bfloat16* __restrict__ Kh, const __nv_bfloat16* __restrict__ Kl,
    const __nv_bfloat16* __restrict__ Vth, const __nv_bfloat16* __restrict__ Vtl,
    float* __restrict__ O) {
  extern __shared__ char sm[];
  const uint32_t sb = smem_u32(sm);
  const int tid = threadIdx.x;
  const int w = tid >> 5, lane = tid & 31;
  const int h = blockIdx.y;
  const int qb = 15 - (int)blockIdx.x;
  const int q0 = qb << 7;
  const int kh = h >> 2;
  const int ii = h & 15;
  const int vh0 = ii >> 2, vh1 = 4 + (ii >> 2);
  const int nk = 2 * qb + 2;

  auto load_stage = [&](int k0, uint32_t stg) {
#pragma unroll
    for (int i = 0; i < 12; i++) {
      int id = tid + (i << 8);
      if (id < 1024) {
        int half = id >> 9;
        int t = id & 511;
        int row = t >> 3, ch = t & 7;
        const __nv_bfloat16* src = (half ? Kl : Kh) + (size_t)(k0 + row) * KVDIM + kh * HDIM + ch * 8;
        CP_ASYNC16(stg + half * 9216 + row * 144 + ch * 16, src);
      } else {
        int id2 = id - 1024;
        int half = id2 >> 10;
        int t = id2 & 1023;
        int row = t >> 3, ch = t & 7;
        int grow = (row < 64) ? (vh0 * HDIM + row) : (vh1 * HDIM + row - 64);
        const __nv_bfloat16* src = (half ? Vtl : Vth) + (size_t)grow * S_LEN + k0 + ch * 8;
        CP_ASYNC16(stg + 18432 + half * 18432 + row * 144 + ch * 16, src);
      }
    }
  };

  {
#pragma unroll
    for (int i = 0; i < 8; i++) {
      int id = tid + (i << 8);
      int half = id >> 10;
      int t = id & 1023;
      int row = t >> 3, ch = t & 7;
      const __nv_bfloat16* src = (half ? Ql : Qh) + (size_t)(q0 + row) * QDIM + h * HDIM + ch * 8;
      CP_ASYNC16(sb + half * 18432 + row * 144 + ch * 16, src);
    }
    load_stage(0, sb + ATT_ST);
    CP_COMMIT();
    CP_WAIT0();
  }
  __syncthreads();

  uint32_t qfh[4][4], qfl[4][4];
#pragma unroll
  for (int s = 0; s < 4; s++) {
    uint32_t a = sb + (uint32_t)(w * 16 + (lane & 15)) * 144 + ((lane >> 4) << 4) + s * 32;
    LDMATRIX_X4(qfh[s][0], qfh[s][1], qfh[s][2], qfh[s][3], a);
    LDMATRIX_X4(qfl[s][0], qfl[s][1], qfl[s][2], qfl[s][3], a + 18432);
  }

  float oacc[16][4];
#pragma unroll
  for (int n = 0; n < 16; n++)
#pragma unroll
    for (int c = 0; c < 4; c++) oacc[n][c] = 0.f;
  float m0r = -1e30f, m1r = -1e30f, l0r = 0.f, l1r = 0.f;
  const int rmin = q0 + w * 16;
  const int rmax = rmin + 15;
  const int r0g = rmin + (lane >> 2);
  const int r1g = r0g + 8;

  for (int kb = 0; kb < nk; kb++) {
    const int k0 = kb << 6;
    const uint32_t stg = sb + ATT_ST + (uint32_t)(kb & 1) * ATT_STGB;
    if (kb + 1 < nk) {
      load_stage((kb + 1) << 6, sb + ATT_ST + (uint32_t)((kb + 1) & 1) * ATT_STGB);
      CP_COMMIT();
    }

    if (k0 <= rmax) {
      // ---- S = Q K^T (bf16x3) ----
      float sacc[8][4];
#pragma unroll
      for (int j = 0; j < 8; j++)
#pragma unroll
        for (int c = 0; c < 4; c++) sacc[j][c] = 0.f;

#pragma unroll
      for (int j = 0; j < 8; j++) {
        uint32_t bh[2][4], bl[2][4];
#pragma unroll
        for (int s2 = 0; s2 < 2; s2++) {
          uint32_t a = stg + (uint32_t)(j * 8 + (lane & 7)) * 144 + s2 * 64 + ((lane >> 3) & 3) * 16;
          LDMATRIX_X4(bh[s2][0], bh[s2][1], bh[s2][2], bh[s2][3], a);
          LDMATRIX_X4(bl[s2][0], bl[s2][1], bl[s2][2], bl[s2][3], a + 9216);
        }
#pragma unroll
        for (int s = 0; s < 4; s++) {
          uint32_t b0h = bh[s >> 1][(s & 1) * 2], b1h = bh[s >> 1][(s & 1) * 2 + 1];
          uint32_t b0l = bl[s >> 1][(s & 1) * 2], b1l = bl[s >> 1][(s & 1) * 2 + 1];
          MMA16816(sacc[j][0], sacc[j][1], sacc[j][2], sacc[j][3],
                   qfh[s][0], qfh[s][1], qfh[s][2], qfh[s][3], b0h, b1h);
          MMA16816(sacc[j][0], sacc[j][1], sacc[j][2], sacc[j][3],
                   qfh[s][0], qfh[s][1], qfh[s][2], qfh[s][3], b0l, b1l);
          MMA16816(sacc[j][0], sacc[j][1], sacc[j][2], sacc[j][3],
                   qfl[s][0], qfl[s][1], qfl[s][2], qfl[s][3], b0h, b1h);
        }
      }

      // ---- scale + causal mask (FIX: compare vs warp's FIRST row) ----
      const bool needmask = (k0 + 63) > rmin;
#pragma unroll
      for (int j = 0; j < 8; j++) {
        int cb = k0 + j * 8 + ((lane & 3) << 1);
        sacc[j][0] *= 0.125f; sacc[j][1] *= 0.125f;
        sacc[j][2] *= 0.125f; sacc[j][3] *= 0.125f;
        if (needmask) {
          if (cb     > r0g) sacc[j][0] = -1e30f;
          if (cb + 1 > r0g) sacc[j][1] = -1e30f;
          if (cb     > r1g) sacc[j][2] = -1e30f;
          if (cb + 1 > r1g) sacc[j][3] = -1e30f;
        }
      }

      // ---- online softmax ----
      float mx0 = -1e30f, mx1 = -1e30f;
#pragma unroll
      for (int j = 0; j < 8; j++) {
        mx0 = fmaxf(mx0, fmaxf(sacc[j][0], sacc[j][1]));
        mx1 = fmaxf(mx1, fmaxf(sacc[j][2], sacc[j][3]));
      }
      mx0 = fmaxf(mx0, __shfl_xor_sync(0xffffffffu, mx0, 1));
      mx0 = fmaxf(mx0, __shfl_xor_sync(0xffffffffu, mx0, 2));
      mx1 = fmaxf(mx1, __shfl_xor_sync(0xffffffffu, mx1, 1));
      mx1 = fmaxf(mx1, __shfl_xor_sync(0xffffffffu, mx1, 2));
      float mn0 = fmaxf(m0r, mx0), mn1 = fmaxf(m1r, mx1);
      float al0 = __expf(m0r - mn0), al1 = __expf(m1r - mn1);
      m0r = mn0; m1r = mn1;

      float sum0 = 0.f, sum1 = 0.f;
      uint32_t ph[8][2], pl[8][2];
#pragma unroll
      for (int j = 0; j < 8; j++) {
        float p0 = __expf(sacc[j][0] - mn0);
        float p1 = __expf(sacc[j][1] - mn0);
        float p2 = __expf(sacc[j][2] - mn1);
        float p3 = __expf(sacc[j][3] - mn1);
        sum0 += p0 + p1; sum1 += p2 + p3;
        float ra, rb;
        ph[j][0] = pack2bf_res(p0, p1, ra, rb);
        pl[j][0] = pack2bf(ra, rb);
        ph[j][1] = pack2bf_res(p2, p3, ra, rb);
        pl[j][1] = pack2bf(ra, rb);
      }
      sum0 += __shfl_xor_sync(0xffffffffu, sum0, 1);
      sum0 += __shfl_xor_sync(0xffffffffu, sum0, 2);
      sum1 += __shfl_xor_sync(0xffffffffu, sum1, 1);
      sum1 += __shfl_xor_sync(0xffffffffu, sum1, 2);
      l0r = l0r * al0 + sum0;
      l1r = l1r * al1 + sum1;
#pragma unroll
      for (int n = 0; n < 16; n++) {
        oacc[n][0] *= al0; oacc[n][1] *= al0;
        oacc[n][2] *= al1; oacc[n][3] *= al1;
      }

      // ---- O += P V (bf16x3) ----
#pragma unroll
      for (int n = 0; n < 16; n++) {
        uint32_t vh[2][4], vl[2][4];
#pragma unroll
        for (int s2 = 0; s2 < 2; s2++) {
          uint32_t a = stg + 18432 + (uint32_t)(n * 8 + (lane & 7)) * 144 + s2 * 64 + ((lane >> 3) & 3) * 16;
          LDMATRIX_X4(vh[s2][0], vh[s2][1], vh[s2][2], vh[s2][3], a);
          LDMATRIX_X4(vl[s2][0], vl[s2][1], vl[s2][2], vl[s2][3], a + 18432);
        }
#pragma unroll
        for (int t = 0; t < 4; t++) {
          uint32_t a0 = ph[2 * t][0], a1 = ph[2 * t][1], a2 = ph[2 * t + 1][0], a3 = ph[2 * t + 1][1];
          uint32_t c0 = pl[2 * t][0], c1 = pl[2 * t][1], c2 = pl[2 * t + 1][0], c3 = pl[2 * t + 1][1];
          uint32_t b0h = vh[t >> 1][(t & 1) * 2], b1h = vh[t >> 1][(t & 1) * 2 + 1];
          uint32_t b0l = vl[t >> 1][(t & 1) * 2], b1l = vl[t >> 1][(t & 1) * 2 + 1];
          MMA16816(oacc[n][0], oacc[n][1], oacc[n][2], oacc[n][3], a0, a1, a2, a3, b0h, b1h);
          MMA16816(oacc[n][0], oacc[n][1], oacc[n][2], oacc[n][3], a0, a1, a2, a3, b0l, b1l);
          MMA16816(oacc[n][0], oacc[n][1], oacc[n][2], oacc[n][3], c0, c1, c2, c3, b0h, b1h);
        }
      }
    }

    CP_WAIT0();
    __syncthreads();
  }

  // ---- epilogue ----
  float i0 = 1.f / l0r, i1 = 1.f / l1r;
#pragma unroll
  for (int n = 0; n < 16; n++) {
    int col = n * 8 + ((lane & 3) << 1);
    *(float2*)(O + ((size_t)h * S_LEN + r0g) * VD + col) = make_float2(oacc[n][0] * i0, oacc[n][1] * i0);
    *(float2*)(O + ((size_t)h * S_LEN + r1g) * VD + col) = make_float2(oacc[n][2] * i1, oacc[n][3] * i1);
  }
}

// ---------------- differential combine + RMS norm -> bf16 concat ----------------
__global__ void combine_kernel(const float* __restrict__ O, __nv_bfloat16* __restrict__ Ac) {
  const int s = blockIdx.x;
  const int i = blockIdx.y;
  const int d = threadIdx.x;  // 128
  const float lam = g_lam;
  float o1 = O[((size_t)i * S_LEN + s) * VD + d];
  float o2 = O[((size_t)(i + 16) * S_LEN + s) * VD + d];
  float a = o1 - lam * o2;
  float ss = a * a;
#pragma unroll
  for (int off = 16; off > 0; off >>= 1)
    ss += __shfl_xor_sync(0xffffffffu, ss, off);
  __shared__ float ws[4];
  int warp = d >> 5, lane = d & 31;
  if (lane == 0) ws[warp] = ss;
  __syncthreads();
  float tot = ws[0] + ws[1] + ws[2] + ws[3];
  float r = rsqrtf(tot * (1.0f / 128.0f) + 1e-6f);
  float aval = (1.0f - LAMBDA_INIT) * a * r;
  __nv_bfloat16 h = __float2bfloat16_rn(aval);
  __nv_bfloat16 l = __float2bfloat16_rn(aval - __bfloat162float(h));
  size_t base = (size_t)s * KC3 + i * VD + d;
  Ac[base]            = h;
  Ac[base + QDIM]     = h;
  Ac[base + 2 * QDIM] = l;
}

// ---------------- launch ----------------
extern "C" void kernel_launch(void* const* d_in, const int* in_sizes, int n_in,
                              void* d_out, int out_size) {
  const float* hidden = (const float*)d_in[0];
  const float* cosb   = (const float*)d_in[1];
  const float* sinb   = (const float*)d_in[2];
  const float* Wq     = (const float*)d_in[3];
  const float* Wk     = (const float*)d_in[4];
  const float* Wv     = (const float*)d_in[5];
  const float* Wo     = (const float*)d_in[6];
  const float* lq1    = (const float*)d_in[7];
  const float* lk1    = (const float*)d_in[8];
  const float* lq2    = (const float*)d_in[9];
  const float* lk2    = (const float*)d_in[10];
  float* out = (float*)d_out;

  float *Qp, *Kp, *Vp, *Op;
  cudaGetSymbolAddress((void**)&Qp, g_Q);
  cudaGetSymbolAddress((void**)&Kp, g_K);
  cudaGetSymbolAddress((void**)&Vp, g_V);
  cudaGetSymbolAddress((void**)&Op, g_O);
  __nv_bfloat16 *Hc, *Wqc, *Wkc, *Wvc, *Woc, *Ac;
  cudaGetSymbolAddress((void**)&Hc, g_Hc);
  cudaGetSymbolAddress((void**)&Wqc, g_Wqc);
  cudaGetSymbolAddress((void**)&Wkc, g_Wkc);
  cudaGetSymbolAddress((void**)&Wvc, g_Wvc);
  cudaGetSymbolAddress((void**)&Woc, g_Woc);
  cudaGetSymbolAddress((void**)&Ac, g_Ac);
  __nv_bfloat16 *Qhp, *Qlp, *Khp, *Klp, *Vthp, *Vtlp;
  cudaGetSymbolAddress((void**)&Qhp, g_Qh);   cudaGetSymbolAddress((void**)&Qlp, g_Ql);
  cudaGetSymbolAddress((void**)&Khp, g_Kh);   cudaGetSymbolAddress((void**)&Klp, g_Kl);
  cudaGetSymbolAddress((void**)&Vthp, g_Vth); cudaGetSymbolAddress((void**)&Vtlp, g_Vtl);

  // splits (fp32 -> bf16 concat)
  {
    int n = S_LEN * HID;
    splitcat_kernel<<<n / 4 / 256, 256>>>(hidden, Hc, HID, 0, n);
    n = QDIM * HID;
    splitcat_kernel<<<n / 4 / 256, 256>>>(Wq, Wqc, HID, 1, n);
    n = KVDIM * HID;
    splitcat_kernel<<<n / 4 / 256, 256>>>(Wk, Wkc, HID, 1, n);
    splitcat_kernel<<<n / 4 / 256, 256>>>(Wv, Wvc, HID, 1, n);
    n = HID * QDIM;
    splitcat_kernel<<<n / 4 / 256, 256>>>(Wo, Woc, QDIM, 1, n);
  }

  // QKV projections (HMMA bf16x3 via concat-K)
  hgemm_qkv_kernel<<<dim3(QDIM / 128, S_LEN / 128, 3), 256>>>(Hc, Wqc, Wkc, Wvc, Qp, Kp, Vp);

  // RoPE + split to bf16 hi/lo; V transpose+split
  rope_split_kernel<<<(S_LEN * (QDIM / 2)) / 256, 256>>>(Qp, cosb, sinb, Qhp, Qlp, QDIM);
  rope_split_kernel<<<(S_LEN * (KVDIM / 2)) / 256, 256>>>(Kp, cosb, sinb, Khp, Klp, KVDIM);
  vsplit_t_kernel<<<dim3(KVDIM / 32, S_LEN / 32), dim3(32, 8)>>>(Vp, Vthp, Vtlp);

  // lambda
  lam_kernel<<<1, 32>>>(lq1, lk1, lq2, lk2);

  // attention (HMMA)
  cudaFuncSetAttribute(flash_attn_hmma, cudaFuncAttributeMaxDynamicSharedMemorySize, ATT_SMEM);
  flash_attn_hmma<<<dim3(16, NHEADS), 256, ATT_SMEM>>>(Qhp, Qlp, Khp, Klp, Vthp, Vtlp, Op);

  // combine + RMS norm -> bf16 concat activations
  combine_kernel<<<dim3(S_LEN, 16), 128>>>(Op, Ac);

  // output projection
  hgemm_o_kernel<<<dim3(QDIM / 128, S_LEN / 128), 256>>>(Ac, Woc, out);
}

// round 6
// speedup vs baseline: 2.3392x; 1.1433x over previous
#include <cuda_runtime.h>
#include <cuda_bf16.h>
#include <math.h>
#include <stdint.h>

#define S_LEN 2048
#define HID   2048
#define NHEADS 32
#define HDIM   64
#define QDIM  2048
#define KVDIM  512
#define VD     128
#define KC3   (3 * HID)     // 6144, concat-K for bf16x3
#define LAMBDA_INIT 0.7455692280263552f

// ---------------- scratch ----------------
__device__ float g_Q[(size_t)S_LEN * QDIM];
__device__ float g_K[(size_t)S_LEN * KVDIM];
__device__ float g_V[(size_t)S_LEN * KVDIM];
__device__ float g_O[(size_t)NHEADS * S_LEN * VD];
__device__ float g_lam;
__device__ __align__(256) __nv_bfloat16 g_Hc[(size_t)S_LEN * KC3];
__device__ __align__(256) __nv_bfloat16 g_Wqc[(size_t)QDIM * KC3];
__device__ __align__(256) __nv_bfloat16 g_Wkc[(size_t)KVDIM * KC3];
__device__ __align__(256) __nv_bfloat16 g_Wvc[(size_t)KVDIM * KC3];
__device__ __align__(256) __nv_bfloat16 g_Woc[(size_t)HID * KC3];
__device__ __align__(256) __nv_bfloat16 g_Ac[(size_t)S_LEN * KC3];
// attention operands (bf16 hi/lo)
__device__ __align__(256) __nv_bfloat16 g_Qh[(size_t)S_LEN * QDIM],  g_Ql[(size_t)S_LEN * QDIM];
__device__ __align__(256) __nv_bfloat16 g_Kh[(size_t)S_LEN * KVDIM], g_Kl[(size_t)S_LEN * KVDIM];
__device__ __align__(256) __nv_bfloat16 g_Vth[(size_t)KVDIM * S_LEN], g_Vtl[(size_t)KVDIM * S_LEN];

// ---------------- helpers ----------------
__device__ __forceinline__ uint32_t smem_u32(const void* p) {
  uint32_t r;
  asm("{ .reg .u64 t; cvta.to.shared.u64 t, %1; cvt.u32.u64 %0, t; }" : "=r"(r) : "l"(p));
  return r;
}
#define CP_ASYNC16(sa, ga) \
  asm volatile("cp.async.cg.shared.global [%0], [%1], 16;" :: "r"(sa), "l"(ga) : "memory")
#define CP_COMMIT() asm volatile("cp.async.commit_group;" ::: "memory")
#define CP_WAIT0()  asm volatile("cp.async.wait_group 0;" ::: "memory")

#define LDMATRIX_X4(r0, r1, r2, r3, addr) \
  asm volatile("ldmatrix.sync.aligned.m8n8.x4.shared.b16 {%0,%1,%2,%3}, [%4];" \
               : "=r"(r0), "=r"(r1), "=r"(r2), "=r"(r3) : "r"(addr))

#define MMA16816(c0, c1, c2, c3, a0, a1, a2, a3, b0, b1) \
  asm volatile("mma.sync.aligned.m16n8k16.row.col.f32.bf16.bf16.f32 " \
               "{%0,%1,%2,%3}, {%4,%5,%6,%7}, {%8,%9}, {%0,%1,%2,%3};" \
               : "+f"(c0), "+f"(c1), "+f"(c2), "+f"(c3) \
               : "r"(a0), "r"(a1), "r"(a2), "r"(a3), "r"(b0), "r"(b1))

__device__ __forceinline__ uint32_t pack2bf_res(float a, float b, float& ra, float& rb) {
  __nv_bfloat16 ha = __float2bfloat16_rn(a), hb = __float2bfloat16_rn(b);
  ra = a - __bfloat162float(ha);
  rb = b - __bfloat162float(hb);
  return (uint32_t)__bfloat16_as_ushort(ha) | ((uint32_t)__bfloat16_as_ushort(hb) << 16);
}
__device__ __forceinline__ uint32_t pack2bf(float a, float b) {
  return (uint32_t)__bfloat16_as_ushort(__float2bfloat16_rn(a)) |
         ((uint32_t)__bfloat16_as_ushort(__float2bfloat16_rn(b)) << 16);
}

// ---------------- bf16 HMMA GEMM: C[M,N] = A[M,Kc] @ B[N,Kc]^T ----------------
// CTA 128x128, BK=64, 256 threads (8 warps 2m x 4n), 2-stage cp.async pipeline,
// one __syncthreads per k-iter, 144B-padded rows, dynamic smem, 2 CTAs/SM.
#define GROWB 144
#define GTILE (128 * GROWB)          // 18432 B per operand tile
#define GSTAGE (2 * GTILE)           // 36864 B per stage (A+B)
#define GSMEM (2 * GSTAGE)           // 73728 B

__device__ __forceinline__ void hgemm_core(
    const __nv_bfloat16* __restrict__ A, const __nv_bfloat16* __restrict__ B,
    float* __restrict__ C, int N, int Kc, int m0, int n0, char* sm) {
  const int tid = threadIdx.x;
  const int warp = tid >> 5;
  const int lane = tid & 31;
  const int wm = warp & 1;
  const int wn = warp >> 1;
  const uint32_t sb = smem_u32(sm);

  // loader: per stage 1024 A-chunks + 1024 B-chunks of 16B; 8 per thread
  const int lrow = tid >> 1;               // 0..127
  const int lch0 = (tid & 1) << 2;         // 0 or 4 (four consecutive 16B chunks)

  float acc[4][4][4];
#pragma unroll
  for (int i = 0; i < 4; i++)
#pragma unroll
    for (int j = 0; j < 4; j++)
#pragma unroll
      for (int c = 0; c < 4; c++) acc[i][j][c] = 0.f;

  const int T = Kc >> 6;

  auto load_stage = [&](int k0, uint32_t st) {
    const __nv_bfloat16* ag = A + (size_t)(m0 + lrow) * Kc + k0 + lch0 * 8;
    const __nv_bfloat16* bg = B + (size_t)(n0 + lrow) * Kc + k0 + lch0 * 8;
    uint32_t so = st + lrow * GROWB + lch0 * 16;
#pragma unroll
    for (int c = 0; c < 4; c++) {
      CP_ASYNC16(so + c * 16, ag + c * 8);
      CP_ASYNC16(so + GTILE + c * 16, bg + c * 8);
    }
  };

  load_stage(0, sb);
  CP_COMMIT();

  for (int t = 0; t < T; ++t) {
    CP_WAIT0();
    __syncthreads();
    const uint32_t cur = sb + (uint32_t)(t & 1) * GSTAGE;
    if (t + 1 < T) {
      load_stage((t + 1) << 6, sb + (uint32_t)((t + 1) & 1) * GSTAGE);
      CP_COMMIT();
    }

#pragma unroll
    for (int ks = 0; ks < 4; ++ks) {
      uint32_t a[4][4];
#pragma unroll
      for (int mi = 0; mi < 4; ++mi) {
        uint32_t addr = cur + (uint32_t)((wm << 6) + (mi << 4) + (lane & 15)) * GROWB
                        + ((lane >> 4) << 4) + (ks << 5);
        LDMATRIX_X4(a[mi][0], a[mi][1], a[mi][2], a[mi][3], addr);
      }
      uint32_t b[4][2];
#pragma unroll
      for (int pr = 0; pr < 2; ++pr) {
        int r = (lane & 7) + (((lane >> 4) & 1) << 3);
        int hk = (lane >> 3) & 1;
        uint32_t addr = cur + GTILE + (uint32_t)((wn << 5) + (pr << 4) + r) * GROWB
                        + (hk << 4) + (ks << 5);
        uint32_t r0, r1, r2, r3;
        LDMATRIX_X4(r0, r1, r2, r3, addr);
        b[pr * 2 + 0][0] = r0; b[pr * 2 + 0][1] = r1;
        b[pr * 2 + 1][0] = r2; b[pr * 2 + 1][1] = r3;
      }
#pragma unroll
      for (int mi = 0; mi < 4; ++mi)
#pragma unroll
        for (int ni = 0; ni < 4; ++ni)
          MMA16816(acc[mi][ni][0], acc[mi][ni][1], acc[mi][ni][2], acc[mi][ni][3],
                   a[mi][0], a[mi][1], a[mi][2], a[mi][3], b[ni][0], b[ni][1]);
    }
  }

#pragma unroll
  for (int mi = 0; mi < 4; ++mi) {
    int row = m0 + (wm << 6) + (mi << 4) + (lane >> 2);
#pragma unroll
    for (int ni = 0; ni < 4; ++ni) {
      int col = n0 + (wn << 5) + (ni << 3) + ((lane & 3) << 1);
      *(float2*)(C + (size_t)row * N + col)       = make_float2(acc[mi][ni][0], acc[mi][ni][1]);
      *(float2*)(C + (size_t)(row + 8) * N + col) = make_float2(acc[mi][ni][2], acc[mi][ni][3]);
    }
  }
}

__global__ __launch_bounds__(256, 2) void hgemm_qkv_kernel(
    const __nv_bfloat16* __restrict__ Hc,
    const __nv_bfloat16* __restrict__ Wqc, const __nv_bfloat16* __restrict__ Wkc,
    const __nv_bfloat16* __restrict__ Wvc,
    float* __restrict__ Qo, float* __restrict__ Ko, float* __restrict__ Vo) {
  extern __shared__ char sm[];
  const int z = blockIdx.z;
  const __nv_bfloat16* Bp;
  float* C;
  int N;
  if (z == 0)      { Bp = Wqc; C = Qo; N = QDIM; }
  else if (z == 1) { Bp = Wkc; C = Ko; N = KVDIM; }
  else             { Bp = Wvc; C = Vo; N = KVDIM; }
  const int n0 = blockIdx.x << 7;
  if (n0 >= N) return;
  const int m0 = blockIdx.y << 7;
  hgemm_core(Hc, Bp, C, N, KC3, m0, n0, sm);
}

__global__ __launch_bounds__(256, 2) void hgemm_o_kernel(
    const __nv_bfloat16* __restrict__ Ac, const __nv_bfloat16* __restrict__ Woc,
    float* __restrict__ out) {
  extern __shared__ char sm[];
  hgemm_core(Ac, Woc, out, HID, KC3, blockIdx.y << 7, blockIdx.x << 7, sm);
}

// ---------------- fp32 -> bf16 hi/lo concat split ----------------
__global__ void splitcat_kernel(const float* __restrict__ x, __nv_bfloat16* __restrict__ o,
                                int K, int isW, int total) {
  int i4 = (blockIdx.x * blockDim.x + threadIdx.x) << 2;
  if (i4 >= total) return;
  float4 v = *(const float4*)(x + i4);
  int row = i4 / K;
  int col = i4 - row * K;
  __nv_bfloat16 h[4], l[4];
  float vv[4] = {v.x, v.y, v.z, v.w};
#pragma unroll
  for (int j = 0; j < 4; j++) {
    h[j] = __float2bfloat16_rn(vv[j]);
    l[j] = __float2bfloat16_rn(vv[j] - __bfloat162float(h[j]));
  }
  size_t base = (size_t)row * (3 * K) + col;
  uint2 ph, pl;
  ph.x = (uint32_t)__bfloat16_as_ushort(h[0]) | ((uint32_t)__bfloat16_as_ushort(h[1]) << 16);
  ph.y = (uint32_t)__bfloat16_as_ushort(h[2]) | ((uint32_t)__bfloat16_as_ushort(h[3]) << 16);
  pl.x = (uint32_t)__bfloat16_as_ushort(l[0]) | ((uint32_t)__bfloat16_as_ushort(l[1]) << 16);
  pl.y = (uint32_t)__bfloat16_as_ushort(l[2]) | ((uint32_t)__bfloat16_as_ushort(l[3]) << 16);
  *(uint2*)(o + base) = ph;
  if (isW) {
    *(uint2*)(o + base + K)     = pl;
    *(uint2*)(o + base + 2 * K) = ph;
  } else {
    *(uint2*)(o + base + K)     = ph;
    *(uint2*)(o + base + 2 * K) = pl;
  }
}

// ---------------- RoPE + hi/lo split ----------------
__global__ void rope_split_kernel(const float* __restrict__ X, const float* __restrict__ cosb,
                                  const float* __restrict__ sinb,
                                  __nv_bfloat16* __restrict__ Xh, __nv_bfloat16* __restrict__ Xl,
                                  int width) {
  int idx = blockIdx.x * blockDim.x + threadIdx.x;
  int pairsPerRow = width >> 1;
  int total = S_LEN * pairsPerRow;
  if (idx >= total) return;
  int s = idx / pairsPerRow;
  int p = idx - s * pairsPerRow;
  int head = p >> 5;
  int d = p & 31;
  int c1 = head * HDIM + d;
  float c   = cosb[s * HDIM + d];
  float sn  = sinb[s * HDIM + d];
  float c2  = cosb[s * HDIM + d + 32];
  float sn2 = sinb[s * HDIM + d + 32];
  size_t base = (size_t)s * width;
  float x1 = X[base + c1];
  float x2 = X[base + c1 + 32];
  float y1 = x1 * c  - x2 * sn;
  float y2 = x2 * c2 + x1 * sn2;
  __nv_bfloat16 h1 = __float2bfloat16_rn(y1);
  __nv_bfloat16 h2 = __float2bfloat16_rn(y2);
  Xh[base + c1]      = h1;
  Xh[base + c1 + 32] = h2;
  Xl[base + c1]      = __float2bfloat16_rn(y1 - __bfloat162float(h1));
  Xl[base + c1 + 32] = __float2bfloat16_rn(y2 - __bfloat162float(h2));
}

// ---------------- V transpose + split: Vt[d][s] ----------------
__global__ void vsplit_t_kernel(const float* __restrict__ V,
                                __nv_bfloat16* __restrict__ Vth, __nv_bfloat16* __restrict__ Vtl) {
  __shared__ float tile[32][33];
  int c0 = blockIdx.x << 5;
  int s0 = blockIdx.y << 5;
  int tx = threadIdx.x, ty = threadIdx.y;
#pragma unroll
  for (int i = 0; i < 4; i++)
    tile[ty + i * 8][tx] = V[(size_t)(s0 + ty + i * 8) * KVDIM + c0 + tx];
  __syncthreads();
#pragma unroll
  for (int i = 0; i < 4; i++) {
    int r = ty + i * 8;
    float v = tile[tx][r];
    __nv_bfloat16 hv = __float2bfloat16_rn(v);
    Vth[(size_t)(c0 + r) * S_LEN + s0 + tx] = hv;
    Vtl[(size_t)(c0 + r) * S_LEN + s0 + tx] = __float2bfloat16_rn(v - __bfloat162float(hv));
  }
}

// ---------------- lambda ----------------
__global__ void lam_kernel(const float* __restrict__ lq1, const float* __restrict__ lk1,
                           const float* __restrict__ lq2, const float* __restrict__ lk2) {
  int d = threadIdx.x;
  float s1 = lq1[d] * lk1[d] + lq1[d + 32] * lk1[d + 32];
  float s2 = lq2[d] * lk2[d] + lq2[d + 32] * lk2[d + 32];
#pragma unroll
  for (int off = 16; off > 0; off >>= 1) {
    s1 += __shfl_xor_sync(0xffffffffu, s1, off);
    s2 += __shfl_xor_sync(0xffffffffu, s2, off);
  }
  if (d == 0) g_lam = expf(s1) - expf(s2) + LAMBDA_INIT;
}

// ---------------- HMMA flash attention (unchanged, correct) ----------------
#define ATT_QH   0
#define ATT_QL   18432
#define ATT_ST   36864
#define ATT_STGB 55296
#define ATT_SMEM (36864 + 2 * 55296)

__global__ __launch_bounds__(256, 1) void flash_attn_hmma(
    const __nv_bfloat16* __restrict__ Qh, const __nv_bfloat16* __restrict__ Ql,
    const __nv_bfloat16* __restrict__ Kh, const __nv_bfloat16* __restrict__ Kl,
    const __nv_bfloat16* __restrict__ Vth, const __nv_bfloat16* __restrict__ Vtl,
    float* __restrict__ O) {
  extern __shared__ char sm[];
  const uint32_t sb = smem_u32(sm);
  const int tid = threadIdx.x;
  const int w = tid >> 5, lane = tid & 31;
  const int h = blockIdx.y;
  const int qb = 15 - (int)blockIdx.x;
  const int q0 = qb << 7;
  const int kh = h >> 2;
  const int ii = h & 15;
  const int vh0 = ii >> 2, vh1 = 4 + (ii >> 2);
  const int nk = 2 * qb + 2;

  auto load_stage = [&](int k0, uint32_t stg) {
#pragma unroll
    for (int i = 0; i < 12; i++) {
      int id = tid + (i << 8);
      if (id < 1024) {
        int half = id >> 9;
        int t = id & 511;
        int row = t >> 3, ch = t & 7;
        const __nv_bfloat16* src = (half ? Kl : Kh) + (size_t)(k0 + row) * KVDIM + kh * HDIM + ch * 8;
        CP_ASYNC16(stg + half * 9216 + row * 144 + ch * 16, src);
      } else {
        int id2 = id - 1024;
        int half = id2 >> 10;
        int t = id2 & 1023;
        int row = t >> 3, ch = t & 7;
        int grow = (row < 64) ? (vh0 * HDIM + row) : (vh1 * HDIM + row - 64);
        const __nv_bfloat16* src = (half ? Vtl : Vth) + (size_t)grow * S_LEN + k0 + ch * 8;
        CP_ASYNC16(stg + 18432 + half * 18432 + row * 144 + ch * 16, src);
      }
    }
  };

  {
#pragma unroll
    for (int i = 0; i < 8; i++) {
      int id = tid + (i << 8);
      int half = id >> 10;
      int t = id & 1023;
      int row = t >> 3, ch = t & 7;
      const __nv_bfloat16* src = (half ? Ql : Qh) + (size_t)(q0 + row) * QDIM + h * HDIM + ch * 8;
      CP_ASYNC16(sb + half * 18432 + row * 144 + ch * 16, src);
    }
    load_stage(0, sb + ATT_ST);
    CP_COMMIT();
    CP_WAIT0();
  }
  __syncthreads();

  uint32_t qfh[4][4], qfl[4][4];
#pragma unroll
  for (int s = 0; s < 4; s++) {
    uint32_t a = sb + (uint32_t)(w * 16 + (lane & 15)) * 144 + ((lane >> 4) << 4) + s * 32;
    LDMATRIX_X4(qfh[s][0], qfh[s][1], qfh[s][2], qfh[s][3], a);
    LDMATRIX_X4(qfl[s][0], qfl[s][1], qfl[s][2], qfl[s][3], a + 18432);
  }

  float oacc[16][4];
#pragma unroll
  for (int n = 0; n < 16; n++)
#pragma unroll
    for (int c = 0; c < 4; c++) oacc[n][c] = 0.f;
  float m0r = -1e30f, m1r = -1e30f, l0r = 0.f, l1r = 0.f;
  const int rmin = q0 + w * 16;
  const int rmax = rmin + 15;
  const int r0g = rmin + (lane >> 2);
  const int r1g = r0g + 8;

  for (int kb = 0; kb < nk; kb++) {
    const int k0 = kb << 6;
    const uint32_t stg = sb + ATT_ST + (uint32_t)(kb & 1) * ATT_STGB;
    if (kb + 1 < nk) {
      load_stage((kb + 1) << 6, sb + ATT_ST + (uint32_t)((kb + 1) & 1) * ATT_STGB);
      CP_COMMIT();
    }

    if (k0 <= rmax) {
      float sacc[8][4];
#pragma unroll
      for (int j = 0; j < 8; j++)
#pragma unroll
        for (int c = 0; c < 4; c++) sacc[j][c] = 0.f;

#pragma unroll
      for (int j = 0; j < 8; j++) {
        uint32_t bh[2][4], bl[2][4];
#pragma unroll
        for (int s2 = 0; s2 < 2; s2++) {
          uint32_t a = stg + (uint32_t)(j * 8 + (lane & 7)) * 144 + s2 * 64 + ((lane >> 3) & 3) * 16;
          LDMATRIX_X4(bh[s2][0], bh[s2][1], bh[s2][2], bh[s2][3], a);
          LDMATRIX_X4(bl[s2][0], bl[s2][1], bl[s2][2], bl[s2][3], a + 9216);
        }
#pragma unroll
        for (int s = 0; s < 4; s++) {
          uint32_t b0h = bh[s >> 1][(s & 1) * 2], b1h = bh[s >> 1][(s & 1) * 2 + 1];
          uint32_t b0l = bl[s >> 1][(s & 1) * 2], b1l = bl[s >> 1][(s & 1) * 2 + 1];
          MMA16816(sacc[j][0], sacc[j][1], sacc[j][2], sacc[j][3],
                   qfh[s][0], qfh[s][1], qfh[s][2], qfh[s][3], b0h, b1h);
          MMA16816(sacc[j][0], sacc[j][1], sacc[j][2], sacc[j][3],
                   qfh[s][0], qfh[s][1], qfh[s][2], qfh[s][3], b0l, b1l);
          MMA16816(sacc[j][0], sacc[j][1], sacc[j][2], sacc[j][3],
                   qfl[s][0], qfl[s][1], qfl[s][2], qfl[s][3], b0h, b1h);
        }
      }

      const bool needmask = (k0 + 63) > rmin;
#pragma unroll
      for (int j = 0; j < 8; j++) {
        int cb = k0 + j * 8 + ((lane & 3) << 1);
        sacc[j][0] *= 0.125f; sacc[j][1] *= 0.125f;
        sacc[j][2] *= 0.125f; sacc[j][3] *= 0.125f;
        if (needmask) {
          if (cb     > r0g) sacc[j][0] = -1e30f;
          if (cb + 1 > r0g) sacc[j][1] = -1e30f;
          if (cb     > r1g) sacc[j][2] = -1e30f;
          if (cb + 1 > r1g) sacc[j][3] = -1e30f;
        }
      }

      float mx0 = -1e30f, mx1 = -1e30f;
#pragma unroll
      for (int j = 0; j < 8; j++) {
        mx0 = fmaxf(mx0, fmaxf(sacc[j][0], sacc[j][1]));
        mx1 = fmaxf(mx1, fmaxf(sacc[j][2], sacc[j][3]));
      }
      mx0 = fmaxf(mx0, __shfl_xor_sync(0xffffffffu, mx0, 1));
      mx0 = fmaxf(mx0, __shfl_xor_sync(0xffffffffu, mx0, 2));
      mx1 = fmaxf(mx1, __shfl_xor_sync(0xffffffffu, mx1, 1));
      mx1 = fmaxf(mx1, __shfl_xor_sync(0xffffffffu, mx1, 2));
      float mn0 = fmaxf(m0r, mx0), mn1 = fmaxf(m1r, mx1);
      float al0 = __expf(m0r - mn0), al1 = __expf(m1r - mn1);
      m0r = mn0; m1r = mn1;

      float sum0 = 0.f, sum1 = 0.f;
      uint32_t ph[8][2], pl[8][2];
#pragma unroll
      for (int j = 0; j < 8; j++) {
        float p0 = __expf(sacc[j][0] - mn0);
        float p1 = __expf(sacc[j][1] - mn0);
        float p2 = __expf(sacc[j][2] - mn1);
        float p3 = __expf(sacc[j][3] - mn1);
        sum0 += p0 + p1; sum1 += p2 + p3;
        float ra, rb;
        ph[j][0] = pack2bf_res(p0, p1, ra, rb);
        pl[j][0] = pack2bf(ra, rb);
        ph[j][1] = pack2bf_res(p2, p3, ra, rb);
        pl[j][1] = pack2bf(ra, rb);
      }
      sum0 += __shfl_xor_sync(0xffffffffu, sum0, 1);
      sum0 += __shfl_xor_sync(0xffffffffu, sum0, 2);
      sum1 += __shfl_xor_sync(0xffffffffu, sum1, 1);
      sum1 += __shfl_xor_sync(0xffffffffu, sum1, 2);
      l0r = l0r * al0 + sum0;
      l1r = l1r * al1 + sum1;
#pragma unroll
      for (int n = 0; n < 16; n++) {
        oacc[n][0] *= al0; oacc[n][1] *= al0;
        oacc[n][2] *= al1; oacc[n][3] *= al1;
      }

#pragma unroll
      for (int n = 0; n < 16; n++) {
        uint32_t vh[2][4], vl[2][4];
#pragma unroll
        for (int s2 = 0; s2 < 2; s2++) {
          uint32_t a = stg + 18432 + (uint32_t)(n * 8 + (lane & 7)) * 144 + s2 * 64 + ((lane >> 3) & 3) * 16;
          LDMATRIX_X4(vh[s2][0], vh[s2][1], vh[s2][2], vh[s2][3], a);
          LDMATRIX_X4(vl[s2][0], vl[s2][1], vl[s2][2], vl[s2][3], a + 18432);
        }
#pragma unroll
        for (int t = 0; t < 4; t++) {
          uint32_t a0 = ph[2 * t][0], a1 = ph[2 * t][1], a2 = ph[2 * t + 1][0], a3 = ph[2 * t + 1][1];
          uint32_t c0 = pl[2 * t][0], c1 = pl[2 * t][1], c2 = pl[2 * t + 1][0], c3 = pl[2 * t + 1][1];
          uint32_t b0h = vh[t >> 1][(t & 1) * 2], b1h = vh[t >> 1][(t & 1) * 2 + 1];
          uint32_t b0l = vl[t >> 1][(t & 1) * 2], b1l = vl[t >> 1][(t & 1) * 2 + 1];
          MMA16816(oacc[n][0], oacc[n][1], oacc[n][2], oacc[n][3], a0, a1, a2, a3, b0h, b1h);
          MMA16816(oacc[n][0], oacc[n][1], oacc[n][2], oacc[n][3], a0, a1, a2, a3, b0l, b1l);
          MMA16816(oacc[n][0], oacc[n][1], oacc[n][2], oacc[n][3], c0, c1, c2, c3, b0h, b1h);
        }
      }
    }

    CP_WAIT0();
    __syncthreads();
  }

  float i0 = 1.f / l0r, i1 = 1.f / l1r;
#pragma unroll
  for (int n = 0; n < 16; n++) {
    int col = n * 8 + ((lane & 3) << 1);
    *(float2*)(O + ((size_t)h * S_LEN + r0g) * VD + col) = make_float2(oacc[n][0] * i0, oacc[n][1] * i0);
    *(float2*)(O + ((size_t)h * S_LEN + r1g) * VD + col) = make_float2(oacc[n][2] * i1, oacc[n][3] * i1);
  }
}

// ---------------- differential combine + RMS norm -> bf16 concat ----------------
__global__ void combine_kernel(const float* __restrict__ O, __nv_bfloat16* __restrict__ Ac) {
  const int s = blockIdx.x;
  const int i = blockIdx.y;
  const int d = threadIdx.x;
  const float lam = g_lam;
  float o1 = O[((size_t)i * S_LEN + s) * VD + d];
  float o2 = O[((size_t)(i + 16) * S_LEN + s) * VD + d];
  float a = o1 - lam * o2;
  float ss = a * a;
#pragma unroll
  for (int off = 16; off > 0; off >>= 1)
    ss += __shfl_xor_sync(0xffffffffu, ss, off);
  __shared__ float ws[4];
  int warp = d >> 5, lane = d & 31;
  if (lane == 0) ws[warp] = ss;
  __syncthreads();
  float tot = ws[0] + ws[1] + ws[2] + ws[3];
  float r = rsqrtf(tot * (1.0f / 128.0f) + 1e-6f);
  float aval = (1.0f - LAMBDA_INIT) * a * r;
  __nv_bfloat16 h = __float2bfloat16_rn(aval);
  __nv_bfloat16 l = __float2bfloat16_rn(aval - __bfloat162float(h));
  size_t base = (size_t)s * KC3 + i * VD + d;
  Ac[base]            = h;
  Ac[base + QDIM]     = h;
  Ac[base + 2 * QDIM] = l;
}

// ---------------- launch ----------------
extern "C" void kernel_launch(void* const* d_in, const int* in_sizes, int n_in,
                              void* d_out, int out_size) {
  const float* hidden = (const float*)d_in[0];
  const float* cosb   = (const float*)d_in[1];
  const float* sinb   = (const float*)d_in[2];
  const float* Wq     = (const float*)d_in[3];
  const float* Wk     = (const float*)d_in[4];
  const float* Wv     = (const float*)d_in[5];
  const float* Wo     = (const float*)d_in[6];
  const float* lq1    = (const float*)d_in[7];
  const float* lk1    = (const float*)d_in[8];
  const float* lq2    = (const float*)d_in[9];
  const float* lk2    = (const float*)d_in[10];
  float* out = (float*)d_out;

  float *Qp, *Kp, *Vp, *Op;
  cudaGetSymbolAddress((void**)&Qp, g_Q);
  cudaGetSymbolAddress((void**)&Kp, g_K);
  cudaGetSymbolAddress((void**)&Vp, g_V);
  cudaGetSymbolAddress((void**)&Op, g_O);
  __nv_bfloat16 *Hc, *Wqc, *Wkc, *Wvc, *Woc, *Ac;
  cudaGetSymbolAddress((void**)&Hc, g_Hc);
  cudaGetSymbolAddress((void**)&Wqc, g_Wqc);
  cudaGetSymbolAddress((void**)&Wkc, g_Wkc);
  cudaGetSymbolAddress((void**)&Wvc, g_Wvc);
  cudaGetSymbolAddress((void**)&Woc, g_Woc);
  cudaGetSymbolAddress((void**)&Ac, g_Ac);
  __nv_bfloat16 *Qhp, *Qlp, *Khp, *Klp, *Vthp, *Vtlp;
  cudaGetSymbolAddress((void**)&Qhp, g_Qh);   cudaGetSymbolAddress((void**)&Qlp, g_Ql);
  cudaGetSymbolAddress((void**)&Khp, g_Kh);   cudaGetSymbolAddress((void**)&Klp, g_Kl);
  cudaGetSymbolAddress((void**)&Vthp, g_Vth); cudaGetSymbolAddress((void**)&Vtlp, g_Vtl);

  cudaFuncSetAttribute(hgemm_qkv_kernel, cudaFuncAttributeMaxDynamicSharedMemorySize, GSMEM);
  cudaFuncSetAttribute(hgemm_o_kernel,   cudaFuncAttributeMaxDynamicSharedMemorySize, GSMEM);
  cudaFuncSetAttribute(flash_attn_hmma,  cudaFuncAttributeMaxDynamicSharedMemorySize, ATT_SMEM);

  // splits (fp32 -> bf16 concat)
  {
    int n = S_LEN * HID;
    splitcat_kernel<<<n / 4 / 256, 256>>>(hidden, Hc, HID, 0, n);
    n = QDIM * HID;
    splitcat_kernel<<<n / 4 / 256, 256>>>(Wq, Wqc, HID, 1, n);
    n = KVDIM * HID;
    splitcat_kernel<<<n / 4 / 256, 256>>>(Wk, Wkc, HID, 1, n);
    splitcat_kernel<<<n / 4 / 256, 256>>>(Wv, Wvc, HID, 1, n);
    n = HID * QDIM;
    splitcat_kernel<<<n / 4 / 256, 256>>>(Wo, Woc, QDIM, 1, n);
  }

  // QKV projections (HMMA bf16x3 via concat-K, BK=64 pipeline)
  hgemm_qkv_kernel<<<dim3(QDIM / 128, S_LEN / 128, 3), 256, GSMEM>>>(Hc, Wqc, Wkc, Wvc, Qp, Kp, Vp);

  // RoPE + split; V transpose+split
  rope_split_kernel<<<(S_LEN * (QDIM / 2)) / 256, 256>>>(Qp, cosb, sinb, Qhp, Qlp, QDIM);
  rope_split_kernel<<<(S_LEN * (KVDIM / 2)) / 256, 256>>>(Kp, cosb, sinb, Khp, Klp, KVDIM);
  vsplit_t_kernel<<<dim3(KVDIM / 32, S_LEN / 32), dim3(32, 8)>>>(Vp, Vthp, Vtlp);

  // lambda
  lam_kernel<<<1, 32>>>(lq1, lk1, lq2, lk2);

  // attention (HMMA)
  flash_attn_hmma<<<dim3(16, NHEADS), 256, ATT_SMEM>>>(Qhp, Qlp, Khp, Klp, Vthp, Vtlp, Op);

  // combine + RMS norm -> bf16 concat activations
  combine_kernel<<<dim3(S_LEN, 16), 128>>>(Op, Ac);

  // output projection
  hgemm_o_kernel<<<dim3(QDIM / 128, S_LEN / 128), 256, GSMEM>>>(Ac, Woc, out);
}

// round 8
// speedup vs baseline: 2.6548x; 1.1349x over previous
#include <cuda_runtime.h>
#include <cuda_bf16.h>
#include <cuda_fp16.h>
#include <math.h>
#include <stdint.h>

#define S_LEN 2048
#define HID   2048
#define NHEADS 32
#define HDIM   64
#define QDIM  2048
#define KVDIM  512
#define VD     128
#define KC3   (3 * HID)     // 6144, concat-K for bf16x3
#define KC2   (2 * QDIM)    // 4096, concat-K for fp16x2 O-proj
#define LAMBDA_INIT 0.7455692280263552f

// ---------------- scratch ----------------
__device__ float g_Q[(size_t)S_LEN * QDIM];
__device__ float g_K[(size_t)S_LEN * KVDIM];
__device__ float g_V[(size_t)S_LEN * KVDIM];
__device__ float g_O[(size_t)NHEADS * S_LEN * VD];
__device__ float g_lam;
__device__ __align__(256) __nv_bfloat16 g_Hc[(size_t)S_LEN * KC3];
__device__ __align__(256) __nv_bfloat16 g_Wqc[(size_t)QDIM * KC3];
__device__ __align__(256) __nv_bfloat16 g_Wkc[(size_t)KVDIM * KC3];
__device__ __align__(256) __nv_bfloat16 g_Wvc[(size_t)KVDIM * KC3];
__device__ __align__(256) __half       g_Wo2[(size_t)HID * KC2];    // [h | l] fp16
__device__ __align__(256) __half       g_Ac2[(size_t)S_LEN * KC2];  // [a | a] fp16
// attention operands
__device__ __align__(256) __nv_bfloat16 g_Qh[(size_t)S_LEN * QDIM],  g_Ql[(size_t)S_LEN * QDIM];
__device__ __align__(256) __nv_bfloat16 g_Kh[(size_t)S_LEN * KVDIM], g_Kl[(size_t)S_LEN * KVDIM];
__device__ __align__(256) __half g_Vth[(size_t)KVDIM * S_LEN], g_Vtl[(size_t)KVDIM * S_LEN];  // fp16, transposed [d][s]

// ---------------- helpers ----------------
__device__ __forceinline__ uint32_t smem_u32(const void* p) {
  uint32_t r;
  asm("{ .reg .u64 t; cvta.to.shared.u64 t, %1; cvt.u32.u64 %0, t; }" : "=r"(r) : "l"(p));
  return r;
}
#define CP_ASYNC16(sa, ga) \
  asm volatile("cp.async.cg.shared.global [%0], [%1], 16;" :: "r"(sa), "l"(ga) : "memory")
#define CP_COMMIT() asm volatile("cp.async.commit_group;" ::: "memory")
#define CP_WAIT0()  asm volatile("cp.async.wait_group 0;" ::: "memory")

#define LDMATRIX_X4(r0, r1, r2, r3, addr) \
  asm volatile("ldmatrix.sync.aligned.m8n8.x4.shared.b16 {%0,%1,%2,%3}, [%4];" \
               : "=r"(r0), "=r"(r1), "=r"(r2), "=r"(r3) : "r"(addr))

#define MMA16816(c0, c1, c2, c3, a0, a1, a2, a3, b0, b1) \
  asm volatile("mma.sync.aligned.m16n8k16.row.col.f32.bf16.bf16.f32 " \
               "{%0,%1,%2,%3}, {%4,%5,%6,%7}, {%8,%9}, {%0,%1,%2,%3};" \
               : "+f"(c0), "+f"(c1), "+f"(c2), "+f"(c3) \
               : "r"(a0), "r"(a1), "r"(a2), "r"(a3), "r"(b0), "r"(b1))

#define MMA16816H(c0, c1, c2, c3, a0, a1, a2, a3, b0, b1) \
  asm volatile("mma.sync.aligned.m16n8k16.row.col.f32.f16.f16.f32 " \
               "{%0,%1,%2,%3}, {%4,%5,%6,%7}, {%8,%9}, {%0,%1,%2,%3};" \
               : "+f"(c0), "+f"(c1), "+f"(c2), "+f"(c3) \
               : "r"(a0), "r"(a1), "r"(a2), "r"(a3), "r"(b0), "r"(b1))

__device__ __forceinline__ uint32_t pack2h(float a, float b) {
  __half2 h = __floats2half2_rn(a, b);
  return *(uint32_t*)&h;
}

// ---------------- HMMA GEMM: C[M,N] = A[M,Kc] @ B[N,Kc]^T ----------------
// CTA 128x128, BK=64, 256 threads (8 warps 2m x 4n), 2-stage cp.async pipeline,
// one __syncthreads per k-iter, 144B-padded rows, dynamic smem, 2 CTAs/SM.
#define GROWB 144
#define GTILE (128 * GROWB)
#define GSTAGE (2 * GTILE)
#define GSMEM (2 * GSTAGE)

template <typename ET, bool F16>
__device__ __forceinline__ void hgemm_core(
    const ET* __restrict__ A, const ET* __restrict__ B,
    float* __restrict__ C, int N, int Kc, int m0, int n0, char* sm) {
  const int tid = threadIdx.x;
  const int warp = tid >> 5;
  const int lane = tid & 31;
  const int wm = warp & 1;
  const int wn = warp >> 1;
  const uint32_t sb = smem_u32(sm);

  const int lrow = tid >> 1;
  const int lch0 = (tid & 1) << 2;

  float acc[4][4][4];
#pragma unroll
  for (int i = 0; i < 4; i++)
#pragma unroll
    for (int j = 0; j < 4; j++)
#pragma unroll
      for (int c = 0; c < 4; c++) acc[i][j][c] = 0.f;

  const int nT = Kc >> 6;

  auto load_stage = [&](int k0, uint32_t st) {
    const ET* ag = A + (size_t)(m0 + lrow) * Kc + k0 + lch0 * 8;
    const ET* bg = B + (size_t)(n0 + lrow) * Kc + k0 + lch0 * 8;
    uint32_t so = st + lrow * GROWB + lch0 * 16;
#pragma unroll
    for (int c = 0; c < 4; c++) {
      CP_ASYNC16(so + c * 16, ag + c * 8);
      CP_ASYNC16(so + GTILE + c * 16, bg + c * 8);
    }
  };

  load_stage(0, sb);
  CP_COMMIT();

  for (int t = 0; t < nT; ++t) {
    CP_WAIT0();
    __syncthreads();
    const uint32_t cur = sb + (uint32_t)(t & 1) * GSTAGE;
    if (t + 1 < nT) {
      load_stage((t + 1) << 6, sb + (uint32_t)((t + 1) & 1) * GSTAGE);
      CP_COMMIT();
    }

#pragma unroll
    for (int ks = 0; ks < 4; ++ks) {
      uint32_t a[4][4];
#pragma unroll
      for (int mi = 0; mi < 4; ++mi) {
        uint32_t addr = cur + (uint32_t)((wm << 6) + (mi << 4) + (lane & 15)) * GROWB
                        + ((lane >> 4) << 4) + (ks << 5);
        LDMATRIX_X4(a[mi][0], a[mi][1], a[mi][2], a[mi][3], addr);
      }
      uint32_t b[4][2];
#pragma unroll
      for (int pr = 0; pr < 2; ++pr) {
        int r = (lane & 7) + (((lane >> 4) & 1) << 3);
        int hk = (lane >> 3) & 1;
        uint32_t addr = cur + GTILE + (uint32_t)((wn << 5) + (pr << 4) + r) * GROWB
                        + (hk << 4) + (ks << 5);
        uint32_t r0, r1, r2, r3;
        LDMATRIX_X4(r0, r1, r2, r3, addr);
        b[pr * 2 + 0][0] = r0; b[pr * 2 + 0][1] = r1;
        b[pr * 2 + 1][0] = r2; b[pr * 2 + 1][1] = r3;
      }
#pragma unroll
      for (int mi = 0; mi < 4; ++mi)
#pragma unroll
        for (int ni = 0; ni < 4; ++ni) {
          if constexpr (F16) {
            MMA16816H(acc[mi][ni][0], acc[mi][ni][1], acc[mi][ni][2], acc[mi][ni][3],
                      a[mi][0], a[mi][1], a[mi][2], a[mi][3], b[ni][0], b[ni][1]);
          } else {
            MMA16816(acc[mi][ni][0], acc[mi][ni][1], acc[mi][ni][2], acc[mi][ni][3],
                     a[mi][0], a[mi][1], a[mi][2], a[mi][3], b[ni][0], b[ni][1]);
          }
        }
    }
  }

#pragma unroll
  for (int mi = 0; mi < 4; ++mi) {
    int row = m0 + (wm << 6) + (mi << 4) + (lane >> 2);
#pragma unroll
    for (int ni = 0; ni < 4; ++ni) {
      int col = n0 + (wn << 5) + (ni << 3) + ((lane & 3) << 1);
      *(float2*)(C + (size_t)row * N + col)       = make_float2(acc[mi][ni][0], acc[mi][ni][1]);
      *(float2*)(C + (size_t)(row + 8) * N + col) = make_float2(acc[mi][ni][2], acc[mi][ni][3]);
    }
  }
}

__global__ __launch_bounds__(256, 2) void hgemm_qkv_kernel(
    const __nv_bfloat16* __restrict__ Hc,
    const __nv_bfloat16* __restrict__ Wqc, const __nv_bfloat16* __restrict__ Wkc,
    const __nv_bfloat16* __restrict__ Wvc,
    float* __restrict__ Qo, float* __restrict__ Ko, float* __restrict__ Vo) {
  extern __shared__ char sm[];
  const int z = blockIdx.z;
  const __nv_bfloat16* Bp;
  float* C;
  int N;
  if (z == 0)      { Bp = Wqc; C = Qo; N = QDIM; }
  else if (z == 1) { Bp = Wkc; C = Ko; N = KVDIM; }
  else             { Bp = Wvc; C = Vo; N = KVDIM; }
  const int n0 = blockIdx.x << 7;
  if (n0 >= N) return;
  const int m0 = blockIdx.y << 7;
  hgemm_core<__nv_bfloat16, false>(Hc, Bp, C, N, KC3, m0, n0, sm);
}

__global__ __launch_bounds__(256, 2) void hgemm_o_kernel(
    const __half* __restrict__ Ac2, const __half* __restrict__ Wo2,
    float* __restrict__ out) {
  extern __shared__ char sm[];
  hgemm_core<__half, true>(Ac2, Wo2, out, HID, KC2, blockIdx.y << 7, blockIdx.x << 7, sm);
}

// ---------------- fp32 -> bf16 hi/lo concat3 split ----------------
__global__ void splitcat_kernel(const float* __restrict__ x, __nv_bfloat16* __restrict__ o,
                                int K, int isW, int total) {
  int i4 = (blockIdx.x * blockDim.x + threadIdx.x) << 2;
  if (i4 >= total) return;
  float4 v = *(const float4*)(x + i4);
  int row = i4 / K;
  int col = i4 - row * K;
  __nv_bfloat16 h[4], l[4];
  float vv[4] = {v.x, v.y, v.z, v.w};
#pragma unroll
  for (int j = 0; j < 4; j++) {
    h[j] = __float2bfloat16_rn(vv[j]);
    l[j] = __float2bfloat16_rn(vv[j] - __bfloat162float(h[j]));
  }
  size_t base = (size_t)row * (3 * K) + col;
  uint2 ph, pl;
  ph.x = (uint32_t)__bfloat16_as_ushort(h[0]) | ((uint32_t)__bfloat16_as_ushort(h[1]) << 16);
  ph.y = (uint32_t)__bfloat16_as_ushort(h[2]) | ((uint32_t)__bfloat16_as_ushort(h[3]) << 16);
  pl.x = (uint32_t)__bfloat16_as_ushort(l[0]) | ((uint32_t)__bfloat16_as_ushort(l[1]) << 16);
  pl.y = (uint32_t)__bfloat16_as_ushort(l[2]) | ((uint32_t)__bfloat16_as_ushort(l[3]) << 16);
  *(uint2*)(o + base) = ph;
  if (isW) {
    *(uint2*)(o + base + K)     = pl;
    *(uint2*)(o + base + 2 * K) = ph;
  } else {
    *(uint2*)(o + base + K)     = ph;
    *(uint2*)(o + base + 2 * K) = pl;
  }
}

// ---------------- fp32 -> fp16 hi/lo concat2 split (for Wo) ----------------
__global__ void splitcat2h_kernel(const float* __restrict__ x, __half* __restrict__ o,
                                  int K, int total) {
  int i4 = (blockIdx.x * blockDim.x + threadIdx.x) << 2;
  if (i4 >= total) return;
  float4 v = *(const float4*)(x + i4);
  int row = i4 / K;
  int col = i4 - row * K;
  __half h[4], l[4];
  float vv[4] = {v.x, v.y, v.z, v.w};
#pragma unroll
  for (int j = 0; j < 4; j++) {
    h[j] = __float2half_rn(vv[j]);
    l[j] = __float2half_rn(vv[j] - __half2float(h[j]));
  }
  size_t base = (size_t)row * (2 * K) + col;
  uint2 ph, pl;
  ph.x = (uint32_t)__half_as_ushort(h[0]) | ((uint32_t)__half_as_ushort(h[1]) << 16);
  ph.y = (uint32_t)__half_as_ushort(h[2]) | ((uint32_t)__half_as_ushort(h[3]) << 16);
  pl.x = (uint32_t)__half_as_ushort(l[0]) | ((uint32_t)__half_as_ushort(l[1]) << 16);
  pl.y = (uint32_t)__half_as_ushort(l[2]) | ((uint32_t)__half_as_ushort(l[3]) << 16);
  *(uint2*)(o + base)     = ph;
  *(uint2*)(o + base + K) = pl;
}

// ---------------- RoPE + bf16 hi/lo split ----------------
__global__ void rope_split_kernel(const float* __restrict__ X, const float* __restrict__ cosb,
                                  const float* __restrict__ sinb,
                                  __nv_bfloat16* __restrict__ Xh, __nv_bfloat16* __restrict__ Xl,
                                  int width) {
  int idx = blockIdx.x * blockDim.x + threadIdx.x;
  int pairsPerRow = width >> 1;
  int total = S_LEN * pairsPerRow;
  if (idx >= total) return;
  int s = idx / pairsPerRow;
  int p = idx - s * pairsPerRow;
  int head = p >> 5;
  int d = p & 31;
  int c1 = head * HDIM + d;
  float c   = cosb[s * HDIM + d];
  float sn  = sinb[s * HDIM + d];
  float c2  = cosb[s * HDIM + d + 32];
  float sn2 = sinb[s * HDIM + d + 32];
  size_t base = (size_t)s * width;
  float x1 = X[base + c1];
  float x2 = X[base + c1 + 32];
  float y1 = x1 * c  - x2 * sn;
  float y2 = x2 * c2 + x1 * sn2;
  __nv_bfloat16 h1 = __float2bfloat16_rn(y1);
  __nv_bfloat16 h2 = __float2bfloat16_rn(y2);
  Xh[base + c1]      = h1;
  Xh[base + c1 + 32] = h2;
  Xl[base + c1]      = __float2bfloat16_rn(y1 - __bfloat162float(h1));
  Xl[base + c1 + 32] = __float2bfloat16_rn(y2 - __bfloat162float(h2));
}

// ---------------- V transpose + fp16 split: Vt[d][s] ----------------
__global__ void vsplit_t_kernel(const float* __restrict__ V,
                                __half* __restrict__ Vth, __half* __restrict__ Vtl) {
  __shared__ float tile[32][33];
  int c0 = blockIdx.x << 5;
  int s0 = blockIdx.y << 5;
  int tx = threadIdx.x, ty = threadIdx.y;
#pragma unroll
  for (int i = 0; i < 4; i++)
    tile[ty + i * 8][tx] = V[(size_t)(s0 + ty + i * 8) * KVDIM + c0 + tx];
  __syncthreads();
#pragma unroll
  for (int i = 0; i < 4; i++) {
    int r = ty + i * 8;
    float v = tile[tx][r];
    __half hv = __float2half_rn(v);
    Vth[(size_t)(c0 + r) * S_LEN + s0 + tx] = hv;
    Vtl[(size_t)(c0 + r) * S_LEN + s0 + tx] = __float2half_rn(v - __half2float(hv));
  }
}

// ---------------- lambda ----------------
__global__ void lam_kernel(const float* __restrict__ lq1, const float* __restrict__ lk1,
                           const float* __restrict__ lq2, const float* __restrict__ lk2) {
  int d = threadIdx.x;
  float s1 = lq1[d] * lk1[d] + lq1[d + 32] * lk1[d + 32];
  float s2 = lq2[d] * lk2[d] + lq2[d + 32] * lk2[d + 32];
#pragma unroll
  for (int off = 16; off > 0; off >>= 1) {
    s1 += __shfl_xor_sync(0xffffffffu, s1, off);
    s2 += __shfl_xor_sync(0xffffffffu, s2, off);
  }
  if (d == 0) g_lam = expf(s1) - expf(s2) + LAMBDA_INIT;
}

// ---------------- HMMA flash attention: QK bf16x3, PV fp16x2 ----------------
#define ATT_QH   0
#define ATT_QL   18432
#define ATT_ST   36864
#define ATT_STGB 55296
#define ATT_SMEM (36864 + 2 * 55296)

__global__ __launch_bounds__(256, 1) void flash_attn_hmma(
    const __nv_bfloat16* __restrict__ Qh, const __nv_bfloat16* __restrict__ Ql,
    const __nv_bfloat16* __restrict__ Kh, const __nv_bfloat16* __restrict__ Kl,
    const __half* __restrict__ Vth, const __half* __restrict__ Vtl,
    float* __restrict__ O) {
  extern __shared__ char sm[];
  const uint32_t sb = smem_u32(sm);
  const int tid = threadIdx.x;
  const int w = tid >> 5, lane = tid & 31;
  const int h = blockIdx.y;
  const int qb = 15 - (int)blockIdx.x;
  const int q0 = qb << 7;
  const int kh = h >> 2;
  const int ii = h & 15;
  const int vh0 = ii >> 2, vh1 = 4 + (ii >> 2);
  const int nk = 2 * qb + 2;

  auto load_stage = [&](int k0, uint32_t stg) {
#pragma unroll
    for (int i = 0; i < 12; i++) {
      int id = tid + (i << 8);
      if (id < 1024) {
        int half_ = id >> 9;
        int t = id & 511;
        int row = t >> 3, ch = t & 7;
        const __nv_bfloat16* src = (half_ ? Kl : Kh) + (size_t)(k0 + row) * KVDIM + kh * HDIM + ch * 8;
        CP_ASYNC16(stg + half_ * 9216 + row * 144 + ch * 16, src);
      } else {
        int id2 = id - 1024;
        int half_ = id2 >> 10;
        int t = id2 & 1023;
        int row = t >> 3, ch = t & 7;
        int grow = (row < 64) ? (vh0 * HDIM + row) : (vh1 * HDIM + row - 64);
        const __half* src = (half_ ? Vtl : Vth) + (size_t)grow * S_LEN + k0 + ch * 8;
        CP_ASYNC16(stg + 18432 + half_ * 18432 + row * 144 + ch * 16, src);
      }
    }
  };

  {
#pragma unroll
    for (int i = 0; i < 8; i++) {
      int id = tid + (i << 8);
      int half_ = id >> 10;
      int t = id & 1023;
      int row = t >> 3, ch = t & 7;
      const __nv_bfloat16* src = (half_ ? Ql : Qh) + (size_t)(q0 + row) * QDIM + h * HDIM + ch * 8;
      CP_ASYNC16(sb + half_ * 18432 + row * 144 + ch * 16, src);
    }
    load_stage(0, sb + ATT_ST);
    CP_COMMIT();
    CP_WAIT0();
  }
  __syncthreads();

  uint32_t qfh[4][4], qfl[4][4];
#pragma unroll
  for (int s = 0; s < 4; s++) {
    uint32_t a = sb + (uint32_t)(w * 16 + (lane & 15)) * 144 + ((lane >> 4) << 4) + s * 32;
    LDMATRIX_X4(qfh[s][0], qfh[s][1], qfh[s][2], qfh[s][3], a);
    LDMATRIX_X4(qfl[s][0], qfl[s][1], qfl[s][2], qfl[s][3], a + 18432);
  }

  float oacc[16][4];
#pragma unroll
  for (int n = 0; n < 16; n++)
#pragma unroll
    for (int c = 0; c < 4; c++) oacc[n][c] = 0.f;
  float m0r = -1e30f, m1r = -1e30f, l0r = 0.f, l1r = 0.f;
  const int rmin = q0 + w * 16;
  const int rmax = rmin + 15;
  const int r0g = rmin + (lane >> 2);
  const int r1g = r0g + 8;

  for (int kb = 0; kb < nk; kb++) {
    const int k0 = kb << 6;
    const uint32_t stg = sb + ATT_ST + (uint32_t)(kb & 1) * ATT_STGB;
    if (kb + 1 < nk) {
      load_stage((kb + 1) << 6, sb + ATT_ST + (uint32_t)((kb + 1) & 1) * ATT_STGB);
      CP_COMMIT();
    }

    if (k0 <= rmax) {
      // ---- S = Q K^T (bf16x3) ----
      float sacc[8][4];
#pragma unroll
      for (int j = 0; j < 8; j++)
#pragma unroll
        for (int c = 0; c < 4; c++) sacc[j][c] = 0.f;

#pragma unroll
      for (int j = 0; j < 8; j++) {
        uint32_t bh[2][4], bl[2][4];
#pragma unroll
        for (int s2 = 0; s2 < 2; s2++) {
          uint32_t a = stg + (uint32_t)(j * 8 + (lane & 7)) * 144 + s2 * 64 + ((lane >> 3) & 3) * 16;
          LDMATRIX_X4(bh[s2][0], bh[s2][1], bh[s2][2], bh[s2][3], a);
          LDMATRIX_X4(bl[s2][0], bl[s2][1], bl[s2][2], bl[s2][3], a + 9216);
        }
#pragma unroll
        for (int s = 0; s < 4; s++) {
          uint32_t b0h = bh[s >> 1][(s & 1) * 2], b1h = bh[s >> 1][(s & 1) * 2 + 1];
          uint32_t b0l = bl[s >> 1][(s & 1) * 2], b1l = bl[s >> 1][(s & 1) * 2 + 1];
          MMA16816(sacc[j][0], sacc[j][1], sacc[j][2], sacc[j][3],
                   qfh[s][0], qfh[s][1], qfh[s][2], qfh[s][3], b0h, b1h);
          MMA16816(sacc[j][0], sacc[j][1], sacc[j][2], sacc[j][3],
                   qfh[s][0], qfh[s][1], qfh[s][2], qfh[s][3], b0l, b1l);
          MMA16816(sacc[j][0], sacc[j][1], sacc[j][2], sacc[j][3],
                   qfl[s][0], qfl[s][1], qfl[s][2], qfl[s][3], b0h, b1h);
        }
      }

      const bool needmask = (k0 + 63) > rmin;
#pragma unroll
      for (int j = 0; j < 8; j++) {
        int cb = k0 + j * 8 + ((lane & 3) << 1);
        sacc[j][0] *= 0.125f; sacc[j][1] *= 0.125f;
        sacc[j][2] *= 0.125f; sacc[j][3] *= 0.125f;
        if (needmask) {
          if (cb     > r0g) sacc[j][0] = -1e30f;
          if (cb + 1 > r0g) sacc[j][1] = -1e30f;
          if (cb     > r1g) sacc[j][2] = -1e30f;
          if (cb + 1 > r1g) sacc[j][3] = -1e30f;
        }
      }

      float mx0 = -1e30f, mx1 = -1e30f;
#pragma unroll
      for (int j = 0; j < 8; j++) {
        mx0 = fmaxf(mx0, fmaxf(sacc[j][0], sacc[j][1]));
        mx1 = fmaxf(mx1, fmaxf(sacc[j][2], sacc[j][3]));
      }
      mx0 = fmaxf(mx0, __shfl_xor_sync(0xffffffffu, mx0, 1));
      mx0 = fmaxf(mx0, __shfl_xor_sync(0xffffffffu, mx0, 2));
      mx1 = fmaxf(mx1, __shfl_xor_sync(0xffffffffu, mx1, 1));
      mx1 = fmaxf(mx1, __shfl_xor_sync(0xffffffffu, mx1, 2));
      float mn0 = fmaxf(m0r, mx0), mn1 = fmaxf(m1r, mx1);
      float al0 = __expf(m0r - mn0), al1 = __expf(m1r - mn1);
      m0r = mn0; m1r = mn1;

      float sum0 = 0.f, sum1 = 0.f;
      uint32_t ph[8][2];
#pragma unroll
      for (int j = 0; j < 8; j++) {
        float p0 = __expf(sacc[j][0] - mn0);
        float p1 = __expf(sacc[j][1] - mn0);
        float p2 = __expf(sacc[j][2] - mn1);
        float p3 = __expf(sacc[j][3] - mn1);
        sum0 += p0 + p1; sum1 += p2 + p3;
        ph[j][0] = pack2h(p0, p1);
        ph[j][1] = pack2h(p2, p3);
      }
      sum0 += __shfl_xor_sync(0xffffffffu, sum0, 1);
      sum0 += __shfl_xor_sync(0xffffffffu, sum0, 2);
      sum1 += __shfl_xor_sync(0xffffffffu, sum1, 1);
      sum1 += __shfl_xor_sync(0xffffffffu, sum1, 2);
      l0r = l0r * al0 + sum0;
      l1r = l1r * al1 + sum1;
#pragma unroll
      for (int n = 0; n < 16; n++) {
        oacc[n][0] *= al0; oacc[n][1] *= al0;
        oacc[n][2] *= al1; oacc[n][3] *= al1;
      }

      // ---- O += P V (fp16x2: p16 * (Vh + Vl)) ----
#pragma unroll
      for (int n = 0; n < 16; n++) {
        uint32_t vh[2][4], vl[2][4];
#pragma unroll
        for (int s2 = 0; s2 < 2; s2++) {
          uint32_t a = stg + 18432 + (uint32_t)(n * 8 + (lane & 7)) * 144 + s2 * 64 + ((lane >> 3) & 3) * 16;
          LDMATRIX_X4(vh[s2][0], vh[s2][1], vh[s2][2], vh[s2][3], a);
          LDMATRIX_X4(vl[s2][0], vl[s2][1], vl[s2][2], vl[s2][3], a + 18432);
        }
#pragma unroll
        for (int t = 0; t < 4; t++) {
          uint32_t a0 = ph[2 * t][0], a1 = ph[2 * t][1], a2 = ph[2 * t + 1][0], a3 = ph[2 * t + 1][1];
          uint32_t b0h = vh[t >> 1][(t & 1) * 2], b1h = vh[t >> 1][(t & 1) * 2 + 1];
          uint32_t b0l = vl[t >> 1][(t & 1) * 2], b1l = vl[t >> 1][(t & 1) * 2 + 1];
          MMA16816H(oacc[n][0], oacc[n][1], oacc[n][2], oacc[n][3], a0, a1, a2, a3, b0h, b1h);
          MMA16816H(oacc[n][0], oacc[n][1], oacc[n][2], oacc[n][3], a0, a1, a2, a3, b0l, b1l);
        }
      }
    }

    CP_WAIT0();
    __syncthreads();
  }

  float i0 = 1.f / l0r, i1 = 1.f / l1r;
#pragma unroll
  for (int n = 0; n < 16; n++) {
    int col = n * 8 + ((lane & 3) << 1);
    *(float2*)(O + ((size_t)h * S_LEN + r0g) * VD + col) = make_float2(oacc[n][0] * i0, oacc[n][1] * i0);
    *(float2*)(O + ((size_t)h * S_LEN + r1g) * VD + col) = make_float2(oacc[n][2] * i1, oacc[n][3] * i1);
  }
}

// ---------------- differential combine + RMS norm -> fp16 concat2 ----------------
__global__ void combine_kernel(const float* __restrict__ O, __half* __restrict__ Ac2) {
  const int s = blockIdx.x;
  const int i = blockIdx.y;
  const int d = threadIdx.x;
  const float lam = g_lam;
  float o1 = O[((size_t)i * S_LEN + s) * VD + d];
  float o2 = O[((size_t)(i + 16) * S_LEN + s) * VD + d];
  float a = o1 - lam * o2;
  float ss = a * a;
#pragma unroll
  for (int off = 16; off > 0; off >>= 1)
    ss += __shfl_xor_sync(0xffffffffu, ss, off);
  __shared__ float ws[4];
  int warp = d >> 5, lane = d & 31;
  if (lane == 0) ws[warp] = ss;
  __syncthreads();
  float tot = ws[0] + ws[1] + ws[2] + ws[3];
  float r = rsqrtf(tot * (1.0f / 128.0f) + 1e-6f);
  float aval = (1.0f - LAMBDA_INIT) * a * r;
  __half ah = __float2half_rn(aval);
  size_t base = (size_t)s * KC2 + i * VD + d;
  Ac2[base]        = ah;   // seg0: A fp16
  Ac2[base + QDIM] = ah;   // seg1: A fp16 (pairs with Wo lo)
}

// ---------------- launch ----------------
extern "C" void kernel_launch(void* const* d_in, const int* in_sizes, int n_in,
                              void* d_out, int out_size) {
  const float* hidden = (const float*)d_in[0];
  const float* cosb   = (const float*)d_in[1];
  const float* sinb   = (const float*)d_in[2];
  const float* Wq     = (const float*)d_in[3];
  const float* Wk     = (const float*)d_in[4];
  const float* Wv     = (const float*)d_in[5];
  const float* Wo     = (const float*)d_in[6];
  const float* lq1    = (const float*)d_in[7];
  const float* lk1    = (const float*)d_in[8];
  const float* lq2    = (const float*)d_in[9];
  const float* lk2    = (const float*)d_in[10];
  float* out = (float*)d_out;

  float *Qp, *Kp, *Vp, *Op;
  cudaGetSymbolAddress((void**)&Qp, g_Q);
  cudaGetSymbolAddress((void**)&Kp, g_K);
  cudaGetSymbolAddress((void**)&Vp, g_V);
  cudaGetSymbolAddress((void**)&Op, g_O);
  __nv_bfloat16 *Hc, *Wqc, *Wkc, *Wvc;
  cudaGetSymbolAddress((void**)&Hc, g_Hc);
  cudaGetSymbolAddress((void**)&Wqc, g_Wqc);
  cudaGetSymbolAddress((void**)&Wkc, g_Wkc);
  cudaGetSymbolAddress((void**)&Wvc, g_Wvc);
  __half *Wo2, *Ac2;
  cudaGetSymbolAddress((void**)&Wo2, g_Wo2);
  cudaGetSymbolAddress((void**)&Ac2, g_Ac2);
  __nv_bfloat16 *Qhp, *Qlp, *Khp, *Klp;
  cudaGetSymbolAddress((void**)&Qhp, g_Qh);   cudaGetSymbolAddress((void**)&Qlp, g_Ql);
  cudaGetSymbolAddress((void**)&Khp, g_Kh);   cudaGetSymbolAddress((void**)&Klp, g_Kl);
  __half *Vthp, *Vtlp;
  cudaGetSymbolAddress((void**)&Vthp, g_Vth); cudaGetSymbolAddress((void**)&Vtlp, g_Vtl);

  cudaFuncSetAttribute(hgemm_qkv_kernel, cudaFuncAttributeMaxDynamicSharedMemorySize, GSMEM);
  cudaFuncSetAttribute(hgemm_o_kernel,   cudaFuncAttributeMaxDynamicSharedMemorySize, GSMEM);
  cudaFuncSetAttribute(flash_attn_hmma,  cudaFuncAttributeMaxDynamicSharedMemorySize, ATT_SMEM);

  // splits
  {
    int n = S_LEN * HID;
    splitcat_kernel<<<n / 4 / 256, 256>>>(hidden, Hc, HID, 0, n);
    n = QDIM * HID;
    splitcat_kernel<<<n / 4 / 256, 256>>>(Wq, Wqc, HID, 1, n);
    n = KVDIM * HID;
    splitcat_kernel<<<n / 4 / 256, 256>>>(Wk, Wkc, HID, 1, n);
    splitcat_kernel<<<n / 4 / 256, 256>>>(Wv, Wvc, HID, 1, n);
    n = HID * QDIM;
    splitcat2h_kernel<<<n / 4 / 256, 256>>>(Wo, Wo2, QDIM, n);
  }

  // QKV projections (bf16x3 concat-K)
  hgemm_qkv_kernel<<<dim3(QDIM / 128, S_LEN / 128, 3), 256, GSMEM>>>(Hc, Wqc, Wkc, Wvc, Qp, Kp, Vp);

  // RoPE + split; V transpose+split (fp16)
  rope_split_kernel<<<(S_LEN * (QDIM / 2)) / 256, 256>>>(Qp, cosb, sinb, Qhp, Qlp, QDIM);
  rope_split_kernel<<<(S_LEN * (KVDIM / 2)) / 256, 256>>>(Kp, cosb, sinb, Khp, Klp, KVDIM);
  vsplit_t_kernel<<<dim3(KVDIM / 32, S_LEN / 32), dim3(32, 8)>>>(Vp, Vthp, Vtlp);

  // lambda
  lam_kernel<<<1, 32>>>(lq1, lk1, lq2, lk2);

  // attention (QK bf16x3, PV fp16x2)
  flash_attn_hmma<<<dim3(16, NHEADS), 256, ATT_SMEM>>>(Qhp, Qlp, Khp, Klp, Vthp, Vtlp, Op);

  // combine + RMS norm -> fp16 A
  combine_kernel<<<dim3(S_LEN, 16), 128>>>(Op, Ac2);

  // output projection (fp16x2)
  hgemm_o_kernel<<<dim3(QDIM / 128, S_LEN / 128), 256, GSMEM>>>(Ac2, Wo2, out);
}

// round 9
// speedup vs baseline: 3.2516x; 1.2248x over previous
#include <cuda_runtime.h>
#include <cuda_bf16.h>
#include <cuda_fp16.h>
#include <math.h>
#include <stdint.h>

#define S_LEN 2048
#define HID   2048
#define NHEADS 32
#define HDIM   64
#define QDIM  2048
#define KVDIM  512
#define VD     128
#define KC2H  (2 * HID)     // 4096, concat-K for fp16x2 QKV
#define KC2   (2 * QDIM)    // 4096, concat-K for fp16x2 O-proj
#define LAMBDA_INIT 0.7455692280263552f

// ---------------- scratch ----------------
__device__ float g_Q[(size_t)S_LEN * QDIM];
__device__ float g_K[(size_t)S_LEN * KVDIM];
__device__ float g_V[(size_t)S_LEN * KVDIM];
__device__ float g_O[(size_t)NHEADS * S_LEN * VD];
__device__ float g_lam;
__device__ __align__(256) __half g_H2[(size_t)S_LEN * KC2H];     // [H16 | H16]
__device__ __align__(256) __half g_Wq2[(size_t)QDIM * KC2H];     // [Wh | Wl]
__device__ __align__(256) __half g_Wk2[(size_t)KVDIM * KC2H];
__device__ __align__(256) __half g_Wv2[(size_t)KVDIM * KC2H];
__device__ __align__(256) __half g_Wo2[(size_t)HID * KC2];
__device__ __align__(256) __half g_Ac2[(size_t)S_LEN * KC2];
// attention operands (fp16)
__device__ __align__(256) __half g_Qh[(size_t)S_LEN * QDIM], g_Ql[(size_t)S_LEN * QDIM];
__device__ __align__(256) __half g_K16[(size_t)S_LEN * KVDIM];
__device__ __align__(256) __half g_Vth[(size_t)KVDIM * S_LEN], g_Vtl[(size_t)KVDIM * S_LEN];

// ---------------- helpers ----------------
__device__ __forceinline__ uint32_t smem_u32(const void* p) {
  uint32_t r;
  asm("{ .reg .u64 t; cvta.to.shared.u64 t, %1; cvt.u32.u64 %0, t; }" : "=r"(r) : "l"(p));
  return r;
}
#define CP_ASYNC16(sa, ga) \
  asm volatile("cp.async.cg.shared.global [%0], [%1], 16;" :: "r"(sa), "l"(ga) : "memory")
#define CP_COMMIT() asm volatile("cp.async.commit_group;" ::: "memory")
#define CP_WAIT0()  asm volatile("cp.async.wait_group 0;" ::: "memory")

#define LDMATRIX_X4(r0, r1, r2, r3, addr) \
  asm volatile("ldmatrix.sync.aligned.m8n8.x4.shared.b16 {%0,%1,%2,%3}, [%4];" \
               : "=r"(r0), "=r"(r1), "=r"(r2), "=r"(r3) : "r"(addr))

#define MMA16816H(c0, c1, c2, c3, a0, a1, a2, a3, b0, b1) \
  asm volatile("mma.sync.aligned.m16n8k16.row.col.f32.f16.f16.f32 " \
               "{%0,%1,%2,%3}, {%4,%5,%6,%7}, {%8,%9}, {%0,%1,%2,%3};" \
               : "+f"(c0), "+f"(c1), "+f"(c2), "+f"(c3) \
               : "r"(a0), "r"(a1), "r"(a2), "r"(a3), "r"(b0), "r"(b1))

__device__ __forceinline__ uint32_t pack2h(float a, float b) {
  __half2 h = __floats2half2_rn(a, b);
  return *(uint32_t*)&h;
}

// ---------------- fp16 HMMA GEMM: C[M,N] = A[M,Kc] @ B[N,Kc]^T ----------------
#define GROWB 144
#define GTILE (128 * GROWB)
#define GSTAGE (2 * GTILE)
#define GSMEM (2 * GSTAGE)

__device__ __forceinline__ void hgemm_core(
    const __half* __restrict__ A, const __half* __restrict__ B,
    float* __restrict__ C, int N, int Kc, int m0, int n0, char* sm) {
  const int tid = threadIdx.x;
  const int warp = tid >> 5;
  const int lane = tid & 31;
  const int wm = warp & 1;
  const int wn = warp >> 1;
  const uint32_t sb = smem_u32(sm);

  const int lrow = tid >> 1;
  const int lch0 = (tid & 1) << 2;

  float acc[4][4][4];
#pragma unroll
  for (int i = 0; i < 4; i++)
#pragma unroll
    for (int j = 0; j < 4; j++)
#pragma unroll
      for (int c = 0; c < 4; c++) acc[i][j][c] = 0.f;

  const int nT = Kc >> 6;

  auto load_stage = [&](int k0, uint32_t st) {
    const __half* ag = A + (size_t)(m0 + lrow) * Kc + k0 + lch0 * 8;
    const __half* bg = B + (size_t)(n0 + lrow) * Kc + k0 + lch0 * 8;
    uint32_t so = st + lrow * GROWB + lch0 * 16;
#pragma unroll
    for (int c = 0; c < 4; c++) {
      CP_ASYNC16(so + c * 16, ag + c * 8);
      CP_ASYNC16(so + GTILE + c * 16, bg + c * 8);
    }
  };

  load_stage(0, sb);
  CP_COMMIT();

  for (int t = 0; t < nT; ++t) {
    CP_WAIT0();
    __syncthreads();
    const uint32_t cur = sb + (uint32_t)(t & 1) * GSTAGE;
    if (t + 1 < nT) {
      load_stage((t + 1) << 6, sb + (uint32_t)((t + 1) & 1) * GSTAGE);
      CP_COMMIT();
    }

#pragma unroll
    for (int ks = 0; ks < 4; ++ks) {
      uint32_t a[4][4];
#pragma unroll
      for (int mi = 0; mi < 4; ++mi) {
        uint32_t addr = cur + (uint32_t)((wm << 6) + (mi << 4) + (lane & 15)) * GROWB
                        + ((lane >> 4) << 4) + (ks << 5);
        LDMATRIX_X4(a[mi][0], a[mi][1], a[mi][2], a[mi][3], addr);
      }
      uint32_t b[4][2];
#pragma unroll
      for (int pr = 0; pr < 2; ++pr) {
        int r = (lane & 7) + (((lane >> 4) & 1) << 3);
        int hk = (lane >> 3) & 1;
        uint32_t addr = cur + GTILE + (uint32_t)((wn << 5) + (pr << 4) + r) * GROWB
                        + (hk << 4) + (ks << 5);
        uint32_t r0, r1, r2, r3;
        LDMATRIX_X4(r0, r1, r2, r3, addr);
        b[pr * 2 + 0][0] = r0; b[pr * 2 + 0][1] = r1;
        b[pr * 2 + 1][0] = r2; b[pr * 2 + 1][1] = r3;
      }
#pragma unroll
      for (int mi = 0; mi < 4; ++mi)
#pragma unroll
        for (int ni = 0; ni < 4; ++ni)
          MMA16816H(acc[mi][ni][0], acc[mi][ni][1], acc[mi][ni][2], acc[mi][ni][3],
                    a[mi][0], a[mi][1], a[mi][2], a[mi][3], b[ni][0], b[ni][1]);
    }
  }

#pragma unroll
  for (int mi = 0; mi < 4; ++mi) {
    int row = m0 + (wm << 6) + (mi << 4) + (lane >> 2);
#pragma unroll
    for (int ni = 0; ni < 4; ++ni) {
      int col = n0 + (wn << 5) + (ni << 3) + ((lane & 3) << 1);
      *(float2*)(C + (size_t)row * N + col)       = make_float2(acc[mi][ni][0], acc[mi][ni][1]);
      *(float2*)(C + (size_t)(row + 8) * N + col) = make_float2(acc[mi][ni][2], acc[mi][ni][3]);
    }
  }
}

__global__ __launch_bounds__(256, 2) void hgemm_qkv_kernel(
    const __half* __restrict__ H2,
    const __half* __restrict__ Wq2, const __half* __restrict__ Wk2,
    const __half* __restrict__ Wv2,
    float* __restrict__ Qo, float* __restrict__ Ko, float* __restrict__ Vo) {
  extern __shared__ char sm[];
  const int z = blockIdx.z;
  const __half* Bp;
  float* C;
  int N;
  if (z == 0)      { Bp = Wq2; C = Qo; N = QDIM; }
  else if (z == 1) { Bp = Wk2; C = Ko; N = KVDIM; }
  else             { Bp = Wv2; C = Vo; N = KVDIM; }
  const int n0 = blockIdx.x << 7;
  if (n0 >= N) return;
  const int m0 = blockIdx.y << 7;
  hgemm_core(H2, Bp, C, N, KC2H, m0, n0, sm);
}

__global__ __launch_bounds__(256, 2) void hgemm_o_kernel(
    const __half* __restrict__ Ac2, const __half* __restrict__ Wo2,
    float* __restrict__ out) {
  extern __shared__ char sm[];
  hgemm_core(Ac2, Wo2, out, HID, KC2, blockIdx.y << 7, blockIdx.x << 7, sm);
}

// ---------------- fp32 -> fp16 hi/lo concat2 split (weights) ----------------
__global__ void splitcat2h_kernel(const float* __restrict__ x, __half* __restrict__ o,
                                  int K, int total) {
  int i4 = (blockIdx.x * blockDim.x + threadIdx.x) << 2;
  if (i4 >= total) return;
  float4 v = *(const float4*)(x + i4);
  int row = i4 / K;
  int col = i4 - row * K;
  __half h[4], l[4];
  float vv[4] = {v.x, v.y, v.z, v.w};
#pragma unroll
  for (int j = 0; j < 4; j++) {
    h[j] = __float2half_rn(vv[j]);
    l[j] = __float2half_rn(vv[j] - __half2float(h[j]));
  }
  size_t base = (size_t)row * (2 * K) + col;
  uint2 ph, pl;
  ph.x = (uint32_t)__half_as_ushort(h[0]) | ((uint32_t)__half_as_ushort(h[1]) << 16);
  ph.y = (uint32_t)__half_as_ushort(h[2]) | ((uint32_t)__half_as_ushort(h[3]) << 16);
  pl.x = (uint32_t)__half_as_ushort(l[0]) | ((uint32_t)__half_as_ushort(l[1]) << 16);
  pl.y = (uint32_t)__half_as_ushort(l[2]) | ((uint32_t)__half_as_ushort(l[3]) << 16);
  *(uint2*)(o + base)     = ph;
  *(uint2*)(o + base + K) = pl;
}

// ---------------- fp32 -> fp16 duplicate concat2 (hidden) ----------------
__global__ void dup2h_kernel(const float* __restrict__ x, __half* __restrict__ o,
                             int K, int total) {
  int i4 = (blockIdx.x * blockDim.x + threadIdx.x) << 2;
  if (i4 >= total) return;
  float4 v = *(const float4*)(x + i4);
  int row = i4 / K;
  int col = i4 - row * K;
  uint2 ph;
  ph.x = (uint32_t)__half_as_ushort(__float2half_rn(v.x)) |
         ((uint32_t)__half_as_ushort(__float2half_rn(v.y)) << 16);
  ph.y = (uint32_t)__half_as_ushort(__float2half_rn(v.z)) |
         ((uint32_t)__half_as_ushort(__float2half_rn(v.w)) << 16);
  size_t base = (size_t)row * (2 * K) + col;
  *(uint2*)(o + base)     = ph;
  *(uint2*)(o + base + K) = ph;
}

// ---------------- RoPE + fp16 hi/lo split (Q) ----------------
__global__ void rope_split_h_kernel(const float* __restrict__ X, const float* __restrict__ cosb,
                                    const float* __restrict__ sinb,
                                    __half* __restrict__ Xh, __half* __restrict__ Xl,
                                    int width) {
  int idx = blockIdx.x * blockDim.x + threadIdx.x;
  int pairsPerRow = width >> 1;
  int total = S_LEN * pairsPerRow;
  if (idx >= total) return;
  int s = idx / pairsPerRow;
  int p = idx - s * pairsPerRow;
  int head = p >> 5;
  int d = p & 31;
  int c1 = head * HDIM + d;
  float c   = cosb[s * HDIM + d];
  float sn  = sinb[s * HDIM + d];
  float c2  = cosb[s * HDIM + d + 32];
  float sn2 = sinb[s * HDIM + d + 32];
  size_t base = (size_t)s * width;
  float x1 = X[base + c1];
  float x2 = X[base + c1 + 32];
  float y1 = x1 * c  - x2 * sn;
  float y2 = x2 * c2 + x1 * sn2;
  __half h1 = __float2half_rn(y1);
  __half h2 = __float2half_rn(y2);
  Xh[base + c1]      = h1;
  Xh[base + c1 + 32] = h2;
  Xl[base + c1]      = __float2half_rn(y1 - __half2float(h1));
  Xl[base + c1 + 32] = __float2half_rn(y2 - __half2float(h2));
}

// ---------------- RoPE + single fp16 (K) ----------------
__global__ void rope_h16_kernel(const float* __restrict__ X, const float* __restrict__ cosb,
                                const float* __restrict__ sinb,
                                __half* __restrict__ X16, int width) {
  int idx = blockIdx.x * blockDim.x + threadIdx.x;
  int pairsPerRow = width >> 1;
  int total = S_LEN * pairsPerRow;
  if (idx >= total) return;
  int s = idx / pairsPerRow;
  int p = idx - s * pairsPerRow;
  int head = p >> 5;
  int d = p & 31;
  int c1 = head * HDIM + d;
  float c   = cosb[s * HDIM + d];
  float sn  = sinb[s * HDIM + d];
  float c2  = cosb[s * HDIM + d + 32];
  float sn2 = sinb[s * HDIM + d + 32];
  size_t base = (size_t)s * width;
  float x1 = X[base + c1];
  float x2 = X[base + c1 + 32];
  X16[base + c1]      = __float2half_rn(x1 * c  - x2 * sn);
  X16[base + c1 + 32] = __float2half_rn(x2 * c2 + x1 * sn2);
}

// ---------------- V transpose + fp16 split: Vt[d][s] ----------------
__global__ void vsplit_t_kernel(const float* __restrict__ V,
                                __half* __restrict__ Vth, __half* __restrict__ Vtl) {
  __shared__ float tile[32][33];
  int c0 = blockIdx.x << 5;
  int s0 = blockIdx.y << 5;
  int tx = threadIdx.x, ty = threadIdx.y;
#pragma unroll
  for (int i = 0; i < 4; i++)
    tile[ty + i * 8][tx] = V[(size_t)(s0 + ty + i * 8) * KVDIM + c0 + tx];
  __syncthreads();
#pragma unroll
  for (int i = 0; i < 4; i++) {
    int r = ty + i * 8;
    float v = tile[tx][r];
    __half hv = __float2half_rn(v);
    Vth[(size_t)(c0 + r) * S_LEN + s0 + tx] = hv;
    Vtl[(size_t)(c0 + r) * S_LEN + s0 + tx] = __float2half_rn(v - __half2float(hv));
  }
}

// ---------------- lambda ----------------
__global__ void lam_kernel(const float* __restrict__ lq1, const float* __restrict__ lk1,
                           const float* __restrict__ lq2, const float* __restrict__ lk2) {
  int d = threadIdx.x;
  float s1 = lq1[d] * lk1[d] + lq1[d + 32] * lk1[d + 32];
  float s2 = lq2[d] * lk2[d] + lq2[d + 32] * lk2[d + 32];
#pragma unroll
  for (int off = 16; off > 0; off >>= 1) {
    s1 += __shfl_xor_sync(0xffffffffu, s1, off);
    s2 += __shfl_xor_sync(0xffffffffu, s2, off);
  }
  if (d == 0) g_lam = expf(s1) - expf(s2) + LAMBDA_INIT;
}

// ---------------- HMMA flash attention: QK fp16x2 (Q split), PV fp16x2 (V split) ----------------
// SMEM: Qh[128][72h] Ql | 2 stages of {K16[64][72h], Vth[128][72h], Vtl[128][72h]}
#define ATT_ST   36864                  // Q region: 2 x 18432
#define ATT_STGB 46080                  // K 9216 | Vh 18432 | Vl 18432
#define ATT_SMEM (36864 + 2 * 46080)    // 129024

__global__ __launch_bounds__(256, 1) void flash_attn_hmma(
    const __half* __restrict__ Qh, const __half* __restrict__ Ql,
    const __half* __restrict__ K16,
    const __half* __restrict__ Vth, const __half* __restrict__ Vtl,
    float* __restrict__ O) {
  extern __shared__ char sm[];
  const uint32_t sb = smem_u32(sm);
  const int tid = threadIdx.x;
  const int w = tid >> 5, lane = tid & 31;
  const int h = blockIdx.y;
  const int qb = 15 - (int)blockIdx.x;
  const int q0 = qb << 7;
  const int kh = h >> 2;
  const int ii = h & 15;
  const int vh0 = ii >> 2, vh1 = 4 + (ii >> 2);
  const int nk = 2 * qb + 2;

  // stage: 2560 x 16B chunks (K 512, V 2048) = 10 per thread
  auto load_stage = [&](int k0, uint32_t stg) {
#pragma unroll
    for (int i = 0; i < 10; i++) {
      int id = tid + (i << 8);
      if (id < 512) {
        int row = id >> 3, ch = id & 7;
        const __half* src = K16 + (size_t)(k0 + row) * KVDIM + kh * HDIM + ch * 8;
        CP_ASYNC16(stg + row * 144 + ch * 16, src);
      } else {
        int id2 = id - 512;
        int half_ = id2 >> 10;
        int t = id2 & 1023;
        int row = t >> 3, ch = t & 7;
        int grow = (row < 64) ? (vh0 * HDIM + row) : (vh1 * HDIM + row - 64);
        const __half* src = (half_ ? Vtl : Vth) + (size_t)grow * S_LEN + k0 + ch * 8;
        CP_ASYNC16(stg + 9216 + half_ * 18432 + row * 144 + ch * 16, src);
      }
    }
  };

  {
#pragma unroll
    for (int i = 0; i < 8; i++) {
      int id = tid + (i << 8);
      int half_ = id >> 10;
      int t = id & 1023;
      int row = t >> 3, ch = t & 7;
      const __half* src = (half_ ? Ql : Qh) + (size_t)(q0 + row) * QDIM + h * HDIM + ch * 8;
      CP_ASYNC16(sb + half_ * 18432 + row * 144 + ch * 16, src);
    }
    load_stage(0, sb + ATT_ST);
    CP_COMMIT();
    CP_WAIT0();
  }
  __syncthreads();

  uint32_t qfh[4][4], qfl[4][4];
#pragma unroll
  for (int s = 0; s < 4; s++) {
    uint32_t a = sb + (uint32_t)(w * 16 + (lane & 15)) * 144 + ((lane >> 4) << 4) + s * 32;
    LDMATRIX_X4(qfh[s][0], qfh[s][1], qfh[s][2], qfh[s][3], a);
    LDMATRIX_X4(qfl[s][0], qfl[s][1], qfl[s][2], qfl[s][3], a + 18432);
  }

  float oacc[16][4];
#pragma unroll
  for (int n = 0; n < 16; n++)
#pragma unroll
    for (int c = 0; c < 4; c++) oacc[n][c] = 0.f;
  float m0r = -1e30f, m1r = -1e30f, l0r = 0.f, l1r = 0.f;
  const int rmin = q0 + w * 16;
  const int rmax = rmin + 15;
  const int r0g = rmin + (lane >> 2);
  const int r1g = r0g + 8;

  for (int kb = 0; kb < nk; kb++) {
    const int k0 = kb << 6;
    const uint32_t stg = sb + ATT_ST + (uint32_t)(kb & 1) * ATT_STGB;
    if (kb + 1 < nk) {
      load_stage((kb + 1) << 6, sb + ATT_ST + (uint32_t)((kb + 1) & 1) * ATT_STGB);
      CP_COMMIT();
    }

    if (k0 <= rmax) {
      // ---- S = Q K^T (fp16x2: (Qh+Ql) x K16) ----
      float sacc[8][4];
#pragma unroll
      for (int j = 0; j < 8; j++)
#pragma unroll
        for (int c = 0; c < 4; c++) sacc[j][c] = 0.f;

#pragma unroll
      for (int j = 0; j < 8; j++) {
        uint32_t bh[2][4];
#pragma unroll
        for (int s2 = 0; s2 < 2; s2++) {
          uint32_t a = stg + (uint32_t)(j * 8 + (lane & 7)) * 144 + s2 * 64 + ((lane >> 3) & 3) * 16;
          LDMATRIX_X4(bh[s2][0], bh[s2][1], bh[s2][2], bh[s2][3], a);
        }
#pragma unroll
        for (int s = 0; s < 4; s++) {
          uint32_t b0 = bh[s >> 1][(s & 1) * 2], b1 = bh[s >> 1][(s & 1) * 2 + 1];
          MMA16816H(sacc[j][0], sacc[j][1], sacc[j][2], sacc[j][3],
                    qfh[s][0], qfh[s][1], qfh[s][2], qfh[s][3], b0, b1);
          MMA16816H(sacc[j][0], sacc[j][1], sacc[j][2], sacc[j][3],
                    qfl[s][0], qfl[s][1], qfl[s][2], qfl[s][3], b0, b1);
        }
      }

      const bool needmask = (k0 + 63) > rmin;
#pragma unroll
      for (int j = 0; j < 8; j++) {
        int cb = k0 + j * 8 + ((lane & 3) << 1);
        sacc[j][0] *= 0.125f; sacc[j][1] *= 0.125f;
        sacc[j][2] *= 0.125f; sacc[j][3] *= 0.125f;
        if (needmask) {
          if (cb     > r0g) sacc[j][0] = -1e30f;
          if (cb + 1 > r0g) sacc[j][1] = -1e30f;
          if (cb     > r1g) sacc[j][2] = -1e30f;
          if (cb + 1 > r1g) sacc[j][3] = -1e30f;
        }
      }

      float mx0 = -1e30f, mx1 = -1e30f;
#pragma unroll
      for (int j = 0; j < 8; j++) {
        mx0 = fmaxf(mx0, fmaxf(sacc[j][0], sacc[j][1]));
        mx1 = fmaxf(mx1, fmaxf(sacc[j][2], sacc[j][3]));
      }
      mx0 = fmaxf(mx0, __shfl_xor_sync(0xffffffffu, mx0, 1));
      mx0 = fmaxf(mx0, __shfl_xor_sync(0xffffffffu, mx0, 2));
      mx1 = fmaxf(mx1, __shfl_xor_sync(0xffffffffu, mx1, 1));
      mx1 = fmaxf(mx1, __shfl_xor_sync(0xffffffffu, mx1, 2));
      float mn0 = fmaxf(m0r, mx0), mn1 = fmaxf(m1r, mx1);
      float al0 = __expf(m0r - mn0), al1 = __expf(m1r - mn1);
      m0r = mn0; m1r = mn1;

      float sum0 = 0.f, sum1 = 0.f;
      uint32_t ph[8][2];
#pragma unroll
      for (int j = 0; j < 8; j++) {
        float p0 = __expf(sacc[j][0] - mn0);
        float p1 = __expf(sacc[j][1] - mn0);
        float p2 = __expf(sacc[j][2] - mn1);
        float p3 = __expf(sacc[j][3] - mn1);
        sum0 += p0 + p1; sum1 += p2 + p3;
        ph[j][0] = pack2h(p0, p1);
        ph[j][1] = pack2h(p2, p3);
      }
      sum0 += __shfl_xor_sync(0xffffffffu, sum0, 1);
      sum0 += __shfl_xor_sync(0xffffffffu, sum0, 2);
      sum1 += __shfl_xor_sync(0xffffffffu, sum1, 1);
      sum1 += __shfl_xor_sync(0xffffffffu, sum1, 2);
      l0r = l0r * al0 + sum0;
      l1r = l1r * al1 + sum1;
#pragma unroll
      for (int n = 0; n < 16; n++) {
        oacc[n][0] *= al0; oacc[n][1] *= al0;
        oacc[n][2] *= al1; oacc[n][3] *= al1;
      }

      // ---- O += P V (fp16x2: p16 * (Vh + Vl)) ----
#pragma unroll
      for (int n = 0; n < 16; n++) {
        uint32_t vh[2][4], vl[2][4];
#pragma unroll
        for (int s2 = 0; s2 < 2; s2++) {
          uint32_t a = stg + 9216 + (uint32_t)(n * 8 + (lane & 7)) * 144 + s2 * 64 + ((lane >> 3) & 3) * 16;
          LDMATRIX_X4(vh[s2][0], vh[s2][1], vh[s2][2], vh[s2][3], a);
          LDMATRIX_X4(vl[s2][0], vl[s2][1], vl[s2][2], vl[s2][3], a + 18432);
        }
#pragma unroll
        for (int t = 0; t < 4; t++) {
          uint32_t a0 = ph[2 * t][0], a1 = ph[2 * t][1], a2 = ph[2 * t + 1][0], a3 = ph[2 * t + 1][1];
          uint32_t b0h = vh[t >> 1][(t & 1) * 2], b1h = vh[t >> 1][(t & 1) * 2 + 1];
          uint32_t b0l = vl[t >> 1][(t & 1) * 2], b1l = vl[t >> 1][(t & 1) * 2 + 1];
          MMA16816H(oacc[n][0], oacc[n][1], oacc[n][2], oacc[n][3], a0, a1, a2, a3, b0h, b1h);
          MMA16816H(oacc[n][0], oacc[n][1], oacc[n][2], oacc[n][3], a0, a1, a2, a3, b0l, b1l);
        }
      }
    }

    CP_WAIT0();
    __syncthreads();
  }

  float i0 = 1.f / l0r, i1 = 1.f / l1r;
#pragma unroll
  for (int n = 0; n < 16; n++) {
    int col = n * 8 + ((lane & 3) << 1);
    *(float2*)(O + ((size_t)h * S_LEN + r0g) * VD + col) = make_float2(oacc[n][0] * i0, oacc[n][1] * i0);
    *(float2*)(O + ((size_t)h * S_LEN + r1g) * VD + col) = make_float2(oacc[n][2] * i1, oacc[n][3] * i1);
  }
}

// ---------------- differential combine + RMS norm -> fp16 concat2 ----------------
__global__ void combine_kernel(const float* __restrict__ O, __half* __restrict__ Ac2) {
  const int s = blockIdx.x;
  const int i = blockIdx.y;
  const int d = threadIdx.x;
  const float lam = g_lam;
  float o1 = O[((size_t)i * S_LEN + s) * VD + d];
  float o2 = O[((size_t)(i + 16) * S_LEN + s) * VD + d];
  float a = o1 - lam * o2;
  float ss = a * a;
#pragma unroll
  for (int off = 16; off > 0; off >>= 1)
    ss += __shfl_xor_sync(0xffffffffu, ss, off);
  __shared__ float ws[4];
  int warp = d >> 5, lane = d & 31;
  if (lane == 0) ws[warp] = ss;
  __syncthreads();
  float tot = ws[0] + ws[1] + ws[2] + ws[3];
  float r = rsqrtf(tot * (1.0f / 128.0f) + 1e-6f);
  float aval = (1.0f - LAMBDA_INIT) * a * r;
  __half ah = __float2half_rn(aval);
  size_t base = (size_t)s * KC2 + i * VD + d;
  Ac2[base]        = ah;
  Ac2[base + QDIM] = ah;
}

// ---------------- launch ----------------
extern "C" void kernel_launch(void* const* d_in, const int* in_sizes, int n_in,
                              void* d_out, int out_size) {
  const float* hidden = (const float*)d_in[0];
  const float* cosb   = (const float*)d_in[1];
  const float* sinb   = (const float*)d_in[2];
  const float* Wq     = (const float*)d_in[3];
  const float* Wk     = (const float*)d_in[4];
  const float* Wv     = (const float*)d_in[5];
  const float* Wo     = (const float*)d_in[6];
  const float* lq1    = (const float*)d_in[7];
  const float* lk1    = (const float*)d_in[8];
  const float* lq2    = (const float*)d_in[9];
  const float* lk2    = (const float*)d_in[10];
  float* out = (float*)d_out;

  float *Qp, *Kp, *Vp, *Op;
  cudaGetSymbolAddress((void**)&Qp, g_Q);
  cudaGetSymbolAddress((void**)&Kp, g_K);
  cudaGetSymbolAddress((void**)&Vp, g_V);
  cudaGetSymbolAddress((void**)&Op, g_O);
  __half *H2, *Wq2, *Wk2, *Wv2, *Wo2, *Ac2;
  cudaGetSymbolAddress((void**)&H2, g_H2);
  cudaGetSymbolAddress((void**)&Wq2, g_Wq2);
  cudaGetSymbolAddress((void**)&Wk2, g_Wk2);
  cudaGetSymbolAddress((void**)&Wv2, g_Wv2);
  cudaGetSymbolAddress((void**)&Wo2, g_Wo2);
  cudaGetSymbolAddress((void**)&Ac2, g_Ac2);
  __half *Qhp, *Qlp, *K16p, *Vthp, *Vtlp;
  cudaGetSymbolAddress((void**)&Qhp, g_Qh);
  cudaGetSymbolAddress((void**)&Qlp, g_Ql);
  cudaGetSymbolAddress((void**)&K16p, g_K16);
  cudaGetSymbolAddress((void**)&Vthp, g_Vth);
  cudaGetSymbolAddress((void**)&Vtlp, g_Vtl);

  cudaFuncSetAttribute(hgemm_qkv_kernel, cudaFuncAttributeMaxDynamicSharedMemorySize, GSMEM);
  cudaFuncSetAttribute(hgemm_o_kernel,   cudaFuncAttributeMaxDynamicSharedMemorySize, GSMEM);
  cudaFuncSetAttribute(flash_attn_hmma,  cudaFuncAttributeMaxDynamicSharedMemorySize, ATT_SMEM);

  // splits
  {
    int n = S_LEN * HID;
    dup2h_kernel<<<n / 4 / 256, 256>>>(hidden, H2, HID, n);
    n = QDIM * HID;
    splitcat2h_kernel<<<n / 4 / 256, 256>>>(Wq, Wq2, HID, n);
    n = KVDIM * HID;
    splitcat2h_kernel<<<n / 4 / 256, 256>>>(Wk, Wk2, HID, n);
    splitcat2h_kernel<<<n / 4 / 256, 256>>>(Wv, Wv2, HID, n);
    n = HID * QDIM;
    splitcat2h_kernel<<<n / 4 / 256, 256>>>(Wo, Wo2, QDIM, n);
  }

  // QKV projections (fp16x2 concat-K)
  hgemm_qkv_kernel<<<dim3(QDIM / 128, S_LEN / 128, 3), 256, GSMEM>>>(H2, Wq2, Wk2, Wv2, Qp, Kp, Vp);

  // RoPE: Q -> fp16 hi/lo, K -> single fp16; V transpose+split fp16
  rope_split_h_kernel<<<(S_LEN * (QDIM / 2)) / 256, 256>>>(Qp, cosb, sinb, Qhp, Qlp, QDIM);
  rope_h16_kernel<<<(S_LEN * (KVDIM / 2)) / 256, 256>>>(Kp, cosb, sinb, K16p, KVDIM);
  vsplit_t_kernel<<<dim3(KVDIM / 32, S_LEN / 32), dim3(32, 8)>>>(Vp, Vthp, Vtlp);

  // lambda
  lam_kernel<<<1, 32>>>(lq1, lk1, lq2, lk2);

  // attention (QK fp16x2, PV fp16x2)
  flash_attn_hmma<<<dim3(16, NHEADS), 256, ATT_SMEM>>>(Qhp, Qlp, K16p, Vthp, Vtlp, Op);

  // combine + RMS norm -> fp16 A
  combine_kernel<<<dim3(S_LEN, 16), 128>>>(Op, Ac2);

  // output projection (fp16x2)
  hgemm_o_kernel<<<dim3(QDIM / 128, S_LEN / 128), 256, GSMEM>>>(Ac2, Wo2, out);
}

// round 10
// speedup vs baseline: 3.6468x; 1.1215x over previous
#include <cuda_runtime.h>
#include <cuda_bf16.h>
#include <cuda_fp16.h>
#include <math.h>
#include <stdint.h>

#define S_LEN 2048
#define HID   2048
#define NHEADS 32
#define HDIM   64
#define QDIM  2048
#define KVDIM  512
#define VD     128
#define KC2H  (2 * HID)     // 4096, concat-K for fp16x2 QKV
#define KC2   (2 * QDIM)    // 4096, concat-K for fp16x2 O-proj
#define LAMBDA_INIT 0.7455692280263552f

// ---------------- scratch ----------------
__device__ float g_Q[(size_t)S_LEN * QDIM];
__device__ float g_K[(size_t)S_LEN * KVDIM];
__device__ float g_V[(size_t)S_LEN * KVDIM];
__device__ float g_O[(size_t)NHEADS * S_LEN * VD];
__device__ float g_lam;
__device__ __align__(256) __half g_H2[(size_t)S_LEN * KC2H];     // [H16 | H16]
__device__ __align__(256) __half g_Wq2[(size_t)QDIM * KC2H];     // [Wh | Wl]
__device__ __align__(256) __half g_Wk2[(size_t)KVDIM * KC2H];
__device__ __align__(256) __half g_Wv2[(size_t)KVDIM * KC2H];
__device__ __align__(256) __half g_Wo2[(size_t)HID * KC2];
__device__ __align__(256) __half g_Ac2[(size_t)S_LEN * KC2];
// attention operands (single fp16)
__device__ __align__(256) __half g_Q16[(size_t)S_LEN * QDIM];
__device__ __align__(256) __half g_K16[(size_t)S_LEN * KVDIM];
__device__ __align__(256) __half g_Vt16[(size_t)KVDIM * S_LEN];   // transposed [d][s]

// ---------------- helpers ----------------
__device__ __forceinline__ uint32_t smem_u32(const void* p) {
  uint32_t r;
  asm("{ .reg .u64 t; cvta.to.shared.u64 t, %1; cvt.u32.u64 %0, t; }" : "=r"(r) : "l"(p));
  return r;
}
#define CP_ASYNC16(sa, ga) \
  asm volatile("cp.async.cg.shared.global [%0], [%1], 16;" :: "r"(sa), "l"(ga) : "memory")
#define CP_COMMIT() asm volatile("cp.async.commit_group;" ::: "memory")
#define CP_WAIT0()  asm volatile("cp.async.wait_group 0;" ::: "memory")

#define LDMATRIX_X4(r0, r1, r2, r3, addr) \
  asm volatile("ldmatrix.sync.aligned.m8n8.x4.shared.b16 {%0,%1,%2,%3}, [%4];" \
               : "=r"(r0), "=r"(r1), "=r"(r2), "=r"(r3) : "r"(addr))

#define MMA16816H(c0, c1, c2, c3, a0, a1, a2, a3, b0, b1) \
  asm volatile("mma.sync.aligned.m16n8k16.row.col.f32.f16.f16.f32 " \
               "{%0,%1,%2,%3}, {%4,%5,%6,%7}, {%8,%9}, {%0,%1,%2,%3};" \
               : "+f"(c0), "+f"(c1), "+f"(c2), "+f"(c3) \
               : "r"(a0), "r"(a1), "r"(a2), "r"(a3), "r"(b0), "r"(b1))

__device__ __forceinline__ uint32_t pack2h(float a, float b) {
  __half2 h = __floats2half2_rn(a, b);
  return *(uint32_t*)&h;
}

// ---------------- fp16 HMMA GEMM: C[M,N] = A[M,Kc] @ B[N,Kc]^T ----------------
#define GROWB 144
#define GTILE (128 * GROWB)
#define GSTAGE (2 * GTILE)
#define GSMEM (2 * GSTAGE)

__device__ __forceinline__ void hgemm_core(
    const __half* __restrict__ A, const __half* __restrict__ B,
    float* __restrict__ C, int N, int Kc, int m0, int n0, char* sm) {
  const int tid = threadIdx.x;
  const int warp = tid >> 5;
  const int lane = tid & 31;
  const int wm = warp & 1;
  const int wn = warp >> 1;
  const uint32_t sb = smem_u32(sm);

  const int lrow = tid >> 1;
  const int lch0 = (tid & 1) << 2;

  float acc[4][4][4];
#pragma unroll
  for (int i = 0; i < 4; i++)
#pragma unroll
    for (int j = 0; j < 4; j++)
#pragma unroll
      for (int c = 0; c < 4; c++) acc[i][j][c] = 0.f;

  const int nT = Kc >> 6;

  auto load_stage = [&](int k0, uint32_t st) {
    const __half* ag = A + (size_t)(m0 + lrow) * Kc + k0 + lch0 * 8;
    const __half* bg = B + (size_t)(n0 + lrow) * Kc + k0 + lch0 * 8;
    uint32_t so = st + lrow * GROWB + lch0 * 16;
#pragma unroll
    for (int c = 0; c < 4; c++) {
      CP_ASYNC16(so + c * 16, ag + c * 8);
      CP_ASYNC16(so + GTILE + c * 16, bg + c * 8);
    }
  };

  load_stage(0, sb);
  CP_COMMIT();

  for (int t = 0; t < nT; ++t) {
    CP_WAIT0();
    __syncthreads();
    const uint32_t cur = sb + (uint32_t)(t & 1) * GSTAGE;
    if (t + 1 < nT) {
      load_stage((t + 1) << 6, sb + (uint32_t)((t + 1) & 1) * GSTAGE);
      CP_COMMIT();
    }

#pragma unroll
    for (int ks = 0; ks < 4; ++ks) {
      uint32_t a[4][4];
#pragma unroll
      for (int mi = 0; mi < 4; ++mi) {
        uint32_t addr = cur + (uint32_t)((wm << 6) + (mi << 4) + (lane & 15)) * GROWB
                        + ((lane >> 4) << 4) + (ks << 5);
        LDMATRIX_X4(a[mi][0], a[mi][1], a[mi][2], a[mi][3], addr);
      }
      uint32_t b[4][2];
#pragma unroll
      for (int pr = 0; pr < 2; ++pr) {
        int r = (lane & 7) + (((lane >> 4) & 1) << 3);
        int hk = (lane >> 3) & 1;
        uint32_t addr = cur + GTILE + (uint32_t)((wn << 5) + (pr << 4) + r) * GROWB
                        + (hk << 4) + (ks << 5);
        uint32_t r0, r1, r2, r3;
        LDMATRIX_X4(r0, r1, r2, r3, addr);
        b[pr * 2 + 0][0] = r0; b[pr * 2 + 0][1] = r1;
        b[pr * 2 + 1][0] = r2; b[pr * 2 + 1][1] = r3;
      }
#pragma unroll
      for (int mi = 0; mi < 4; ++mi)
#pragma unroll
        for (int ni = 0; ni < 4; ++ni)
          MMA16816H(acc[mi][ni][0], acc[mi][ni][1], acc[mi][ni][2], acc[mi][ni][3],
                    a[mi][0], a[mi][1], a[mi][2], a[mi][3], b[ni][0], b[ni][1]);
    }
  }

#pragma unroll
  for (int mi = 0; mi < 4; ++mi) {
    int row = m0 + (wm << 6) + (mi << 4) + (lane >> 2);
#pragma unroll
    for (int ni = 0; ni < 4; ++ni) {
      int col = n0 + (wn << 5) + (ni << 3) + ((lane & 3) << 1);
      *(float2*)(C + (size_t)row * N + col)       = make_float2(acc[mi][ni][0], acc[mi][ni][1]);
      *(float2*)(C + (size_t)(row + 8) * N + col) = make_float2(acc[mi][ni][2], acc[mi][ni][3]);
    }
  }
}

__global__ __launch_bounds__(256, 2) void hgemm_qkv_kernel(
    const __half* __restrict__ H2,
    const __half* __restrict__ Wq2, const __half* __restrict__ Wk2,
    const __half* __restrict__ Wv2,
    float* __restrict__ Qo, float* __restrict__ Ko, float* __restrict__ Vo) {
  extern __shared__ char sm[];
  const int z = blockIdx.z;
  const __half* Bp;
  float* C;
  int N;
  if (z == 0)      { Bp = Wq2; C = Qo; N = QDIM; }
  else if (z == 1) { Bp = Wk2; C = Ko; N = KVDIM; }
  else             { Bp = Wv2; C = Vo; N = KVDIM; }
  const int n0 = blockIdx.x << 7;
  if (n0 >= N) return;
  const int m0 = blockIdx.y << 7;
  hgemm_core(H2, Bp, C, N, KC2H, m0, n0, sm);
}

__global__ __launch_bounds__(256, 2) void hgemm_o_kernel(
    const __half* __restrict__ Ac2, const __half* __restrict__ Wo2,
    float* __restrict__ out) {
  extern __shared__ char sm[];
  hgemm_core(Ac2, Wo2, out, HID, KC2, blockIdx.y << 7, blockIdx.x << 7, sm);
}

// ---------------- fp32 -> fp16 hi/lo concat2 split (weights) ----------------
__global__ void splitcat2h_kernel(const float* __restrict__ x, __half* __restrict__ o,
                                  int K, int total) {
  int i4 = (blockIdx.x * blockDim.x + threadIdx.x) << 2;
  if (i4 >= total) return;
  float4 v = *(const float4*)(x + i4);
  int row = i4 / K;
  int col = i4 - row * K;
  __half h[4], l[4];
  float vv[4] = {v.x, v.y, v.z, v.w};
#pragma unroll
  for (int j = 0; j < 4; j++) {
    h[j] = __float2half_rn(vv[j]);
    l[j] = __float2half_rn(vv[j] - __half2float(h[j]));
  }
  size_t base = (size_t)row * (2 * K) + col;
  uint2 ph, pl;
  ph.x = (uint32_t)__half_as_ushort(h[0]) | ((uint32_t)__half_as_ushort(h[1]) << 16);
  ph.y = (uint32_t)__half_as_ushort(h[2]) | ((uint32_t)__half_as_ushort(h[3]) << 16);
  pl.x = (uint32_t)__half_as_ushort(l[0]) | ((uint32_t)__half_as_ushort(l[1]) << 16);
  pl.y = (uint32_t)__half_as_ushort(l[2]) | ((uint32_t)__half_as_ushort(l[3]) << 16);
  *(uint2*)(o + base)     = ph;
  *(uint2*)(o + base + K) = pl;
}

// ---------------- fp32 -> fp16 duplicate concat2 (hidden) ----------------
__global__ void dup2h_kernel(const float* __restrict__ x, __half* __restrict__ o,
                             int K, int total) {
  int i4 = (blockIdx.x * blockDim.x + threadIdx.x) << 2;
  if (i4 >= total) return;
  float4 v = *(const float4*)(x + i4);
  int row = i4 / K;
  int col = i4 - row * K;
  uint2 ph;
  ph.x = (uint32_t)__half_as_ushort(__float2half_rn(v.x)) |
         ((uint32_t)__half_as_ushort(__float2half_rn(v.y)) << 16);
  ph.y = (uint32_t)__half_as_ushort(__float2half_rn(v.z)) |
         ((uint32_t)__half_as_ushort(__float2half_rn(v.w)) << 16);
  size_t base = (size_t)row * (2 * K) + col;
  *(uint2*)(o + base)     = ph;
  *(uint2*)(o + base + K) = ph;
}

// ---------------- RoPE -> single fp16 ----------------
__global__ void rope_h16_kernel(const float* __restrict__ X, const float* __restrict__ cosb,
                                const float* __restrict__ sinb,
                                __half* __restrict__ X16, int width) {
  int idx = blockIdx.x * blockDim.x + threadIdx.x;
  int pairsPerRow = width >> 1;
  int total = S_LEN * pairsPerRow;
  if (idx >= total) return;
  int s = idx / pairsPerRow;
  int p = idx - s * pairsPerRow;
  int head = p >> 5;
  int d = p & 31;
  int c1 = head * HDIM + d;
  float c   = cosb[s * HDIM + d];
  float sn  = sinb[s * HDIM + d];
  float c2  = cosb[s * HDIM + d + 32];
  float sn2 = sinb[s * HDIM + d + 32];
  size_t base = (size_t)s * width;
  float x1 = X[base + c1];
  float x2 = X[base + c1 + 32];
  X16[base + c1]      = __float2half_rn(x1 * c  - x2 * sn);
  X16[base + c1 + 32] = __float2half_rn(x2 * c2 + x1 * sn2);
}

// ---------------- V transpose -> single fp16: Vt[d][s] ----------------
__global__ void vt16_kernel(const float* __restrict__ V, __half* __restrict__ Vt16) {
  __shared__ float tile[32][33];
  int c0 = blockIdx.x << 5;
  int s0 = blockIdx.y << 5;
  int tx = threadIdx.x, ty = threadIdx.y;
#pragma unroll
  for (int i = 0; i < 4; i++)
    tile[ty + i * 8][tx] = V[(size_t)(s0 + ty + i * 8) * KVDIM + c0 + tx];
  __syncthreads();
#pragma unroll
  for (int i = 0; i < 4; i++) {
    int r = ty + i * 8;
    Vt16[(size_t)(c0 + r) * S_LEN + s0 + tx] = __float2half_rn(tile[tx][r]);
  }
}

// ---------------- lambda ----------------
__global__ void lam_kernel(const float* __restrict__ lq1, const float* __restrict__ lk1,
                           const float* __restrict__ lq2, const float* __restrict__ lk2) {
  int d = threadIdx.x;
  float s1 = lq1[d] * lk1[d] + lq1[d + 32] * lk1[d + 32];
  float s2 = lq2[d] * lk2[d] + lq2[d + 32] * lk2[d + 32];
#pragma unroll
  for (int off = 16; off > 0; off >>= 1) {
    s1 += __shfl_xor_sync(0xffffffffu, s1, off);
    s2 += __shfl_xor_sync(0xffffffffu, s2, off);
  }
  if (d == 0) g_lam = expf(s1) - expf(s2) + LAMBDA_INIT;
}

// ---------------- HMMA flash attention: plain fp16 ----------------
// SMEM: Q16[128][72h] | 2 stages of {K16[64][72h], Vt16[128][72h]}
#define ATT_ST   18432                  // Q region
#define ATT_STGB 27648                  // K 9216 | V 18432
#define ATT_SMEM (18432 + 2 * 27648)    // 73728

__global__ __launch_bounds__(256, 2) void flash_attn_hmma(
    const __half* __restrict__ Q16, const __half* __restrict__ K16,
    const __half* __restrict__ Vt16, float* __restrict__ O) {
  extern __shared__ char sm[];
  const uint32_t sb = smem_u32(sm);
  const int tid = threadIdx.x;
  const int w = tid >> 5, lane = tid & 31;
  const int h = blockIdx.y;
  const int qb = 15 - (int)blockIdx.x;
  const int q0 = qb << 7;
  const int kh = h >> 2;
  const int ii = h & 15;
  const int vh0 = ii >> 2, vh1 = 4 + (ii >> 2);
  const int nk = 2 * qb + 2;

  // stage: 1536 x 16B chunks (K 512, V 1024) = 6 per thread
  auto load_stage = [&](int k0, uint32_t stg) {
#pragma unroll
    for (int i = 0; i < 6; i++) {
      int id = tid + (i << 8);
      if (id < 512) {
        int row = id >> 3, ch = id & 7;
        const __half* src = K16 + (size_t)(k0 + row) * KVDIM + kh * HDIM + ch * 8;
        CP_ASYNC16(stg + row * 144 + ch * 16, src);
      } else {
        int t = id - 512;
        int row = t >> 3, ch = t & 7;
        int grow = (row < 64) ? (vh0 * HDIM + row) : (vh1 * HDIM + row - 64);
        const __half* src = Vt16 + (size_t)grow * S_LEN + k0 + ch * 8;
        CP_ASYNC16(stg + 9216 + row * 144 + ch * 16, src);
      }
    }
  };

  {
#pragma unroll
    for (int i = 0; i < 4; i++) {
      int id = tid + (i << 8);
      int row = id >> 3, ch = id & 7;
      const __half* src = Q16 + (size_t)(q0 + row) * QDIM + h * HDIM + ch * 8;
      CP_ASYNC16(sb + row * 144 + ch * 16, src);
    }
    load_stage(0, sb + ATT_ST);
    CP_COMMIT();
    CP_WAIT0();
  }
  __syncthreads();

  uint32_t qf[4][4];
#pragma unroll
  for (int s = 0; s < 4; s++) {
    uint32_t a = sb + (uint32_t)(w * 16 + (lane & 15)) * 144 + ((lane >> 4) << 4) + s * 32;
    LDMATRIX_X4(qf[s][0], qf[s][1], qf[s][2], qf[s][3], a);
  }

  float oacc[16][4];
#pragma unroll
  for (int n = 0; n < 16; n++)
#pragma unroll
    for (int c = 0; c < 4; c++) oacc[n][c] = 0.f;
  float m0r = -1e30f, m1r = -1e30f, l0r = 0.f, l1r = 0.f;
  const int rmin = q0 + w * 16;
  const int rmax = rmin + 15;
  const int r0g = rmin + (lane >> 2);
  const int r1g = r0g + 8;

  for (int kb = 0; kb < nk; kb++) {
    const int k0 = kb << 6;
    const uint32_t stg = sb + ATT_ST + (uint32_t)(kb & 1) * ATT_STGB;
    if (kb + 1 < nk) {
      load_stage((kb + 1) << 6, sb + ATT_ST + (uint32_t)((kb + 1) & 1) * ATT_STGB);
      CP_COMMIT();
    }

    if (k0 <= rmax) {
      // ---- S = Q K^T (fp16) ----
      float sacc[8][4];
#pragma unroll
      for (int j = 0; j < 8; j++)
#pragma unroll
        for (int c = 0; c < 4; c++) sacc[j][c] = 0.f;

#pragma unroll
      for (int j = 0; j < 8; j++) {
        uint32_t bh[2][4];
#pragma unroll
        for (int s2 = 0; s2 < 2; s2++) {
          uint32_t a = stg + (uint32_t)(j * 8 + (lane & 7)) * 144 + s2 * 64 + ((lane >> 3) & 3) * 16;
          LDMATRIX_X4(bh[s2][0], bh[s2][1], bh[s2][2], bh[s2][3], a);
        }
#pragma unroll
        for (int s = 0; s < 4; s++) {
          uint32_t b0 = bh[s >> 1][(s & 1) * 2], b1 = bh[s >> 1][(s & 1) * 2 + 1];
          MMA16816H(sacc[j][0], sacc[j][1], sacc[j][2], sacc[j][3],
                    qf[s][0], qf[s][1], qf[s][2], qf[s][3], b0, b1);
        }
      }

      const bool needmask = (k0 + 63) > rmin;
#pragma unroll
      for (int j = 0; j < 8; j++) {
        int cb = k0 + j * 8 + ((lane & 3) << 1);
        sacc[j][0] *= 0.125f; sacc[j][1] *= 0.125f;
        sacc[j][2] *= 0.125f; sacc[j][3] *= 0.125f;
        if (needmask) {
          if (cb     > r0g) sacc[j][0] = -1e30f;
          if (cb + 1 > r0g) sacc[j][1] = -1e30f;
          if (cb     > r1g) sacc[j][2] = -1e30f;
          if (cb + 1 > r1g) sacc[j][3] = -1e30f;
        }
      }

      float mx0 = -1e30f, mx1 = -1e30f;
#pragma unroll
      for (int j = 0; j < 8; j++) {
        mx0 = fmaxf(mx0, fmaxf(sacc[j][0], sacc[j][1]));
        mx1 = fmaxf(mx1, fmaxf(sacc[j][2], sacc[j][3]));
      }
      mx0 = fmaxf(mx0, __shfl_xor_sync(0xffffffffu, mx0, 1));
      mx0 = fmaxf(mx0, __shfl_xor_sync(0xffffffffu, mx0, 2));
      mx1 = fmaxf(mx1, __shfl_xor_sync(0xffffffffu, mx1, 1));
      mx1 = fmaxf(mx1, __shfl_xor_sync(0xffffffffu, mx1, 2));
      float mn0 = fmaxf(m0r, mx0), mn1 = fmaxf(m1r, mx1);
      float al0 = __expf(m0r - mn0), al1 = __expf(m1r - mn1);
      m0r = mn0; m1r = mn1;

      float sum0 = 0.f, sum1 = 0.f;
      uint32_t ph[8][2];
#pragma unroll
      for (int j = 0; j < 8; j++) {
        float p0 = __expf(sacc[j][0] - mn0);
        float p1 = __expf(sacc[j][1] - mn0);
        float p2 = __expf(sacc[j][2] - mn1);
        float p3 = __expf(sacc[j][3] - mn1);
        sum0 += p0 + p1; sum1 += p2 + p3;
        ph[j][0] = pack2h(p0, p1);
        ph[j][1] = pack2h(p2, p3);
      }
      sum0 += __shfl_xor_sync(0xffffffffu, sum0, 1);
      sum0 += __shfl_xor_sync(0xffffffffu, sum0, 2);
      sum1 += __shfl_xor_sync(0xffffffffu, sum1, 1);
      sum1 += __shfl_xor_sync(0xffffffffu, sum1, 2);
      l0r = l0r * al0 + sum0;
      l1r = l1r * al1 + sum1;
#pragma unroll
      for (int n = 0; n < 16; n++) {
        oacc[n][0] *= al0; oacc[n][1] *= al0;
        oacc[n][2] *= al1; oacc[n][3] *= al1;
      }

      // ---- O += P V (fp16) ----
#pragma unroll
      for (int n = 0; n < 16; n++) {
        uint32_t vh[2][4];
#pragma unroll
        for (int s2 = 0; s2 < 2; s2++) {
          uint32_t a = stg + 9216 + (uint32_t)(n * 8 + (lane & 7)) * 144 + s2 * 64 + ((lane >> 3) & 3) * 16;
          LDMATRIX_X4(vh[s2][0], vh[s2][1], vh[s2][2], vh[s2][3], a);
        }
#pragma unroll
        for (int t = 0; t < 4; t++) {
          uint32_t a0 = ph[2 * t][0], a1 = ph[2 * t][1], a2 = ph[2 * t + 1][0], a3 = ph[2 * t + 1][1];
          uint32_t b0 = vh[t >> 1][(t & 1) * 2], b1 = vh[t >> 1][(t & 1) * 2 + 1];
          MMA16816H(oacc[n][0], oacc[n][1], oacc[n][2], oacc[n][3], a0, a1, a2, a3, b0, b1);
        }
      }
    }

    CP_WAIT0();
    __syncthreads();
  }

  float i0 = 1.f / l0r, i1 = 1.f / l1r;
#pragma unroll
  for (int n = 0; n < 16; n++) {
    int col = n * 8 + ((lane & 3) << 1);
    *(float2*)(O + ((size_t)h * S_LEN + r0g) * VD + col) = make_float2(oacc[n][0] * i0, oacc[n][1] * i0);
    *(float2*)(O + ((size_t)h * S_LEN + r1g) * VD + col) = make_float2(oacc[n][2] * i1, oacc[n][3] * i1);
  }
}

// ---------------- differential combine + RMS norm -> fp16 concat2 ----------------
__global__ void combine_kernel(const float* __restrict__ O, __half* __restrict__ Ac2) {
  const int s = blockIdx.x;
  const int i = blockIdx.y;
  const int d = threadIdx.x;
  const float lam = g_lam;
  float o1 = O[((size_t)i * S_LEN + s) * VD + d];
  float o2 = O[((size_t)(i + 16) * S_LEN + s) * VD + d];
  float a = o1 - lam * o2;
  float ss = a * a;
#pragma unroll
  for (int off = 16; off > 0; off >>= 1)
    ss += __shfl_xor_sync(0xffffffffu, ss, off);
  __shared__ float ws[4];
  int warp = d >> 5, lane = d & 31;
  if (lane == 0) ws[warp] = ss;
  __syncthreads();
  float tot = ws[0] + ws[1] + ws[2] + ws[3];
  float r = rsqrtf(tot * (1.0f / 128.0f) + 1e-6f);
  float aval = (1.0f - LAMBDA_INIT) * a * r;
  __half ah = __float2half_rn(aval);
  size_t base = (size_t)s * KC2 + i * VD + d;
  Ac2[base]        = ah;
  Ac2[base + QDIM] = ah;
}

// ---------------- launch ----------------
extern "C" void kernel_launch(void* const* d_in, const int* in_sizes, int n_in,
                              void* d_out, int out_size) {
  const float* hidden = (const float*)d_in[0];
  const float* cosb   = (const float*)d_in[1];
  const float* sinb   = (const float*)d_in[2];
  const float* Wq     = (const float*)d_in[3];
  const float* Wk     = (const float*)d_in[4];
  const float* Wv     = (const float*)d_in[5];
  const float* Wo     = (const float*)d_in[6];
  const float* lq1    = (const float*)d_in[7];
  const float* lk1    = (const float*)d_in[8];
  const float* lq2    = (const float*)d_in[9];
  const float* lk2    = (const float*)d_in[10];
  float* out = (float*)d_out;

  float *Qp, *Kp, *Vp, *Op;
  cudaGetSymbolAddress((void**)&Qp, g_Q);
  cudaGetSymbolAddress((void**)&Kp, g_K);
  cudaGetSymbolAddress((void**)&Vp, g_V);
  cudaGetSymbolAddress((void**)&Op, g_O);
  __half *H2, *Wq2, *Wk2, *Wv2, *Wo2, *Ac2;
  cudaGetSymbolAddress((void**)&H2, g_H2);
  cudaGetSymbolAddress((void**)&Wq2, g_Wq2);
  cudaGetSymbolAddress((void**)&Wk2, g_Wk2);
  cudaGetSymbolAddress((void**)&Wv2, g_Wv2);
  cudaGetSymbolAddress((void**)&Wo2, g_Wo2);
  cudaGetSymbolAddress((void**)&Ac2, g_Ac2);
  __half *Q16p, *K16p, *Vt16p;
  cudaGetSymbolAddress((void**)&Q16p, g_Q16);
  cudaGetSymbolAddress((void**)&K16p, g_K16);
  cudaGetSymbolAddress((void**)&Vt16p, g_Vt16);

  cudaFuncSetAttribute(hgemm_qkv_kernel, cudaFuncAttributeMaxDynamicSharedMemorySize, GSMEM);
  cudaFuncSetAttribute(hgemm_o_kernel,   cudaFuncAttributeMaxDynamicSharedMemorySize, GSMEM);
  cudaFuncSetAttribute(flash_attn_hmma,  cudaFuncAttributeMaxDynamicSharedMemorySize, ATT_SMEM);

  // splits
  {
    int n = S_LEN * HID;
    dup2h_kernel<<<n / 4 / 256, 256>>>(hidden, H2, HID, n);
    n = QDIM * HID;
    splitcat2h_kernel<<<n / 4 / 256, 256>>>(Wq, Wq2, HID, n);
    n = KVDIM * HID;
    splitcat2h_kernel<<<n / 4 / 256, 256>>>(Wk, Wk2, HID, n);
    splitcat2h_kernel<<<n / 4 / 256, 256>>>(Wv, Wv2, HID, n);
    n = HID * QDIM;
    splitcat2h_kernel<<<n / 4 / 256, 256>>>(Wo, Wo2, QDIM, n);
  }

  // QKV projections (fp16x2 concat-K)
  hgemm_qkv_kernel<<<dim3(QDIM / 128, S_LEN / 128, 3), 256, GSMEM>>>(H2, Wq2, Wk2, Wv2, Qp, Kp, Vp);

  // RoPE -> fp16 (Q, K); V transpose -> fp16
  rope_h16_kernel<<<(S_LEN * (QDIM / 2)) / 256, 256>>>(Qp, cosb, sinb, Q16p, QDIM);
  rope_h16_kernel<<<(S_LEN * (KVDIM / 2)) / 256, 256>>>(Kp, cosb, sinb, K16p, KVDIM);
  vt16_kernel<<<dim3(KVDIM / 32, S_LEN / 32), dim3(32, 8)>>>(Vp, Vt16p);

  // lambda
  lam_kernel<<<1, 32>>>(lq1, lk1, lq2, lk2);

  // attention (plain fp16 HMMA)
  flash_attn_hmma<<<dim3(16, NHEADS), 256, ATT_SMEM>>>(Q16p, K16p, Vt16p, Op);

  // combine + RMS norm -> fp16 A
  combine_kernel<<<dim3(S_LEN, 16), 128>>>(Op, Ac2);

  // output projection (fp16x2)
  hgemm_o_kernel<<<dim3(QDIM / 128, S_LEN / 128), 256, GSMEM>>>(Ac2, Wo2, out);
}

// round 11
// speedup vs baseline: 5.2971x; 1.4525x over previous
#include <cuda_runtime.h>
#include <cuda_fp16.h>
#include <math.h>
#include <stdint.h>

#define S_LEN 2048
#define HID   2048
#define NHEADS 32
#define HDIM   64
#define QDIM  2048
#define KVDIM  512
#define VD     128
#define LAMBDA_INIT 0.7455692280263552f

// ---------------- scratch ----------------
__device__ float g_Q[(size_t)S_LEN * QDIM];
__device__ float g_K[(size_t)S_LEN * KVDIM];
__device__ float g_V[(size_t)S_LEN * KVDIM];
__device__ float g_O[(size_t)NHEADS * S_LEN * VD];
__device__ float g_lam;
__device__ __align__(256) __half g_H16[(size_t)S_LEN * HID];
__device__ __align__(256) __half g_Wq16[(size_t)QDIM * HID];
__device__ __align__(256) __half g_Wk16[(size_t)KVDIM * HID];
__device__ __align__(256) __half g_Wv16[(size_t)KVDIM * HID];
__device__ __align__(256) __half g_Wo16[(size_t)HID * QDIM];
__device__ __align__(256) __half g_Ac16[(size_t)S_LEN * QDIM];
// attention operands (single fp16)
__device__ __align__(256) __half g_Q16[(size_t)S_LEN * QDIM];
__device__ __align__(256) __half g_K16[(size_t)S_LEN * KVDIM];
__device__ __align__(256) __half g_Vt16[(size_t)KVDIM * S_LEN];   // transposed [d][s]

// ---------------- helpers ----------------
__device__ __forceinline__ uint32_t smem_u32(const void* p) {
  uint32_t r;
  asm("{ .reg .u64 t; cvta.to.shared.u64 t, %1; cvt.u32.u64 %0, t; }" : "=r"(r) : "l"(p));
  return r;
}
#define CP_ASYNC16(sa, ga) \
  asm volatile("cp.async.cg.shared.global [%0], [%1], 16;" :: "r"(sa), "l"(ga) : "memory")
#define CP_COMMIT() asm volatile("cp.async.commit_group;" ::: "memory")
#define CP_WAIT0()  asm volatile("cp.async.wait_group 0;" ::: "memory")

#define LDMATRIX_X4(r0, r1, r2, r3, addr) \
  asm volatile("ldmatrix.sync.aligned.m8n8.x4.shared.b16 {%0,%1,%2,%3}, [%4];" \
               : "=r"(r0), "=r"(r1), "=r"(r2), "=r"(r3) : "r"(addr))

#define MMA16816H(c0, c1, c2, c3, a0, a1, a2, a3, b0, b1) \
  asm volatile("mma.sync.aligned.m16n8k16.row.col.f32.f16.f16.f32 " \
               "{%0,%1,%2,%3}, {%4,%5,%6,%7}, {%8,%9}, {%0,%1,%2,%3};" \
               : "+f"(c0), "+f"(c1), "+f"(c2), "+f"(c3) \
               : "r"(a0), "r"(a1), "r"(a2), "r"(a3), "r"(b0), "r"(b1))

__device__ __forceinline__ uint32_t pack2h(float a, float b) {
  __half2 h = __floats2half2_rn(a, b);
  return *(uint32_t*)&h;
}

// ---------------- fp16 HMMA GEMM: C[M,N] = A[M,Kc] @ B[N,Kc]^T ----------------
#define GROWB 144
#define GTILE (128 * GROWB)
#define GSTAGE (2 * GTILE)
#define GSMEM (2 * GSTAGE)

__device__ __forceinline__ void hgemm_core(
    const __half* __restrict__ A, const __half* __restrict__ B,
    float* __restrict__ C, int N, int Kc, int m0, int n0, char* sm) {
  const int tid = threadIdx.x;
  const int warp = tid >> 5;
  const int lane = tid & 31;
  const int wm = warp & 1;
  const int wn = warp >> 1;
  const uint32_t sb = smem_u32(sm);

  const int lrow = tid >> 1;
  const int lch0 = (tid & 1) << 2;

  float acc[4][4][4];
#pragma unroll
  for (int i = 0; i < 4; i++)
#pragma unroll
    for (int j = 0; j < 4; j++)
#pragma unroll
      for (int c = 0; c < 4; c++) acc[i][j][c] = 0.f;

  const int nT = Kc >> 6;

  auto load_stage = [&](int k0, uint32_t st) {
    const __half* ag = A + (size_t)(m0 + lrow) * Kc + k0 + lch0 * 8;
    const __half* bg = B + (size_t)(n0 + lrow) * Kc + k0 + lch0 * 8;
    uint32_t so = st + lrow * GROWB + lch0 * 16;
#pragma unroll
    for (int c = 0; c < 4; c++) {
      CP_ASYNC16(so + c * 16, ag + c * 8);
      CP_ASYNC16(so + GTILE + c * 16, bg + c * 8);
    }
  };

  load_stage(0, sb);
  CP_COMMIT();

  for (int t = 0; t < nT; ++t) {
    CP_WAIT0();
    __syncthreads();
    const uint32_t cur = sb + (uint32_t)(t & 1) * GSTAGE;
    if (t + 1 < nT) {
      load_stage((t + 1) << 6, sb + (uint32_t)((t + 1) & 1) * GSTAGE);
      CP_COMMIT();
    }

#pragma unroll
    for (int ks = 0; ks < 4; ++ks) {
      uint32_t a[4][4];
#pragma unroll
      for (int mi = 0; mi < 4; ++mi) {
        uint32_t addr = cur + (uint32_t)((wm << 6) + (mi << 4) + (lane & 15)) * GROWB
                        + ((lane >> 4) << 4) + (ks << 5);
        LDMATRIX_X4(a[mi][0], a[mi][1], a[mi][2], a[mi][3], addr);
      }
      uint32_t b[4][2];
#pragma unroll
      for (int pr = 0; pr < 2; ++pr) {
        int r = (lane & 7) + (((lane >> 4) & 1) << 3);
        int hk = (lane >> 3) & 1;
        uint32_t addr = cur + GTILE + (uint32_t)((wn << 5) + (pr << 4) + r) * GROWB
                        + (hk << 4) + (ks << 5);
        uint32_t r0, r1, r2, r3;
        LDMATRIX_X4(r0, r1, r2, r3, addr);
        b[pr * 2 + 0][0] = r0; b[pr * 2 + 0][1] = r1;
        b[pr * 2 + 1][0] = r2; b[pr * 2 + 1][1] = r3;
      }
#pragma unroll
      for (int mi = 0; mi < 4; ++mi)
#pragma unroll
        for (int ni = 0; ni < 4; ++ni)
          MMA16816H(acc[mi][ni][0], acc[mi][ni][1], acc[mi][ni][2], acc[mi][ni][3],
                    a[mi][0], a[mi][1], a[mi][2], a[mi][3], b[ni][0], b[ni][1]);
    }
  }

#pragma unroll
  for (int mi = 0; mi < 4; ++mi) {
    int row = m0 + (wm << 6) + (mi << 4) + (lane >> 2);
#pragma unroll
    for (int ni = 0; ni < 4; ++ni) {
      int col = n0 + (wn << 5) + (ni << 3) + ((lane & 3) << 1);
      *(float2*)(C + (size_t)row * N + col)       = make_float2(acc[mi][ni][0], acc[mi][ni][1]);
      *(float2*)(C + (size_t)(row + 8) * N + col) = make_float2(acc[mi][ni][2], acc[mi][ni][3]);
    }
  }
}

__global__ __launch_bounds__(256, 2) void hgemm_qkv_kernel(
    const __half* __restrict__ H16,
    const __half* __restrict__ Wq16, const __half* __restrict__ Wk16,
    const __half* __restrict__ Wv16,
    float* __restrict__ Qo, float* __restrict__ Ko, float* __restrict__ Vo) {
  extern __shared__ char sm[];
  const int z = blockIdx.z;
  const __half* Bp;
  float* C;
  int N;
  if (z == 0)      { Bp = Wq16; C = Qo; N = QDIM; }
  else if (z == 1) { Bp = Wk16; C = Ko; N = KVDIM; }
  else             { Bp = Wv16; C = Vo; N = KVDIM; }
  const int n0 = blockIdx.x << 7;
  if (n0 >= N) return;
  const int m0 = blockIdx.y << 7;
  hgemm_core(H16, Bp, C, N, HID, m0, n0, sm);
}

__global__ __launch_bounds__(256, 2) void hgemm_o_kernel(
    const __half* __restrict__ Ac16, const __half* __restrict__ Wo16,
    float* __restrict__ out) {
  extern __shared__ char sm[];
  hgemm_core(Ac16, Wo16, out, HID, QDIM, blockIdx.y << 7, blockIdx.x << 7, sm);
}

// ---------------- fp32 -> fp16 convert ----------------
__global__ void f2h_kernel(const float* __restrict__ x, __half* __restrict__ o, int total) {
  int i4 = (blockIdx.x * blockDim.x + threadIdx.x) << 2;
  if (i4 >= total) return;
  float4 v = *(const float4*)(x + i4);
  uint2 ph;
  ph.x = (uint32_t)__half_as_ushort(__float2half_rn(v.x)) |
         ((uint32_t)__half_as_ushort(__float2half_rn(v.y)) << 16);
  ph.y = (uint32_t)__half_as_ushort(__float2half_rn(v.z)) |
         ((uint32_t)__half_as_ushort(__float2half_rn(v.w)) << 16);
  *(uint2*)(o + i4) = ph;
}

// ---------------- RoPE -> single fp16 ----------------
__global__ void rope_h16_kernel(const float* __restrict__ X, const float* __restrict__ cosb,
                                const float* __restrict__ sinb,
                                __half* __restrict__ X16, int width) {
  int idx = blockIdx.x * blockDim.x + threadIdx.x;
  int pairsPerRow = width >> 1;
  int total = S_LEN * pairsPerRow;
  if (idx >= total) return;
  int s = idx / pairsPerRow;
  int p = idx - s * pairsPerRow;
  int head = p >> 5;
  int d = p & 31;
  int c1 = head * HDIM + d;
  float c   = cosb[s * HDIM + d];
  float sn  = sinb[s * HDIM + d];
  float c2  = cosb[s * HDIM + d + 32];
  float sn2 = sinb[s * HDIM + d + 32];
  size_t base = (size_t)s * width;
  float x1 = X[base + c1];
  float x2 = X[base + c1 + 32];
  X16[base + c1]      = __float2half_rn(x1 * c  - x2 * sn);
  X16[base + c1 + 32] = __float2half_rn(x2 * c2 + x1 * sn2);
}

// ---------------- V transpose -> single fp16: Vt[d][s] ----------------
__global__ void vt16_kernel(const float* __restrict__ V, __half* __restrict__ Vt16) {
  __shared__ float tile[32][33];
  int c0 = blockIdx.x << 5;
  int s0 = blockIdx.y << 5;
  int tx = threadIdx.x, ty = threadIdx.y;
#pragma unroll
  for (int i = 0; i < 4; i++)
    tile[ty + i * 8][tx] = V[(size_t)(s0 + ty + i * 8) * KVDIM + c0 + tx];
  __syncthreads();
#pragma unroll
  for (int i = 0; i < 4; i++) {
    int r = ty + i * 8;
    Vt16[(size_t)(c0 + r) * S_LEN + s0 + tx] = __float2half_rn(tile[tx][r]);
  }
}

// ---------------- lambda ----------------
__global__ void lam_kernel(const float* __restrict__ lq1, const float* __restrict__ lk1,
                           const float* __restrict__ lq2, const float* __restrict__ lk2) {
  int d = threadIdx.x;
  float s1 = lq1[d] * lk1[d] + lq1[d + 32] * lk1[d + 32];
  float s2 = lq2[d] * lk2[d] + lq2[d + 32] * lk2[d + 32];
#pragma unroll
  for (int off = 16; off > 0; off >>= 1) {
    s1 += __shfl_xor_sync(0xffffffffu, s1, off);
    s2 += __shfl_xor_sync(0xffffffffu, s2, off);
  }
  if (d == 0) g_lam = expf(s1) - expf(s2) + LAMBDA_INIT;
}

// ---------------- HMMA flash attention: plain fp16 ----------------
#define ATT_ST   18432
#define ATT_STGB 27648
#define ATT_SMEM (18432 + 2 * 27648)    // 73728

__global__ __launch_bounds__(256, 2) void flash_attn_hmma(
    const __half* __restrict__ Q16, const __half* __restrict__ K16,
    const __half* __restrict__ Vt16, float* __restrict__ O) {
  extern __shared__ char sm[];
  const uint32_t sb = smem_u32(sm);
  const int tid = threadIdx.x;
  const int w = tid >> 5, lane = tid & 31;
  const int h = blockIdx.y;
  const int qb = 15 - (int)blockIdx.x;
  const int q0 = qb << 7;
  const int kh = h >> 2;
  const int ii = h & 15;
  const int vh0 = ii >> 2, vh1 = 4 + (ii >> 2);
  const int nk = 2 * qb + 2;

  auto load_stage = [&](int k0, uint32_t stg) {
#pragma unroll
    for (int i = 0; i < 6; i++) {
      int id = tid + (i << 8);
      if (id < 512) {
        int row = id >> 3, ch = id & 7;
        const __half* src = K16 + (size_t)(k0 + row) * KVDIM + kh * HDIM + ch * 8;
        CP_ASYNC16(stg + row * 144 + ch * 16, src);
      } else {
        int t = id - 512;
        int row = t >> 3, ch = t & 7;
        int grow = (row < 64) ? (vh0 * HDIM + row) : (vh1 * HDIM + row - 64);
        const __half* src = Vt16 + (size_t)grow * S_LEN + k0 + ch * 8;
        CP_ASYNC16(stg + 9216 + row * 144 + ch * 16, src);
      }
    }
  };

  {
#pragma unroll
    for (int i = 0; i < 4; i++) {
      int id = tid + (i << 8);
      int row = id >> 3, ch = id & 7;
      const __half* src = Q16 + (size_t)(q0 + row) * QDIM + h * HDIM + ch * 8;
      CP_ASYNC16(sb + row * 144 + ch * 16, src);
    }
    load_stage(0, sb + ATT_ST);
    CP_COMMIT();
    CP_WAIT0();
  }
  __syncthreads();

  uint32_t qf[4][4];
#pragma unroll
  for (int s = 0; s < 4; s++) {
    uint32_t a = sb + (uint32_t)(w * 16 + (lane & 15)) * 144 + ((lane >> 4) << 4) + s * 32;
    LDMATRIX_X4(qf[s][0], qf[s][1], qf[s][2], qf[s][3], a);
  }

  float oacc[16][4];
#pragma unroll
  for (int n = 0; n < 16; n++)
#pragma unroll
    for (int c = 0; c < 4; c++) oacc[n][c] = 0.f;
  float m0r = -1e30f, m1r = -1e30f, l0r = 0.f, l1r = 0.f;
  const int rmin = q0 + w * 16;
  const int rmax = rmin + 15;
  const int r0g = rmin + (lane >> 2);
  const int r1g = r0g + 8;

  for (int kb = 0; kb < nk; kb++) {
    const int k0 = kb << 6;
    const uint32_t stg = sb + ATT_ST + (uint32_t)(kb & 1) * ATT_STGB;
    if (kb + 1 < nk) {
      load_stage((kb + 1) << 6, sb + ATT_ST + (uint32_t)((kb + 1) & 1) * ATT_STGB);
      CP_COMMIT();
    }

    if (k0 <= rmax) {
      float sacc[8][4];
#pragma unroll
      for (int j = 0; j < 8; j++)
#pragma unroll
        for (int c = 0; c < 4; c++) sacc[j][c] = 0.f;

#pragma unroll
      for (int j = 0; j < 8; j++) {
        uint32_t bh[2][4];
#pragma unroll
        for (int s2 = 0; s2 < 2; s2++) {
          uint32_t a = stg + (uint32_t)(j * 8 + (lane & 7)) * 144 + s2 * 64 + ((lane >> 3) & 3) * 16;
          LDMATRIX_X4(bh[s2][0], bh[s2][1], bh[s2][2], bh[s2][3], a);
        }
#pragma unroll
        for (int s = 0; s < 4; s++) {
          uint32_t b0 = bh[s >> 1][(s & 1) * 2], b1 = bh[s >> 1][(s & 1) * 2 + 1];
          MMA16816H(sacc[j][0], sacc[j][1], sacc[j][2], sacc[j][3],
                    qf[s][0], qf[s][1], qf[s][2], qf[s][3], b0, b1);
        }
      }

      const bool needmask = (k0 + 63) > rmin;
#pragma unroll
      for (int j = 0; j < 8; j++) {
        int cb = k0 + j * 8 + ((lane & 3) << 1);
        sacc[j][0] *= 0.125f; sacc[j][1] *= 0.125f;
        sacc[j][2] *= 0.125f; sacc[j][3] *= 0.125f;
        if (needmask) {
          if (cb     > r0g) sacc[j][0] = -1e30f;
          if (cb + 1 > r0g) sacc[j][1] = -1e30f;
          if (cb     > r1g) sacc[j][2] = -1e30f;
          if (cb + 1 > r1g) sacc[j][3] = -1e30f;
        }
      }

      float mx0 = -1e30f, mx1 = -1e30f;
#pragma unroll
      for (int j = 0; j < 8; j++) {
        mx0 = fmaxf(mx0, fmaxf(sacc[j][0], sacc[j][1]));
        mx1 = fmaxf(mx1, fmaxf(sacc[j][2], sacc[j][3]));
      }
      mx0 = fmaxf(mx0, __shfl_xor_sync(0xffffffffu, mx0, 1));
      mx0 = fmaxf(mx0, __shfl_xor_sync(0xffffffffu, mx0, 2));
      mx1 = fmaxf(mx1, __shfl_xor_sync(0xffffffffu, mx1, 1));
      mx1 = fmaxf(mx1, __shfl_xor_sync(0xffffffffu, mx1, 2));
      float mn0 = fmaxf(m0r, mx0), mn1 = fmaxf(m1r, mx1);
      float al0 = __expf(m0r - mn0), al1 = __expf(m1r - mn1);
      m0r = mn0; m1r = mn1;

      float sum0 = 0.f, sum1 = 0.f;
      uint32_t ph[8][2];
#pragma unroll
      for (int j = 0; j < 8; j++) {
        float p0 = __expf(sacc[j][0] - mn0);
        float p1 = __expf(sacc[j][1] - mn0);
        float p2 = __expf(sacc[j][2] - mn1);
        float p3 = __expf(sacc[j][3] - mn1);
        sum0 += p0 + p1; sum1 += p2 + p3;
        ph[j][0] = pack2h(p0, p1);
        ph[j][1] = pack2h(p2, p3);
      }
      sum0 += __shfl_xor_sync(0xffffffffu, sum0, 1);
      sum0 += __shfl_xor_sync(0xffffffffu, sum0, 2);
      sum1 += __shfl_xor_sync(0xffffffffu, sum1, 1);
      sum1 += __shfl_xor_sync(0xffffffffu, sum1, 2);
      l0r = l0r * al0 + sum0;
      l1r = l1r * al1 + sum1;
#pragma unroll
      for (int n = 0; n < 16; n++) {
        oacc[n][0] *= al0; oacc[n][1] *= al0;
        oacc[n][2] *= al1; oacc[n][3] *= al1;
      }

#pragma unroll
      for (int n = 0; n < 16; n++) {
        uint32_t vh[2][4];
#pragma unroll
        for (int s2 = 0; s2 < 2; s2++) {
          uint32_t a = stg + 9216 + (uint32_t)(n * 8 + (lane & 7)) * 144 + s2 * 64 + ((lane >> 3) & 3) * 16;
          LDMATRIX_X4(vh[s2][0], vh[s2][1], vh[s2][2], vh[s2][3], a);
        }
#pragma unroll
        for (int t = 0; t < 4; t++) {
          uint32_t a0 = ph[2 * t][0], a1 = ph[2 * t][1], a2 = ph[2 * t + 1][0], a3 = ph[2 * t + 1][1];
          uint32_t b0 = vh[t >> 1][(t & 1) * 2], b1 = vh[t >> 1][(t & 1) * 2 + 1];
          MMA16816H(oacc[n][0], oacc[n][1], oacc[n][2], oacc[n][3], a0, a1, a2, a3, b0, b1);
        }
      }
    }

    CP_WAIT0();
    __syncthreads();
  }

  float i0 = 1.f / l0r, i1 = 1.f / l1r;
#pragma unroll
  for (int n = 0; n < 16; n++) {
    int col = n * 8 + ((lane & 3) << 1);
    *(float2*)(O + ((size_t)h * S_LEN + r0g) * VD + col) = make_float2(oacc[n][0] * i0, oacc[n][1] * i0);
    *(float2*)(O + ((size_t)h * S_LEN + r1g) * VD + col) = make_float2(oacc[n][2] * i1, oacc[n][3] * i1);
  }
}

// ---------------- differential combine + RMS norm -> single fp16 ----------------
__global__ void combine_kernel(const float* __restrict__ O, __half* __restrict__ Ac16) {
  const int s = blockIdx.x;
  const int i = blockIdx.y;
  const int d = threadIdx.x;
  const float lam = g_lam;
  float o1 = O[((size_t)i * S_LEN + s) * VD + d];
  float o2 = O[((size_t)(i + 16) * S_LEN + s) * VD + d];
  float a = o1 - lam * o2;
  float ss = a * a;
#pragma unroll
  for (int off = 16; off > 0; off >>= 1)
    ss += __shfl_xor_sync(0xffffffffu, ss, off);
  __shared__ float ws[4];
  int warp = d >> 5, lane = d & 31;
  if (lane == 0) ws[warp] = ss;
  __syncthreads();
  float tot = ws[0] + ws[1] + ws[2] + ws[3];
  float r = rsqrtf(tot * (1.0f / 128.0f) + 1e-6f);
  float aval = (1.0f - LAMBDA_INIT) * a * r;
  Ac16[(size_t)s * QDIM + i * VD + d] = __float2half_rn(aval);
}

// ---------------- launch ----------------
extern "C" void kernel_launch(void* const* d_in, const int* in_sizes, int n_in,
                              void* d_out, int out_size) {
  const float* hidden = (const float*)d_in[0];
  const float* cosb   = (const float*)d_in[1];
  const float* sinb   = (const float*)d_in[2];
  const float* Wq     = (const float*)d_in[3];
  const float* Wk     = (const float*)d_in[4];
  const float* Wv     = (const float*)d_in[5];
  const float* Wo     = (const float*)d_in[6];
  const float* lq1    = (const float*)d_in[7];
  const float* lk1    = (const float*)d_in[8];
  const float* lq2    = (const float*)d_in[9];
  const float* lk2    = (const float*)d_in[10];
  float* out = (float*)d_out;

  float *Qp, *Kp, *Vp, *Op;
  cudaGetSymbolAddress((void**)&Qp, g_Q);
  cudaGetSymbolAddress((void**)&Kp, g_K);
  cudaGetSymbolAddress((void**)&Vp, g_V);
  cudaGetSymbolAddress((void**)&Op, g_O);
  __half *H16, *Wq16, *Wk16, *Wv16, *Wo16, *Ac16;
  cudaGetSymbolAddress((void**)&H16, g_H16);
  cudaGetSymbolAddress((void**)&Wq16, g_Wq16);
  cudaGetSymbolAddress((void**)&Wk16, g_Wk16);
  cudaGetSymbolAddress((void**)&Wv16, g_Wv16);
  cudaGetSymbolAddress((void**)&Wo16, g_Wo16);
  cudaGetSymbolAddress((void**)&Ac16, g_Ac16);
  __half *Q16p, *K16p, *Vt16p;
  cudaGetSymbolAddress((void**)&Q16p, g_Q16);
  cudaGetSymbolAddress((void**)&K16p, g_K16);
  cudaGetSymbolAddress((void**)&Vt16p, g_Vt16);

  cudaFuncSetAttribute(hgemm_qkv_kernel, cudaFuncAttributeMaxDynamicSharedMemorySize, GSMEM);
  cudaFuncSetAttribute(hgemm_o_kernel,   cudaFuncAttributeMaxDynamicSharedMemorySize, GSMEM);
  cudaFuncSetAttribute(flash_attn_hmma,  cudaFuncAttributeMaxDynamicSharedMemorySize, ATT_SMEM);

  // converts (fp32 -> fp16)
  {
    int n = S_LEN * HID;
    f2h_kernel<<<n / 4 / 256, 256>>>(hidden, H16, n);
    n = QDIM * HID;
    f2h_kernel<<<n / 4 / 256, 256>>>(Wq, Wq16, n);
    n = KVDIM * HID;
    f2h_kernel<<<n / 4 / 256, 256>>>(Wk, Wk16, n);
    f2h_kernel<<<n / 4 / 256, 256>>>(Wv, Wv16, n);
    n = HID * QDIM;
    f2h_kernel<<<n / 4 / 256, 256>>>(Wo, Wo16, n);
  }

  // QKV projections (plain fp16, Kc=2048)
  hgemm_qkv_kernel<<<dim3(QDIM / 128, S_LEN / 128, 3), 256, GSMEM>>>(H16, Wq16, Wk16, Wv16, Qp, Kp, Vp);

  // RoPE -> fp16 (Q, K); V transpose -> fp16
  rope_h16_kernel<<<(S_LEN * (QDIM / 2)) / 256, 256>>>(Qp, cosb, sinb, Q16p, QDIM);
  rope_h16_kernel<<<(S_LEN * (KVDIM / 2)) / 256, 256>>>(Kp, cosb, sinb, K16p, KVDIM);
  vt16_kernel<<<dim3(KVDIM / 32, S_LEN / 32), dim3(32, 8)>>>(Vp, Vt16p);

  // lambda
  lam_kernel<<<1, 32>>>(lq1, lk1, lq2, lk2);

  // attention (plain fp16 HMMA)
  flash_attn_hmma<<<dim3(16, NHEADS), 256, ATT_SMEM>>>(Q16p, K16p, Vt16p, Op);

  // combine + RMS norm -> fp16 A
  combine_kernel<<<dim3(S_LEN, 16), 128>>>(Op, Ac16);

  // output projection (plain fp16, Kc=2048)
  hgemm_o_kernel<<<dim3(QDIM / 128, S_LEN / 128), 256, GSMEM>>>(Ac16, Wo16, out);
}